// round 8
// baseline (speedup 1.0000x reference)
#include <cuda_runtime.h>
#include <cuda_fp16.h>
#include <cuda_fp8.h>
#include <math.h>
#include <stdint.h>

#define Ntok 4096
#define Bb   8
#define Cc   512
#define Hh   8
#define Dd   64
#define BH   64          // B*H
#define EPSf 1e-6f
#define MCH   16         // mid-section chunks

// ---------------- scratch (static device arrays; no allocation) ----------------
__device__ __half g_qh[BH * Ntok * Dd];    // (B,H,N,D) sigmoid(q proj) fp16
__device__ __half g_kh[BH * Ntok * Dd];
__device__ __half g_vh[BH * Ntok * Dd];
__device__ float g_si[BH * Ntok];
__device__ float g_kpart[MCH * BH * Dd],  g_qpart[MCH * BH * Dd];   // plain col sums
__device__ float g_kpart2[MCH * BH * Dd], g_qpart2[MCH * BH * Dd];  // weighted col sums
__device__ float g_esum[MCH * BH];                                   // exp-sum partials
__device__ float g_kv[BH * Dd * Dd];
__device__ float g_kvpart[MCH * BH * Dd * Dd];

// GEMM operands
__device__ uint8_t g_A8[32768 * 512];      // e4m3(query * 8)
__device__ uint8_t g_B8[3 * 512 * 512];    // e4m3(W * 32), [proj][n][k]
__device__ __half  g_Bh[512 * 512];        // fp16(Wo), [n][k]
__device__ __half  g_Oh[32768 * 512];      // fp16(out_update), scrambled (B,N,C)

#define ASCALE 8.0f
#define WSCALE 32.0f
#define INVSC  (1.0f / (ASCALE * WSCALE))

// ---------------- PTX helpers (base-arch only) ----------------
__device__ __forceinline__ uint32_t smem_u32(const void* p) {
    uint32_t a;
    asm("{ .reg .u64 t; cvta.to.shared.u64 t, %1; cvt.u32.u64 %0, t; }" : "=r"(a) : "l"(p));
    return a;
}
__device__ __forceinline__ void cp16(uint32_t dst, const void* src) {
    asm volatile("cp.async.cg.shared.global [%0], [%1], 16;" :: "r"(dst), "l"(src) : "memory");
}
__device__ __forceinline__ void cp_commit() {
    asm volatile("cp.async.commit_group;" ::: "memory");
}
__device__ __forceinline__ void cp_wait2() {
    asm volatile("cp.async.wait_group 2;" ::: "memory");
}
__device__ __forceinline__ void ldm4(uint32_t* r, uint32_t addr) {
    asm volatile("ldmatrix.sync.aligned.m8n8.x4.shared.b16 {%0,%1,%2,%3}, [%4];"
                 : "=r"(r[0]), "=r"(r[1]), "=r"(r[2]), "=r"(r[3]) : "r"(addr));
}
__device__ __forceinline__ void mma16816(float* c, const uint32_t* a, const uint32_t* b) {
    asm volatile(
        "mma.sync.aligned.m16n8k16.row.col.f32.f16.f16.f32 "
        "{%0,%1,%2,%3}, {%4,%5,%6,%7}, {%8,%9}, {%0,%1,%2,%3};"
        : "+f"(c[0]), "+f"(c[1]), "+f"(c[2]), "+f"(c[3])
        : "r"(a[0]), "r"(a[1]), "r"(a[2]), "r"(a[3]), "r"(b[0]), "r"(b[1]));
}
__device__ __forceinline__ void mma16832f8(float* c, const uint32_t* a, const uint32_t* b) {
    asm volatile(
        "mma.sync.aligned.m16n8k32.row.col.f32.e4m3.e4m3.f32 "
        "{%0,%1,%2,%3}, {%4,%5,%6,%7}, {%8,%9}, {%0,%1,%2,%3};"
        : "+f"(c[0]), "+f"(c[1]), "+f"(c[2]), "+f"(c[3])
        : "r"(a[0]), "r"(a[1]), "r"(a[2]), "r"(a[3]), "r"(b[0]), "r"(b[1]));
}

// ---------------- conversion kernels ----------------
__global__ void k_split8(const float* __restrict__ src, uint8_t* __restrict__ dst)
{
    int i = blockIdx.x * blockDim.x + threadIdx.x;
    float4 v = ((const float4*)src)[i];
    __nv_fp8x2_storage_t lo = __nv_cvt_float2_to_fp8x2(make_float2(v.x * ASCALE, v.y * ASCALE),
                                                       __NV_SATFINITE, __NV_E4M3);
    __nv_fp8x2_storage_t hi = __nv_cvt_float2_to_fp8x2(make_float2(v.z * ASCALE, v.w * ASCALE),
                                                       __NV_SATFINITE, __NV_E4M3);
    ((uint32_t*)dst)[i] = (uint32_t)lo | ((uint32_t)hi << 16);
}

__global__ void k_convW(const float* __restrict__ Wq, const float* __restrict__ Wk,
                        const float* __restrict__ Wv, const float* __restrict__ Wo,
                        uint8_t* __restrict__ B8, __half* __restrict__ Bh)
{
    const float* W = (blockIdx.z == 0) ? Wq : (blockIdx.z == 1) ? Wk
                   : (blockIdx.z == 2) ? Wv : Wo;
    __shared__ float t[32][33];
    const int k0 = blockIdx.y * 32, n0 = blockIdx.x * 32;
    const int tx = threadIdx.x, ty = threadIdx.y;  // (32,8)
    for (int j = ty; j < 32; j += 8) t[j][tx] = W[(size_t)(k0 + j) * 512 + n0 + tx];
    __syncthreads();
    if (blockIdx.z < 3) {
        uint8_t* Bp = B8 + (size_t)blockIdx.z * (512 * 512);
        for (int j = ty; j < 32; j += 8)
            Bp[(size_t)(n0 + j) * 512 + (k0 + tx)] =
                __nv_cvt_float_to_fp8(t[tx][j] * WSCALE, __NV_SATFINITE, __NV_E4M3);
    } else {
        for (int j = ty; j < 32; j += 8)
            Bh[(size_t)(n0 + j) * 512 + (k0 + tx)] = __float2half_rn(t[tx][j]);
    }
}

// ---------------- fp8 mma.sync GEMM: qkv projections ----------------
// z = mode: 0 q (sigmoid -> g_qh), 1 k -> g_kh, 2 v -> g_vh
__global__ void __launch_bounds__(256) gemm_f8(
    const uint8_t* __restrict__ A, const uint8_t* __restrict__ Bbase,
    const float* __restrict__ b0, const float* __restrict__ b1, const float* __restrict__ b2)
{
    extern __shared__ char dyn[];
    const uint32_t sbase = (smem_u32(dyn) + 1023u) & ~1023u;
    char* dynA = dyn + (sbase - smem_u32(dyn));
    const int tid = threadIdx.x;
    const int wid = tid >> 5, lane = tid & 31;
    const int bn = blockIdx.x * 128, bm = blockIdx.y * 128;
    const int mode = blockIdx.z;
    const uint8_t* Bop = Bbase + (size_t)mode * (512 * 512);
    const float* bias = (mode == 1) ? b1 : (mode == 2) ? b2 : b0;
    const int warpM = wid & 3, warpN = wid >> 2;

    float acc[2][8][4];
#pragma unroll
    for (int mf = 0; mf < 2; mf++)
#pragma unroll
        for (int nf = 0; nf < 8; nf++)
#pragma unroll
            for (int i = 0; i < 4; i++) acc[mf][nf][i] = 0.f;

    int aRow[2], bRow[4];
#pragma unroll
    for (int mf = 0; mf < 2; mf++)
        aRow[mf] = warpM * 32 + mf * 16 + (lane & 7) + ((lane >> 3) & 1) * 8;
    const int aHi = lane >> 4;
#pragma unroll
    for (int nf2 = 0; nf2 < 4; nf2++)
        bRow[nf2] = warpN * 64 + nf2 * 16 + (lane & 7) + (lane >> 4) * 8;
    const int bHi = (lane >> 3) & 1;

    // chunk covers K=128 fp8 (128B rows); 4 chunks total
    auto issue = [&](int c) {
        const int akoff = c << 7;
        const uint32_t buf = sbase + (uint32_t)(c % 3) * 32768u;
#pragma unroll
        for (int t = 0; t < 4; t++) {
            int s = tid + (t << 8);
            int row = s >> 3, sc = s & 7;
            uint32_t off = row * 128 + ((sc ^ (row & 7)) << 4);
            cp16(buf + off, A + ((size_t)(bm + row) * 512 + akoff + sc * 16));
        }
#pragma unroll
        for (int t = 0; t < 4; t++) {
            int s = tid + (t << 8);
            int row = s >> 3, sc = s & 7;
            uint32_t off = row * 128 + ((sc ^ (row & 7)) << 4);
            cp16(buf + 16384u + off, Bop + ((size_t)(bn + row) * 512 + akoff + sc * 16));
        }
    };

    issue(0); cp_commit();
    issue(1); cp_commit();

    for (int c = 0; c < 4; c++) {
        if (c + 2 < 4) issue(c + 2);
        cp_commit();
        cp_wait2();
        __syncthreads();

        const uint32_t abuf = sbase + (uint32_t)(c % 3) * 32768u;
        const uint32_t bbuf = abuf + 16384u;
#pragma unroll
        for (int ks = 0; ks < 4; ks++) {   // each ks = K32 (two 16B units)
            uint32_t a[2][4], b[4][4];
#pragma unroll
            for (int mf = 0; mf < 2; mf++) {
                const int row = aRow[mf];
                const int cc = 2 * ks + aHi;
                ldm4(a[mf], abuf + row * 128 + ((cc ^ (row & 7)) << 4));
            }
#pragma unroll
            for (int nf2 = 0; nf2 < 4; nf2++) {
                const int row = bRow[nf2];
                const int cc = 2 * ks + bHi;
                ldm4(b[nf2], bbuf + row * 128 + ((cc ^ (row & 7)) << 4));
            }
#pragma unroll
            for (int mf = 0; mf < 2; mf++)
#pragma unroll
                for (int nf = 0; nf < 8; nf++)
                    mma16832f8(acc[mf][nf], a[mf], &b[nf >> 1][(nf & 1) * 2]);
        }
        __syncthreads();
    }

    // ---------------- epilogue: scale, bias, sigmoid, coalesced fp16 store ----------------
    __half* smh = (__half*)dynA;
    const int rloc = warpM * 32 + (lane >> 2);
    const int cloc = warpN * 64 + ((lane & 3) << 1);
#pragma unroll
    for (int mf = 0; mf < 2; mf++)
#pragma unroll
        for (int half = 0; half < 2; half++) {
#pragma unroll
            for (int nf = 0; nf < 8; nf++) {
                const int c0 = bn + cloc + nf * 8;
                float vx = acc[mf][nf][half * 2 + 0] * INVSC + bias[c0];
                float vy = acc[mf][nf][half * 2 + 1] * INVSC + bias[c0 + 1];
                if (mode <= 1) {
                    vx = 1.f / (1.f + expf(-vx));
                    vy = 1.f / (1.f + expf(-vy));
                }
                *(__half2*)&smh[(rloc + mf * 16 + half * 8) * 136 + cloc + nf * 8]
                    = __floats2half2_rn(vx, vy);
            }
        }
    __syncthreads();
    __half* dstg = (mode == 0) ? g_qh : (mode == 1) ? g_kh : g_vh;
    const int h0 = bn >> 6;
    const int hl = tid >> 7, nl = (tid & 127) >> 3, dp = tid & 7;
#pragma unroll
    for (int bb2 = 0; bb2 < 8; bb2++) {
        uint4 val = *(const uint4*)(smh + (size_t)(nl * 8 + bb2) * 136 + hl * 64 + dp * 8);
        *(uint4*)(dstg + ((size_t)((bb2 << 3) | (h0 + hl)) * Ntok + (bm >> 3) + nl) * Dd + dp * 8) = val;
    }
}

// ---------------- fp16 mma.sync GEMM: output projection (+bias+residual) ----------------
__global__ void __launch_bounds__(256) gemm_out(
    const __half* __restrict__ A, const __half* __restrict__ Bop,
    const float* __restrict__ bias,
    const float* __restrict__ resid, float* __restrict__ out)
{
    extern __shared__ char dyn[];
    const uint32_t sbase = (smem_u32(dyn) + 1023u) & ~1023u;
    const int tid = threadIdx.x;
    const int wid = tid >> 5, lane = tid & 31;
    const int bn = blockIdx.x * 128, bm = blockIdx.y * 128;
    const int warpM = wid & 3, warpN = wid >> 2;

    float acc[2][8][4];
#pragma unroll
    for (int mf = 0; mf < 2; mf++)
#pragma unroll
        for (int nf = 0; nf < 8; nf++)
#pragma unroll
            for (int i = 0; i < 4; i++) acc[mf][nf][i] = 0.f;

    int aRow[2], bRow[4];
#pragma unroll
    for (int mf = 0; mf < 2; mf++)
        aRow[mf] = warpM * 32 + mf * 16 + (lane & 7) + ((lane >> 3) & 1) * 8;
    const int aHi = lane >> 4;
#pragma unroll
    for (int nf2 = 0; nf2 < 4; nf2++)
        bRow[nf2] = warpN * 64 + nf2 * 16 + (lane & 7) + (lane >> 4) * 8;
    const int bHi = (lane >> 3) & 1;

    auto issue = [&](int c) {
        const int akoff = c << 6;
        const uint32_t buf = sbase + (uint32_t)(c % 3) * 32768u;
#pragma unroll
        for (int t = 0; t < 4; t++) {
            int s = tid + (t << 8);
            int row = s >> 3, sc = s & 7;
            uint32_t off = row * 128 + ((sc ^ (row & 7)) << 4);
            cp16(buf + off, A + ((size_t)(bm + row) * 512 + akoff + sc * 8));
        }
#pragma unroll
        for (int t = 0; t < 4; t++) {
            int s = tid + (t << 8);
            int row = s >> 3, sc = s & 7;
            uint32_t off = row * 128 + ((sc ^ (row & 7)) << 4);
            cp16(buf + 16384u + off, Bop + ((size_t)(bn + row) * 512 + akoff + sc * 8));
        }
    };

    issue(0); cp_commit();
    issue(1); cp_commit();

    for (int c = 0; c < 8; c++) {
        if (c + 2 < 8) issue(c + 2);
        cp_commit();
        cp_wait2();
        __syncthreads();

        const uint32_t abuf = sbase + (uint32_t)(c % 3) * 32768u;
        const uint32_t bbuf = abuf + 16384u;
#pragma unroll
        for (int ks = 0; ks < 4; ks++) {
            uint32_t a[2][4], b[4][4];
#pragma unroll
            for (int mf = 0; mf < 2; mf++) {
                const int row = aRow[mf];
                const int cc = 2 * ks + aHi;
                ldm4(a[mf], abuf + row * 128 + ((cc ^ (row & 7)) << 4));
            }
#pragma unroll
            for (int nf2 = 0; nf2 < 4; nf2++) {
                const int row = bRow[nf2];
                const int cc = 2 * ks + bHi;
                ldm4(b[nf2], bbuf + row * 128 + ((cc ^ (row & 7)) << 4));
            }
#pragma unroll
            for (int mf = 0; mf < 2; mf++)
#pragma unroll
                for (int nf = 0; nf < 8; nf++)
                    mma16816(acc[mf][nf], a[mf], &b[nf >> 1][(nf & 1) * 2]);
        }
        __syncthreads();
    }

    const int r0base = bm + warpM * 32 + (lane >> 2);
    const int cb = bn + warpN * 64 + ((lane & 3) << 1);
#pragma unroll
    for (int mf = 0; mf < 2; mf++)
#pragma unroll
        for (int half = 0; half < 2; half++) {
            const int r = r0base + mf * 16 + half * 8;
#pragma unroll
            for (int nf = 0; nf < 8; nf++) {
                const int c0 = cb + nf * 8;
                const int bb = r >> 12, n = r & 4095;
                const size_t o = (size_t)((n << 3) | bb) * Cc + c0;
                float2 rs = *(const float2*)(resid + o);
                float2 v;
                v.x = acc[mf][nf][half * 2 + 0] + bias[c0] + rs.x;
                v.y = acc[mf][nf][half * 2 + 1] + bias[c0 + 1] + rs.y;
                *(float2*)(out + o) = v;
            }
        }
}

// ---------------- plain column sums over s (fp16 inputs, fp32 accum) ----------------
__global__ void k_colsum()
{
    const int bh = blockIdx.y, chunk = blockIdx.x;
    const int dp = threadIdx.x & 31, p = threadIdx.x >> 5;
    const __half* kb = g_kh + (size_t)bh * Ntok * Dd;
    const __half* qb = g_qh + (size_t)bh * Ntok * Dd;
    float ak0 = 0.f, ak1 = 0.f, aq0 = 0.f, aq1 = 0.f;
    const int s0 = chunk * 256;
    for (int s = s0 + p; s < s0 + 256; s += 8) {
        float2 kf = __half22float2(*(const __half2*)(kb + (size_t)s * Dd + 2 * dp));
        float2 qf = __half22float2(*(const __half2*)(qb + (size_t)s * Dd + 2 * dp));
        ak0 += kf.x; ak1 += kf.y;
        aq0 += qf.x; aq1 += qf.y;
    }
    __shared__ float sk[8][64], sq[8][64];
    sk[p][2 * dp] = ak0; sk[p][2 * dp + 1] = ak1;
    sq[p][2 * dp] = aq0; sq[p][2 * dp + 1] = aq1;
    __syncthreads();
    if (threadIdx.x < 64) {
        const int d = threadIdx.x;
        float a = 0.f, b = 0.f;
#pragma unroll
        for (int i = 0; i < 8; i++) { a += sk[i][d]; b += sq[i][d]; }
        g_kpart[(chunk * BH + bh) * Dd + d] = a;
        g_qpart[(chunk * BH + bh) * Dd + d] = b;
    }
}

// ---------------- fused: reduce colsum partials + rownorm (si/so) + weighted colsums ----------------
__global__ void __launch_bounds__(256) k_fuse1()
{
    const int bh = blockIdx.y, chunk = blockIdx.x;
    const int w = threadIdx.x >> 5, lane = threadIdx.x & 31;
    __shared__ float ksS[64], qsS[64];
    __shared__ float sQ[8][64], sK[8][64];
    if (threadIdx.x < 64) {
        float a = 0.f, b = 0.f;
#pragma unroll
        for (int c = 0; c < MCH; c++) {
            a += g_kpart[(c * BH + bh) * Dd + threadIdx.x];
            b += g_qpart[(c * BH + bh) * Dd + threadIdx.x];
        }
        ksS[threadIdx.x] = a + EPSf;
        qsS[threadIdx.x] = b + EPSf;
    }
    __syncthreads();
    const __half* qb = g_qh + (size_t)bh * Ntok * Dd;
    const __half* kb = g_kh + (size_t)bh * Ntok * Dd;
    const float ks0 = ksS[2 * lane], ks1 = ksS[2 * lane + 1];
    const float qs0 = qsS[2 * lane], qs1 = qsS[2 * lane + 1];
    float aq0 = 0.f, aq1 = 0.f, ak0 = 0.f, ak1 = 0.f;
    const int s0 = chunk * 256 + w * 32;
    for (int i = 0; i < 32; i++) {
        const int s = s0 + i;
        float2 qf = __half22float2(*(const __half2*)(qb + (size_t)s * Dd + 2 * lane));
        float2 kf = __half22float2(*(const __half2*)(kb + (size_t)s * Dd + 2 * lane));
        float s1 = (qf.x + EPSf) * ks0 + (qf.y + EPSf) * ks1;
        float s2 = (kf.x + EPSf) * qs0 + (kf.y + EPSf) * qs1;
#pragma unroll
        for (int o = 16; o > 0; o >>= 1) {
            s1 += __shfl_xor_sync(0xffffffffu, s1, o);
            s2 += __shfl_xor_sync(0xffffffffu, s2, o);
        }
        const float si = 1.f / (s1 + EPSf);
        const float so = 1.f / (s2 + EPSf);
        if (lane == 0) g_si[bh * Ntok + s] = si;
        aq0 += si * qf.x; aq1 += si * qf.y;
        ak0 += so * kf.x; ak1 += so * kf.y;
    }
    sQ[w][2 * lane] = aq0; sQ[w][2 * lane + 1] = aq1;
    sK[w][2 * lane] = ak0; sK[w][2 * lane + 1] = ak1;
    __syncthreads();
    if (threadIdx.x < 64) {
        const int d = threadIdx.x;
        float sq = 0.f, sk = 0.f;
#pragma unroll
        for (int w2 = 0; w2 < 8; w2++) { sq += sQ[w2][d]; sk += sK[w2][d]; }
        g_qpart2[(chunk * BH + bh) * Dd + d] = sq;
        g_kpart2[(chunk * BH + bh) * Dd + d] = sk;
    }
}

// ---------------- fused: conserved_source (inline) + exp + kv partials + exp-sum ----------------
__global__ void __launch_bounds__(256) k_kv(const float* __restrict__ tptr)
{
    const int bh = blockIdx.y, chunk = blockIdx.x;
    __shared__ float ks[32][64];
    __shared__ float ws[32][64];
    __shared__ float qsiS[64];
    __shared__ float esred[32];
    const int tid = threadIdx.x;
    const int lr = tid >> 3;
    const int lc = (tid & 7) << 3;
    if (tid < 64) {
        float a = 0.f;
#pragma unroll
        for (int c = 0; c < MCH; c++) a += g_qpart2[(c * BH + bh) * Dd + tid];
        qsiS[tid] = a + EPSf;
    }
    __syncthreads();
    const float invT = 1.f / tptr[0];
    const size_t base = (size_t)bh * Ntok * Dd;
    const int d0 = (tid & 15) << 2, e0 = (tid >> 4) << 2;
    float acc[4][4] = {};
    float esum = 0.f;
    for (int s0 = chunk * 256; s0 < chunk * 256 + 256; s0 += 32) {
        const int s = s0 + lr;
        uint4 kraw = *(const uint4*)(g_kh + base + (size_t)s * Dd + lc);
        uint4 vraw = *(const uint4*)(g_vh + base + (size_t)s * Dd + lc);
        const __half2* kh2 = (const __half2*)&kraw;
        const __half2* vh2 = (const __half2*)&vraw;
        float kvals[8], vvals[8];
        float pd = 0.f;
#pragma unroll
        for (int j = 0; j < 4; j++) {
            float2 kf = __half22float2(kh2[j]);
            float2 vf = __half22float2(vh2[j]);
            kvals[2 * j] = kf.x; kvals[2 * j + 1] = kf.y;
            vvals[2 * j] = vf.x; vvals[2 * j + 1] = vf.y;
            pd += (kf.x + EPSf) * qsiS[lc + 2 * j] + (kf.y + EPSf) * qsiS[lc + 2 * j + 1];
        }
        pd += __shfl_xor_sync(0xffffffffu, pd, 1);
        pd += __shfl_xor_sync(0xffffffffu, pd, 2);
        pd += __shfl_xor_sync(0xffffffffu, pd, 4);
        const float cs = fminf(1.f, fmaxf(-1.f, pd + EPSf));
        const float e = expf(cs * invT);
        if ((tid & 7) == 0) esum += e;
#pragma unroll
        for (int j = 0; j < 8; j++) {
            ks[lr][lc + j] = kvals[j];
            ws[lr][lc + j] = vvals[j] * e;
        }
        __syncthreads();
#pragma unroll
        for (int ss = 0; ss < 32; ss++) {
            float4 kf = *(const float4*)&ks[ss][d0];
            float4 wf = *(const float4*)&ws[ss][e0];
            float krr[4] = {kf.x, kf.y, kf.z, kf.w};
            float wr[4] = {wf.x, wf.y, wf.z, wf.w};
#pragma unroll
            for (int i = 0; i < 4; i++)
#pragma unroll
                for (int j = 0; j < 4; j++)
                    acc[i][j] = fmaf(krr[i], wr[j], acc[i][j]);
        }
        __syncthreads();
    }
    if ((tid & 7) == 0) esred[tid >> 3] = esum;
    __syncthreads();
    if (tid == 0) {
        float t = 0.f;
#pragma unroll
        for (int i = 0; i < 32; i++) t += esred[i];
        g_esum[chunk * BH + bh] = t;
    }
    float* dst = g_kvpart + ((size_t)chunk * BH + bh) * Dd * Dd;
#pragma unroll
    for (int i = 0; i < 4; i++)
#pragma unroll
        for (int j = 0; j < 4; j++)
            dst[(d0 + i) * Dd + e0 + j] = acc[i][j];
}

// ---------------- reduce kv partials, apply softmax scale C/Σe ----------------
__global__ void k_kvred()
{
    const int i = blockIdx.x * blockDim.x + threadIdx.x;
    if (i >= BH * Dd * Dd) return;
    const int bh = i >> 12;
    float es = 0.f;
#pragma unroll
    for (int c = 0; c < MCH; c++) es += g_esum[c * BH + bh];
    const float scale = (float)Cc / es;
    float s = 0.f;
#pragma unroll
    for (int c = 0; c < MCH; c++) s += g_kvpart[(size_t)c * BH * Dd * Dd + i];
    g_kv[i] = s * scale;
}

// ---------------- out_update = (q @ kv) * si * sigmoid(q·(kso+eps)+eps) -> fp16 ----------------
__global__ void __launch_bounds__(256) k_outupd()
{
    const int bh = blockIdx.y, nt = blockIdx.x;
    const int b = bh >> 3, h = bh & 7;
    __shared__ float kvs[64][64];
    __shared__ float qsT[64][68];
    __shared__ float ksoS[64];
    const int tid = threadIdx.x;

    if (tid < 64) {
        float a = 0.f;
#pragma unroll
        for (int c = 0; c < MCH; c++) a += g_kpart2[(c * BH + bh) * Dd + tid];
        ksoS[tid] = a + EPSf;
    }

    const float4* kvsrc = (const float4*)(g_kv + (size_t)bh * (Dd * Dd));
    for (int i = tid; i < 1024; i += 256) ((float4*)kvs)[i] = kvsrc[i];

    const int lr = tid >> 3;
    const int lc = (tid & 7) << 3;
    const __half* qb = g_qh + (size_t)bh * Ntok * Dd + (size_t)(nt * 64) * Dd;
#pragma unroll
    for (int rr = lr; rr < 64; rr += 32) {
        uint4 qraw = *(const uint4*)(qb + rr * Dd + lc);
        const __half2* qh2 = (const __half2*)&qraw;
#pragma unroll
        for (int j = 0; j < 4; j++) {
            float2 qf = __half22float2(qh2[j]);
            qsT[lc + 2 * j][rr]     = qf.x;
            qsT[lc + 2 * j + 1][rr] = qf.y;
        }
    }
    __syncthreads();

    float ksoSum = 0.f;
#pragma unroll
    for (int d = 0; d < 64; d++) ksoSum += ksoS[d];

    const int n0 = (tid & 15) << 2, e0 = (tid >> 4) << 2;
    float acc[4][4] = {};
    float sadot[4] = {};
#pragma unroll
    for (int d = 0; d < 64; d++) {
        float4 qa = *(const float4*)&qsT[d][n0];
        float4 kf = *(const float4*)&kvs[d][e0];
        const float ko = ksoS[d];
        float qr[4] = {qa.x, qa.y, qa.z, qa.w};
        float krr[4] = {kf.x, kf.y, kf.z, kf.w};
#pragma unroll
        for (int i = 0; i < 4; i++) {
            sadot[i] = fmaf(qr[i], ko, sadot[i]);
#pragma unroll
            for (int j = 0; j < 4; j++)
                acc[i][j] = fmaf(qr[i], krr[j], acc[i][j]);
        }
    }

#pragma unroll
    for (int i = 0; i < 4; i++) {
        const int n = nt * 64 + n0 + i;
        const float cs_sink = sadot[i] + EPSf * ksoSum + EPSf;
        const float sa = 1.f / (1.f + expf(-cs_sink));
        const float scale = g_si[bh * Ntok + n] * sa;
        const int np = (h << 9) | (n >> 3);
        const int cbase = (n & 7) << 6;
        const size_t lin = (size_t)(b * Ntok + np) * Cc + cbase + e0;
        __half2 h01 = __floats2half2_rn(acc[i][0] * scale, acc[i][1] * scale);
        __half2 h23 = __floats2half2_rn(acc[i][2] * scale, acc[i][3] * scale);
        *(__half2*)(g_Oh + lin)     = h01;
        *(__half2*)(g_Oh + lin + 2) = h23;
    }
}

// ---------------- launch ----------------
extern "C" void kernel_launch(void* const* d_in, const int* in_sizes, int n_in,
                              void* d_out, int out_size)
{
    const float* query = (const float*)d_in[0];
    const float* Wq = (const float*)d_in[1];
    const float* bq = (const float*)d_in[2];
    const float* Wk = (const float*)d_in[3];
    const float* bk = (const float*)d_in[4];
    const float* Wv = (const float*)d_in[5];
    const float* bv = (const float*)d_in[6];
    const float* Wo = (const float*)d_in[7];
    const float* bo = (const float*)d_in[8];
    const float* temp = (const float*)d_in[9];
    float* out = (float*)d_out;

    const int DSMEM = 3 * 32768 + 1024;
    cudaFuncSetAttribute(gemm_f8,  cudaFuncAttributeMaxDynamicSharedMemorySize, DSMEM);
    cudaFuncSetAttribute(gemm_out, cudaFuncAttributeMaxDynamicSharedMemorySize, DSMEM);

    uint8_t *pA8, *pB8;
    __half *pBh, *pOh;
    cudaGetSymbolAddress((void**)&pA8, g_A8);
    cudaGetSymbolAddress((void**)&pB8, g_B8);
    cudaGetSymbolAddress((void**)&pBh, g_Bh);
    cudaGetSymbolAddress((void**)&pOh, g_Oh);

    // operand conversion
    k_split8<<<16384, 256>>>(query, pA8);
    k_convW<<<dim3(16, 16, 4), dim3(32, 8)>>>(Wq, Wk, Wv, Wo, pB8, pBh);

    // q/k/v projections in one fp8 launch (z selects mode/weights)
    gemm_f8<<<dim3(4, 256, 3), 256, DSMEM>>>(pA8, pB8, bq, bk, bv);

    k_colsum<<<dim3(MCH, BH), 256>>>();
    k_fuse1<<<dim3(MCH, BH), 256>>>();
    k_kv<<<dim3(MCH, BH), 256>>>(temp);
    k_kvred<<<(BH * Dd * Dd + 255) / 256, 256>>>();
    k_outupd<<<dim3(64, BH), 256>>>();

    // output projection (+bias+residual), fp16
    gemm_out<<<dim3(4, 256), 256, DSMEM>>>(pOh, pBh, bo, query, out);
}

// round 9
// speedup vs baseline: 1.1248x; 1.1248x over previous
#include <cuda_runtime.h>
#include <cuda_fp16.h>
#include <math.h>
#include <stdint.h>

#define Ntok 4096
#define Bb   8
#define Cc   512
#define Hh   8
#define Dd   64
#define BH   64          // B*H
#define EPSf 1e-6f
#define NCHUNK 8         // 512 K / 64 per chunk
#define MCH   16         // mid-section chunks
#define FIXSC 16777216.0f        // 2^24
#define FIXINV (1.0f / 16777216.0f)

// ---------------- scratch (static device arrays; no allocation) ----------------
__device__ __half g_qh[BH * Ntok * Dd];    // (B,H,N,D) sigmoid(q proj) fp16
__device__ __half g_kh[BH * Ntok * Dd];
__device__ __half g_vh[BH * Ntok * Dd];
__device__ float g_si[BH * Ntok];
__device__ unsigned long long g_icol[2][BH * Dd];                   // fixed-point col sums (0:q 1:k)
__device__ float g_kpart2[MCH * BH * Dd], g_qpart2[MCH * BH * Dd];  // weighted col sums
__device__ float g_esum[MCH * BH];                                   // exp-sum partials
__device__ float g_kv[BH * Dd * Dd];
__device__ float g_kvpart[MCH * BH * Dd * Dd];

// fp16 GEMM operands
__device__ __half g_Ah[32768 * 512];       // fp16(query)
__device__ __half g_Oh[32768 * 512];       // fp16(out_update), scrambled (B,N,C)
__device__ __half g_B[4 * 512 * 512];      // [proj][n][k]

// ---------------- PTX helpers (base-arch only) ----------------
__device__ __forceinline__ uint32_t smem_u32(const void* p) {
    uint32_t a;
    asm("{ .reg .u64 t; cvta.to.shared.u64 t, %1; cvt.u32.u64 %0, t; }" : "=r"(a) : "l"(p));
    return a;
}
__device__ __forceinline__ void cp16(uint32_t dst, const void* src) {
    asm volatile("cp.async.cg.shared.global [%0], [%1], 16;" :: "r"(dst), "l"(src) : "memory");
}
__device__ __forceinline__ void cp_commit() {
    asm volatile("cp.async.commit_group;" ::: "memory");
}
__device__ __forceinline__ void cp_wait2() {
    asm volatile("cp.async.wait_group 2;" ::: "memory");
}
__device__ __forceinline__ void ldm4(uint32_t* r, uint32_t addr) {
    asm volatile("ldmatrix.sync.aligned.m8n8.x4.shared.b16 {%0,%1,%2,%3}, [%4];"
                 : "=r"(r[0]), "=r"(r[1]), "=r"(r[2]), "=r"(r[3]) : "r"(addr));
}
// f16-accumulator MMA: 2x rate of f32-acc on the mma.sync pipe.
// c[0] = half2{row r, col c ; col c+1}, c[1] = half2{row r+8, ...}
__device__ __forceinline__ void mma16816h(uint32_t* c, const uint32_t* a, const uint32_t* b) {
    asm volatile(
        "mma.sync.aligned.m16n8k16.row.col.f16.f16.f16.f16 "
        "{%0,%1}, {%2,%3,%4,%5}, {%6,%7}, {%0,%1};"
        : "+r"(c[0]), "+r"(c[1])
        : "r"(a[0]), "r"(a[1]), "r"(a[2]), "r"(a[3]), "r"(b[0]), "r"(b[1]));
}

// ---------------- conversion kernels ----------------
__global__ void k_split(const float* __restrict__ src, __half* __restrict__ dst)
{
    int i = blockIdx.x * blockDim.x + threadIdx.x;
    float4 v = ((const float4*)src)[i];
    __half2* hp = (__half2*)dst;
    hp[2 * i]     = __floats2half2_rn(v.x, v.y);
    hp[2 * i + 1] = __floats2half2_rn(v.z, v.w);
}

__global__ void k_convW(const float* __restrict__ Wq, const float* __restrict__ Wk,
                        const float* __restrict__ Wv, const float* __restrict__ Wo,
                        __half* __restrict__ Bop)
{
    const float* W = (blockIdx.z == 0) ? Wq : (blockIdx.z == 1) ? Wk
                   : (blockIdx.z == 2) ? Wv : Wo;
    __half* Bp = Bop + (size_t)blockIdx.z * (512 * 512);
    __shared__ float t[32][33];
    const int k0 = blockIdx.y * 32, n0 = blockIdx.x * 32;
    const int tx = threadIdx.x, ty = threadIdx.y;  // (32,8)
    for (int j = ty; j < 32; j += 8) t[j][tx] = W[(size_t)(k0 + j) * 512 + n0 + tx];
    __syncthreads();
    for (int j = ty; j < 32; j += 8)
        Bp[(size_t)(n0 + j) * 512 + (k0 + tx)] = __float2half_rn(t[tx][j]);
}

// ---------------- mma.sync GEMM (f16 acc): D[32768,512] = A[.,512] @ B^T ----------------
// mode 0: q (sigmoid -> g_qh + colsum), 1: k -> g_kh + colsum, 2: v -> g_vh,
// mode 3: out (+bias+resid -> d_out)
__global__ void __launch_bounds__(256) gemm_tc(
    const __half* __restrict__ A, const __half* __restrict__ Bbase,
    const float* __restrict__ b0, const float* __restrict__ b1, const float* __restrict__ b2,
    const float* __restrict__ resid, float* __restrict__ out, int modeBase)
{
    extern __shared__ char dyn[];
    const uint32_t sbase = (smem_u32(dyn) + 1023u) & ~1023u;
    char* dynA = dyn + (sbase - smem_u32(dyn));
    const int tid = threadIdx.x;
    const int wid = tid >> 5, lane = tid & 31;
    const int bn = blockIdx.x * 128, bm = blockIdx.y * 128;
    const int mode = modeBase + blockIdx.z;
    const __half* Bop = Bbase + (size_t)blockIdx.z * (512 * 512);
    const float* bias = (mode == 1) ? b1 : (mode == 2) ? b2 : b0;
    const int warpM = wid & 3, warpN = wid >> 2;   // 4 x 2 warps -> 32x64 warp tile

    uint32_t acc[2][8][2];
#pragma unroll
    for (int mf = 0; mf < 2; mf++)
#pragma unroll
        for (int nf = 0; nf < 8; nf++) { acc[mf][nf][0] = 0u; acc[mf][nf][1] = 0u; }

    int aRow[2], bRow[4];
#pragma unroll
    for (int mf = 0; mf < 2; mf++)
        aRow[mf] = warpM * 32 + mf * 16 + (lane & 7) + ((lane >> 3) & 1) * 8;
    const int aHi = lane >> 4;
#pragma unroll
    for (int nf2 = 0; nf2 < 4; nf2++)
        bRow[nf2] = warpN * 64 + nf2 * 16 + (lane & 7) + (lane >> 4) * 8;
    const int bHi = (lane >> 3) & 1;

    auto issue = [&](int c) {
        const int akoff = c << 6;
        const uint32_t buf = sbase + (uint32_t)(c % 3) * 32768u;
#pragma unroll
        for (int t = 0; t < 4; t++) {
            int s = tid + (t << 8);
            int row = s >> 3, sc = s & 7;
            uint32_t off = row * 128 + ((sc ^ (row & 7)) << 4);
            cp16(buf + off, A + ((size_t)(bm + row) * 512 + akoff + sc * 8));
        }
#pragma unroll
        for (int t = 0; t < 4; t++) {
            int s = tid + (t << 8);
            int row = s >> 3, sc = s & 7;
            uint32_t off = row * 128 + ((sc ^ (row & 7)) << 4);
            cp16(buf + 16384u + off, Bop + ((size_t)(bn + row) * 512 + akoff + sc * 8));
        }
    };

    issue(0); cp_commit();
    issue(1); cp_commit();

    for (int c = 0; c < NCHUNK; c++) {
        if (c + 2 < NCHUNK) issue(c + 2);
        cp_commit();
        cp_wait2();
        __syncthreads();

        const uint32_t abuf = sbase + (uint32_t)(c % 3) * 32768u;
        const uint32_t bbuf = abuf + 16384u;
#pragma unroll
        for (int ks = 0; ks < 4; ks++) {
            uint32_t a[2][4], b[4][4];
#pragma unroll
            for (int mf = 0; mf < 2; mf++) {
                const int row = aRow[mf];
                const int cc = 2 * ks + aHi;
                ldm4(a[mf], abuf + row * 128 + ((cc ^ (row & 7)) << 4));
            }
#pragma unroll
            for (int nf2 = 0; nf2 < 4; nf2++) {
                const int row = bRow[nf2];
                const int cc = 2 * ks + bHi;
                ldm4(b[nf2], bbuf + row * 128 + ((cc ^ (row & 7)) << 4));
            }
#pragma unroll
            for (int mf = 0; mf < 2; mf++)
#pragma unroll
                for (int nf = 0; nf < 8; nf++)
                    mma16816h(acc[mf][nf], a[mf], &b[nf >> 1][(nf & 1) * 2]);
        }
        __syncthreads();
    }

    // ---------------- epilogue ----------------
    if (mode <= 2) {
        __half* smh = (__half*)dynA;
        const int rloc = warpM * 32 + (lane >> 2);
        const int cloc = warpN * 64 + ((lane & 3) << 1);
#pragma unroll
        for (int mf = 0; mf < 2; mf++)
#pragma unroll
            for (int half = 0; half < 2; half++) {
#pragma unroll
                for (int nf = 0; nf < 8; nf++) {
                    const int c0 = bn + cloc + nf * 8;
                    float2 av = __half22float2(*(__half2*)&acc[mf][nf][half]);
                    float vx = av.x + bias[c0];
                    float vy = av.y + bias[c0 + 1];
                    if (mode <= 1) {
                        vx = 1.f / (1.f + expf(-vx));
                        vy = 1.f / (1.f + expf(-vy));
                    }
                    *(__half2*)&smh[(rloc + mf * 16 + half * 8) * 136 + cloc + nf * 8]
                        = __floats2half2_rn(vx, vy);
                }
            }
        __syncthreads();
        __half* dstg = (mode == 0) ? g_qh : (mode == 1) ? g_kh : g_vh;
        const int h0 = bn >> 6;
        const int hl = tid >> 7, nl = (tid & 127) >> 3, dp = tid & 7;
#pragma unroll
        for (int bb2 = 0; bb2 < 8; bb2++) {
            uint4 val = *(const uint4*)(smh + (size_t)(nl * 8 + bb2) * 136 + hl * 64 + dp * 8);
            *(uint4*)(dstg + ((size_t)((bb2 << 3) | (h0 + hl)) * Ntok + (bm >> 3) + nl) * Dd + dp * 8) = val;
        }
        // fused column sums (q/k modes): deterministic fixed-point atomics
        if (mode <= 1) {
            const int hl2 = tid >> 7;            // which head within tile
            const int b2 = (tid >> 4) & 7;       // batch
            const int d0 = (tid & 15) << 2;      // 4 d's
            float s0 = 0.f, s1 = 0.f, s2 = 0.f, s3 = 0.f;
#pragma unroll
            for (int n = 0; n < 16; n++) {
                const __half* rowp = smh + (size_t)(n * 8 + b2) * 136 + hl2 * 64 + d0;
                float2 p0 = __half22float2(*(const __half2*)rowp);
                float2 p1 = __half22float2(*(const __half2*)(rowp + 2));
                s0 += p0.x; s1 += p0.y; s2 += p1.x; s3 += p1.y;
            }
            const int bh = (b2 << 3) | ((bn >> 6) + hl2);
            unsigned long long* dst = &g_icol[mode][bh * Dd + d0];
            atomicAdd(dst + 0, (unsigned long long)(long long)llrintf(s0 * FIXSC));
            atomicAdd(dst + 1, (unsigned long long)(long long)llrintf(s1 * FIXSC));
            atomicAdd(dst + 2, (unsigned long long)(long long)llrintf(s2 * FIXSC));
            atomicAdd(dst + 3, (unsigned long long)(long long)llrintf(s3 * FIXSC));
        }
    } else {
        const int r0base = bm + warpM * 32 + (lane >> 2);
        const int cb = bn + warpN * 64 + ((lane & 3) << 1);
#pragma unroll
        for (int mf = 0; mf < 2; mf++)
#pragma unroll
            for (int half = 0; half < 2; half++) {
                const int r = r0base + mf * 16 + half * 8;
#pragma unroll
                for (int nf = 0; nf < 8; nf++) {
                    const int c0 = cb + nf * 8;
                    const int bb = r >> 12, n = r & 4095;
                    const size_t o = (size_t)((n << 3) | bb) * Cc + c0;
                    float2 rs = *(const float2*)(resid + o);
                    float2 av = __half22float2(*(__half2*)&acc[mf][nf][half]);
                    float2 v;
                    v.x = av.x + bias[c0] + rs.x;
                    v.y = av.y + bias[c0 + 1] + rs.y;
                    *(float2*)(out + o) = v;
                }
            }
    }
}

// ---------------- fused: rownorm (si/so) + weighted colsum partials ----------------
__global__ void __launch_bounds__(256) k_fuse1()
{
    const int bh = blockIdx.y, chunk = blockIdx.x;
    const int w = threadIdx.x >> 5, lane = threadIdx.x & 31;
    __shared__ float ksS[64], qsS[64];
    __shared__ float sQ[8][64], sK[8][64];
    if (threadIdx.x < 64) {
        ksS[threadIdx.x] = (float)(long long)g_icol[1][bh * Dd + threadIdx.x] * FIXINV + EPSf;
        qsS[threadIdx.x] = (float)(long long)g_icol[0][bh * Dd + threadIdx.x] * FIXINV + EPSf;
    }
    __syncthreads();
    const __half* qb = g_qh + (size_t)bh * Ntok * Dd;
    const __half* kb = g_kh + (size_t)bh * Ntok * Dd;
    const float ks0 = ksS[2 * lane], ks1 = ksS[2 * lane + 1];
    const float qs0 = qsS[2 * lane], qs1 = qsS[2 * lane + 1];
    float aq0 = 0.f, aq1 = 0.f, ak0 = 0.f, ak1 = 0.f;
    const int s0 = chunk * 256 + w * 32;
    for (int i = 0; i < 32; i++) {
        const int s = s0 + i;
        float2 qf = __half22float2(*(const __half2*)(qb + (size_t)s * Dd + 2 * lane));
        float2 kf = __half22float2(*(const __half2*)(kb + (size_t)s * Dd + 2 * lane));
        float s1 = (qf.x + EPSf) * ks0 + (qf.y + EPSf) * ks1;
        float s2 = (kf.x + EPSf) * qs0 + (kf.y + EPSf) * qs1;
#pragma unroll
        for (int o = 16; o > 0; o >>= 1) {
            s1 += __shfl_xor_sync(0xffffffffu, s1, o);
            s2 += __shfl_xor_sync(0xffffffffu, s2, o);
        }
        const float si = 1.f / (s1 + EPSf);
        const float so = 1.f / (s2 + EPSf);
        if (lane == 0) g_si[bh * Ntok + s] = si;
        aq0 += si * qf.x; aq1 += si * qf.y;
        ak0 += so * kf.x; ak1 += so * kf.y;
    }
    sQ[w][2 * lane] = aq0; sQ[w][2 * lane + 1] = aq1;
    sK[w][2 * lane] = ak0; sK[w][2 * lane + 1] = ak1;
    __syncthreads();
    if (threadIdx.x < 64) {
        const int d = threadIdx.x;
        float sq = 0.f, sk = 0.f;
#pragma unroll
        for (int w2 = 0; w2 < 8; w2++) { sq += sQ[w2][d]; sk += sK[w2][d]; }
        g_qpart2[(chunk * BH + bh) * Dd + d] = sq;   // si-weighted q sums -> qsi
        g_kpart2[(chunk * BH + bh) * Dd + d] = sk;   // so-weighted k sums -> kso
    }
}

// ---------------- fused: conserved_source (inline) + exp + kv partials + exp-sum ----------------
__global__ void __launch_bounds__(256) k_kv(const float* __restrict__ tptr)
{
    const int bh = blockIdx.y, chunk = blockIdx.x;
    __shared__ float ks[32][64];
    __shared__ float ws[32][64];
    __shared__ float qsiS[64];
    __shared__ float esred[32];
    const int tid = threadIdx.x;
    const int lr = tid >> 3;
    const int lc = (tid & 7) << 3;
    if (tid < 64) {
        float a = 0.f;
#pragma unroll
        for (int c = 0; c < MCH; c++) a += g_qpart2[(c * BH + bh) * Dd + tid];
        qsiS[tid] = a + EPSf;
    }
    __syncthreads();
    const float invT = 1.f / tptr[0];
    const size_t base = (size_t)bh * Ntok * Dd;
    const int d0 = (tid & 15) << 2, e0 = (tid >> 4) << 2;
    float acc[4][4] = {};
    float esum = 0.f;
    for (int s0 = chunk * 256; s0 < chunk * 256 + 256; s0 += 32) {
        const int s = s0 + lr;
        uint4 kraw = *(const uint4*)(g_kh + base + (size_t)s * Dd + lc);
        uint4 vraw = *(const uint4*)(g_vh + base + (size_t)s * Dd + lc);
        const __half2* kh2 = (const __half2*)&kraw;
        const __half2* vh2 = (const __half2*)&vraw;
        float kvals[8], vvals[8];
        float pd = 0.f;
#pragma unroll
        for (int j = 0; j < 4; j++) {
            float2 kf = __half22float2(kh2[j]);
            float2 vf = __half22float2(vh2[j]);
            kvals[2 * j] = kf.x; kvals[2 * j + 1] = kf.y;
            vvals[2 * j] = vf.x; vvals[2 * j + 1] = vf.y;
            pd += (kf.x + EPSf) * qsiS[lc + 2 * j] + (kf.y + EPSf) * qsiS[lc + 2 * j + 1];
        }
        pd += __shfl_xor_sync(0xffffffffu, pd, 1);
        pd += __shfl_xor_sync(0xffffffffu, pd, 2);
        pd += __shfl_xor_sync(0xffffffffu, pd, 4);
        const float cs = fminf(1.f, fmaxf(-1.f, pd + EPSf));
        const float e = expf(cs * invT);
        if ((tid & 7) == 0) esum += e;
#pragma unroll
        for (int j = 0; j < 8; j++) {
            ks[lr][lc + j] = kvals[j];
            ws[lr][lc + j] = vvals[j] * e;
        }
        __syncthreads();
#pragma unroll
        for (int ss = 0; ss < 32; ss++) {
            float4 kf = *(const float4*)&ks[ss][d0];
            float4 wf = *(const float4*)&ws[ss][e0];
            float krr[4] = {kf.x, kf.y, kf.z, kf.w};
            float wr[4] = {wf.x, wf.y, wf.z, wf.w};
#pragma unroll
            for (int i = 0; i < 4; i++)
#pragma unroll
                for (int j = 0; j < 4; j++)
                    acc[i][j] = fmaf(krr[i], wr[j], acc[i][j]);
        }
        __syncthreads();
    }
    if ((tid & 7) == 0) esred[tid >> 3] = esum;
    __syncthreads();
    if (tid == 0) {
        float t = 0.f;
#pragma unroll
        for (int i = 0; i < 32; i++) t += esred[i];
        g_esum[chunk * BH + bh] = t;
    }
    float* dst = g_kvpart + ((size_t)chunk * BH + bh) * Dd * Dd;
#pragma unroll
    for (int i = 0; i < 4; i++)
#pragma unroll
        for (int j = 0; j < 4; j++)
            dst[(d0 + i) * Dd + e0 + j] = acc[i][j];
}

// ---------------- reduce kv partials, apply softmax scale C/Σe ----------------
__global__ void k_kvred()
{
    const int i = blockIdx.x * blockDim.x + threadIdx.x;
    if (i >= BH * Dd * Dd) return;
    const int bh = i >> 12;
    float es = 0.f;
#pragma unroll
    for (int c = 0; c < MCH; c++) es += g_esum[c * BH + bh];
    const float scale = (float)Cc / es;
    float s = 0.f;
#pragma unroll
    for (int c = 0; c < MCH; c++) s += g_kvpart[(size_t)c * BH * Dd * Dd + i];
    g_kv[i] = s * scale;
}

// ---------------- out_update = (q @ kv) * si * sigmoid(q·(kso+eps)+eps) -> fp16 ----------------
__global__ void __launch_bounds__(256) k_outupd()
{
    const int bh = blockIdx.y, nt = blockIdx.x;
    const int b = bh >> 3, h = bh & 7;
    __shared__ float kvs[64][64];
    __shared__ float qsT[64][68];
    __shared__ float ksoS[64];
    const int tid = threadIdx.x;

    if (tid < 64) {
        float a = 0.f;
#pragma unroll
        for (int c = 0; c < MCH; c++) a += g_kpart2[(c * BH + bh) * Dd + tid];
        ksoS[tid] = a + EPSf;
    }

    const float4* kvsrc = (const float4*)(g_kv + (size_t)bh * (Dd * Dd));
    for (int i = tid; i < 1024; i += 256) ((float4*)kvs)[i] = kvsrc[i];

    const int lr = tid >> 3;
    const int lc = (tid & 7) << 3;
    const __half* qb = g_qh + (size_t)bh * Ntok * Dd + (size_t)(nt * 64) * Dd;
#pragma unroll
    for (int rr = lr; rr < 64; rr += 32) {
        uint4 qraw = *(const uint4*)(qb + rr * Dd + lc);
        const __half2* qh2 = (const __half2*)&qraw;
#pragma unroll
        for (int j = 0; j < 4; j++) {
            float2 qf = __half22float2(qh2[j]);
            qsT[lc + 2 * j][rr]     = qf.x;
            qsT[lc + 2 * j + 1][rr] = qf.y;
        }
    }
    __syncthreads();

    float ksoSum = 0.f;
#pragma unroll
    for (int d = 0; d < 64; d++) ksoSum += ksoS[d];

    const int n0 = (tid & 15) << 2, e0 = (tid >> 4) << 2;
    float acc[4][4] = {};
    float sadot[4] = {};
#pragma unroll
    for (int d = 0; d < 64; d++) {
        float4 qa = *(const float4*)&qsT[d][n0];
        float4 kf = *(const float4*)&kvs[d][e0];
        const float ko = ksoS[d];
        float qr[4] = {qa.x, qa.y, qa.z, qa.w};
        float krr[4] = {kf.x, kf.y, kf.z, kf.w};
#pragma unroll
        for (int i = 0; i < 4; i++) {
            sadot[i] = fmaf(qr[i], ko, sadot[i]);
#pragma unroll
            for (int j = 0; j < 4; j++)
                acc[i][j] = fmaf(qr[i], krr[j], acc[i][j]);
        }
    }

#pragma unroll
    for (int i = 0; i < 4; i++) {
        const int n = nt * 64 + n0 + i;
        const float cs_sink = sadot[i] + EPSf * ksoSum + EPSf;
        const float sa = 1.f / (1.f + expf(-cs_sink));
        const float scale = g_si[bh * Ntok + n] * sa;
        const int np = (h << 9) | (n >> 3);
        const int cbase = (n & 7) << 6;
        const size_t lin = (size_t)(b * Ntok + np) * Cc + cbase + e0;
        __half2 h01 = __floats2half2_rn(acc[i][0] * scale, acc[i][1] * scale);
        __half2 h23 = __floats2half2_rn(acc[i][2] * scale, acc[i][3] * scale);
        *(__half2*)(g_Oh + lin)     = h01;
        *(__half2*)(g_Oh + lin + 2) = h23;
    }
}

// ---------------- launch ----------------
extern "C" void kernel_launch(void* const* d_in, const int* in_sizes, int n_in,
                              void* d_out, int out_size)
{
    const float* query = (const float*)d_in[0];
    const float* Wq = (const float*)d_in[1];
    const float* bq = (const float*)d_in[2];
    const float* Wk = (const float*)d_in[3];
    const float* bk = (const float*)d_in[4];
    const float* Wv = (const float*)d_in[5];
    const float* bv = (const float*)d_in[6];
    const float* Wo = (const float*)d_in[7];
    const float* bo = (const float*)d_in[8];
    const float* temp = (const float*)d_in[9];
    float* out = (float*)d_out;

    const int DSMEM = 3 * 32768 + 1024;
    cudaFuncSetAttribute(gemm_tc, cudaFuncAttributeMaxDynamicSharedMemorySize, DSMEM);

    __half *pAh, *pOh, *pB;
    void* pIcol;
    cudaGetSymbolAddress((void**)&pAh, g_Ah);
    cudaGetSymbolAddress((void**)&pOh, g_Oh);
    cudaGetSymbolAddress((void**)&pB,  g_B);
    cudaGetSymbolAddress(&pIcol, g_icol);

    // zero fixed-point colsum accumulators (graph-capturable async memset)
    cudaMemsetAsync(pIcol, 0, 2 * BH * Dd * sizeof(unsigned long long));

    // operand conversion
    k_split<<<16384, 256>>>(query, pAh);
    k_convW<<<dim3(16, 16, 4), dim3(32, 8)>>>(Wq, Wk, Wv, Wo, pB);

    // q/k/v projections in one launch (z selects mode/weights); colsum fused in epilogue
    gemm_tc<<<dim3(4, 256, 3), 256, DSMEM>>>(pAh, pB, bq, bk, bv, nullptr, nullptr, 0);

    k_fuse1<<<dim3(MCH, BH), 256>>>();
    k_kv<<<dim3(MCH, BH), 256>>>(temp);
    k_kvred<<<(BH * Dd * Dd + 255) / 256, 256>>>();
    k_outupd<<<dim3(64, BH), 256>>>();

    // output projection (+bias+residual)
    gemm_tc<<<dim3(4, 256, 1), 256, DSMEM>>>(pOh, pB + 3 * (512 * 512), bo, bo, bo,
                                             query, out, 3);
}

// round 10
// speedup vs baseline: 1.1777x; 1.0470x over previous
#include <cuda_runtime.h>
#include <cuda_fp16.h>
#include <math.h>
#include <stdint.h>

#define Ntok 4096
#define Bb   8
#define Cc   512
#define Hh   8
#define Dd   64
#define BH   64          // B*H
#define EPSf 1e-6f
#define NCHUNK 8         // 512 K / 64 per chunk
#define MCH   16         // mid-section chunks

// ---------------- scratch (static device arrays; no allocation) ----------------
__device__ __half g_qh[BH * Ntok * Dd];    // (B,H,N,D) sigmoid(q proj) fp16
__device__ __half g_kh[BH * Ntok * Dd];
__device__ __half g_vh[BH * Ntok * Dd];
__device__ float g_si[BH * Ntok];
__device__ float g_kpart[MCH * BH * Dd],  g_qpart[MCH * BH * Dd];   // plain col sums
__device__ float g_kpart2[MCH * BH * Dd], g_qpart2[MCH * BH * Dd];  // weighted col sums
__device__ float g_esum[MCH * BH];                                   // exp-sum partials
__device__ float g_kv[BH * Dd * Dd];
__device__ float g_kvpart[MCH * BH * Dd * Dd];

// fp16 GEMM operands
__device__ __half g_Ah[32768 * 512];       // fp16(query)
__device__ __half g_Oh[32768 * 512];       // fp16(out_update), scrambled (B,N,C)
__device__ __half g_B[4 * 512 * 512];      // [proj][n][k]

// ---------------- PTX helpers (base-arch only) ----------------
__device__ __forceinline__ uint32_t smem_u32(const void* p) {
    uint32_t a;
    asm("{ .reg .u64 t; cvta.to.shared.u64 t, %1; cvt.u32.u64 %0, t; }" : "=r"(a) : "l"(p));
    return a;
}
__device__ __forceinline__ void cp16(uint32_t dst, const void* src) {
    asm volatile("cp.async.cg.shared.global [%0], [%1], 16;" :: "r"(dst), "l"(src) : "memory");
}
__device__ __forceinline__ void cp_commit() {
    asm volatile("cp.async.commit_group;" ::: "memory");
}
__device__ __forceinline__ void cp_wait2() {
    asm volatile("cp.async.wait_group 2;" ::: "memory");
}
__device__ __forceinline__ void ldm4(uint32_t* r, uint32_t addr) {
    asm volatile("ldmatrix.sync.aligned.m8n8.x4.shared.b16 {%0,%1,%2,%3}, [%4];"
                 : "=r"(r[0]), "=r"(r[1]), "=r"(r[2]), "=r"(r[3]) : "r"(addr));
}
__device__ __forceinline__ void mma16816(float* c, const uint32_t* a, const uint32_t* b) {
    asm volatile(
        "mma.sync.aligned.m16n8k16.row.col.f32.f16.f16.f32 "
        "{%0,%1,%2,%3}, {%4,%5,%6,%7}, {%8,%9}, {%0,%1,%2,%3};"
        : "+f"(c[0]), "+f"(c[1]), "+f"(c[2]), "+f"(c[3])
        : "r"(a[0]), "r"(a[1]), "r"(a[2]), "r"(a[3]), "r"(b[0]), "r"(b[1]));
}

// ---------------- conversion kernels ----------------
__global__ void k_split(const float* __restrict__ src, __half* __restrict__ dst)
{
    int i = blockIdx.x * blockDim.x + threadIdx.x;
    float4 v = ((const float4*)src)[i];
    __half2* hp = (__half2*)dst;
    hp[2 * i]     = __floats2half2_rn(v.x, v.y);
    hp[2 * i + 1] = __floats2half2_rn(v.z, v.w);
}

__global__ void k_convW(const float* __restrict__ Wq, const float* __restrict__ Wk,
                        const float* __restrict__ Wv, const float* __restrict__ Wo,
                        __half* __restrict__ Bop)
{
    const float* W = (blockIdx.z == 0) ? Wq : (blockIdx.z == 1) ? Wk
                   : (blockIdx.z == 2) ? Wv : Wo;
    __half* Bp = Bop + (size_t)blockIdx.z * (512 * 512);
    __shared__ float t[32][33];
    const int k0 = blockIdx.y * 32, n0 = blockIdx.x * 32;
    const int tx = threadIdx.x, ty = threadIdx.y;  // (32,8)
    for (int j = ty; j < 32; j += 8) t[j][tx] = W[(size_t)(k0 + j) * 512 + n0 + tx];
    __syncthreads();
    for (int j = ty; j < 32; j += 8)
        Bp[(size_t)(n0 + j) * 512 + (k0 + tx)] = __float2half_rn(t[tx][j]);
}

// ---------------- mma.sync GEMM (f32 acc): D[32768,512] = A[.,512] @ B^T ----------------
// mode 0: q (sigmoid -> g_qh), 1: k -> g_kh, 2: v -> g_vh, 3: out (+bias+resid -> d_out)
__global__ void __launch_bounds__(256) gemm_tc(
    const __half* __restrict__ A, const __half* __restrict__ Bbase,
    const float* __restrict__ b0, const float* __restrict__ b1, const float* __restrict__ b2,
    const float* __restrict__ resid, float* __restrict__ out, int modeBase)
{
    extern __shared__ char dyn[];
    const uint32_t sbase = (smem_u32(dyn) + 1023u) & ~1023u;
    char* dynA = dyn + (sbase - smem_u32(dyn));
    const int tid = threadIdx.x;
    const int wid = tid >> 5, lane = tid & 31;
    const int bn = blockIdx.x * 128, bm = blockIdx.y * 128;
    const int mode = modeBase + blockIdx.z;
    const __half* Bop = Bbase + (size_t)blockIdx.z * (512 * 512);
    const float* bias = (mode == 1) ? b1 : (mode == 2) ? b2 : b0;
    const int warpM = wid & 3, warpN = wid >> 2;   // 4 x 2 warps -> 32x64 warp tile

    float acc[2][8][4];
#pragma unroll
    for (int mf = 0; mf < 2; mf++)
#pragma unroll
        for (int nf = 0; nf < 8; nf++)
#pragma unroll
            for (int i = 0; i < 4; i++) acc[mf][nf][i] = 0.f;

    int aRow[2], bRow[4];
#pragma unroll
    for (int mf = 0; mf < 2; mf++)
        aRow[mf] = warpM * 32 + mf * 16 + (lane & 7) + ((lane >> 3) & 1) * 8;
    const int aHi = lane >> 4;
#pragma unroll
    for (int nf2 = 0; nf2 < 4; nf2++)
        bRow[nf2] = warpN * 64 + nf2 * 16 + (lane & 7) + (lane >> 4) * 8;
    const int bHi = (lane >> 3) & 1;

    auto issue = [&](int c) {
        const int akoff = c << 6;
        const uint32_t buf = sbase + (uint32_t)(c % 3) * 32768u;
#pragma unroll
        for (int t = 0; t < 4; t++) {
            int s = tid + (t << 8);
            int row = s >> 3, sc = s & 7;
            uint32_t off = row * 128 + ((sc ^ (row & 7)) << 4);
            cp16(buf + off, A + ((size_t)(bm + row) * 512 + akoff + sc * 8));
        }
#pragma unroll
        for (int t = 0; t < 4; t++) {
            int s = tid + (t << 8);
            int row = s >> 3, sc = s & 7;
            uint32_t off = row * 128 + ((sc ^ (row & 7)) << 4);
            cp16(buf + 16384u + off, Bop + ((size_t)(bn + row) * 512 + akoff + sc * 8));
        }
    };

    issue(0); cp_commit();
    issue(1); cp_commit();

    for (int c = 0; c < NCHUNK; c++) {
        if (c + 2 < NCHUNK) issue(c + 2);
        cp_commit();
        cp_wait2();
        __syncthreads();

        const uint32_t abuf = sbase + (uint32_t)(c % 3) * 32768u;
        const uint32_t bbuf = abuf + 16384u;
#pragma unroll
        for (int ks = 0; ks < 4; ks++) {
            uint32_t a[2][4], b[4][4];
#pragma unroll
            for (int mf = 0; mf < 2; mf++) {
                const int row = aRow[mf];
                const int cc = 2 * ks + aHi;
                ldm4(a[mf], abuf + row * 128 + ((cc ^ (row & 7)) << 4));
            }
#pragma unroll
            for (int nf2 = 0; nf2 < 4; nf2++) {
                const int row = bRow[nf2];
                const int cc = 2 * ks + bHi;
                ldm4(b[nf2], bbuf + row * 128 + ((cc ^ (row & 7)) << 4));
            }
#pragma unroll
            for (int mf = 0; mf < 2; mf++)
#pragma unroll
                for (int nf = 0; nf < 8; nf++)
                    mma16816(acc[mf][nf], a[mf], &b[nf >> 1][(nf & 1) * 2]);
        }
        __syncthreads();
    }

    // ---------------- epilogue ----------------
    if (mode <= 2) {
        __half* smh = (__half*)dynA;
        const int rloc = warpM * 32 + (lane >> 2);
        const int cloc = warpN * 64 + ((lane & 3) << 1);
#pragma unroll
        for (int mf = 0; mf < 2; mf++)
#pragma unroll
            for (int half = 0; half < 2; half++) {
#pragma unroll
                for (int nf = 0; nf < 8; nf++) {
                    const int c0 = bn + cloc + nf * 8;
                    float vx = acc[mf][nf][half * 2 + 0] + bias[c0];
                    float vy = acc[mf][nf][half * 2 + 1] + bias[c0 + 1];
                    if (mode <= 1) {
                        vx = 1.f / (1.f + expf(-vx));
                        vy = 1.f / (1.f + expf(-vy));
                    }
                    *(__half2*)&smh[(rloc + mf * 16 + half * 8) * 136 + cloc + nf * 8]
                        = __floats2half2_rn(vx, vy);
                }
            }
        __syncthreads();
        __half* dstg = (mode == 0) ? g_qh : (mode == 1) ? g_kh : g_vh;
        const int h0 = bn >> 6;
        const int hl = tid >> 7, nl = (tid & 127) >> 3, dp = tid & 7;
#pragma unroll
        for (int bb2 = 0; bb2 < 8; bb2++) {
            uint4 val = *(const uint4*)(smh + (size_t)(nl * 8 + bb2) * 136 + hl * 64 + dp * 8);
            *(uint4*)(dstg + ((size_t)((bb2 << 3) | (h0 + hl)) * Ntok + (bm >> 3) + nl) * Dd + dp * 8) = val;
        }
    } else {
        const int r0base = bm + warpM * 32 + (lane >> 2);
        const int cb = bn + warpN * 64 + ((lane & 3) << 1);
#pragma unroll
        for (int mf = 0; mf < 2; mf++)
#pragma unroll
            for (int half = 0; half < 2; half++) {
                const int r = r0base + mf * 16 + half * 8;
#pragma unroll
                for (int nf = 0; nf < 8; nf++) {
                    const int c0 = cb + nf * 8;
                    const int bb = r >> 12, n = r & 4095;
                    const size_t o = (size_t)((n << 3) | bb) * Cc + c0;
                    float2 rs = *(const float2*)(resid + o);
                    float2 v;
                    v.x = acc[mf][nf][half * 2 + 0] + bias[c0] + rs.x;
                    v.y = acc[mf][nf][half * 2 + 1] + bias[c0 + 1] + rs.y;
                    *(float2*)(out + o) = v;
                }
            }
    }
}

// ---------------- plain column sums over s (fp16 inputs, fp32 accum) ----------------
__global__ void k_colsum()
{
    const int bh = blockIdx.y, chunk = blockIdx.x;
    const int dp = threadIdx.x & 31, p = threadIdx.x >> 5;
    const __half* kb = g_kh + (size_t)bh * Ntok * Dd;
    const __half* qb = g_qh + (size_t)bh * Ntok * Dd;
    float ak0 = 0.f, ak1 = 0.f, aq0 = 0.f, aq1 = 0.f;
    const int s0 = chunk * 256;
    for (int s = s0 + p; s < s0 + 256; s += 8) {
        float2 kf = __half22float2(*(const __half2*)(kb + (size_t)s * Dd + 2 * dp));
        float2 qf = __half22float2(*(const __half2*)(qb + (size_t)s * Dd + 2 * dp));
        ak0 += kf.x; ak1 += kf.y;
        aq0 += qf.x; aq1 += qf.y;
    }
    __shared__ float sk[8][64], sq[8][64];
    sk[p][2 * dp] = ak0; sk[p][2 * dp + 1] = ak1;
    sq[p][2 * dp] = aq0; sq[p][2 * dp + 1] = aq1;
    __syncthreads();
    if (threadIdx.x < 64) {
        const int d = threadIdx.x;
        float a = 0.f, b = 0.f;
#pragma unroll
        for (int i = 0; i < 8; i++) { a += sk[i][d]; b += sq[i][d]; }
        g_kpart[(chunk * BH + bh) * Dd + d] = a;
        g_qpart[(chunk * BH + bh) * Dd + d] = b;
    }
}

// ---------------- fused: reduce colsum partials + rownorm (si/so) + weighted colsums ----------------
// SHUFFLE-FREE: phase 1 = thread-per-row private dots; phase 2 = coalesced weighted colsums.
__global__ void __launch_bounds__(256) k_fuse1()
{
    const int bh = blockIdx.y, chunk = blockIdx.x;
    const int tid = threadIdx.x;
    __shared__ float ksS[64], qsS[64];
    __shared__ float siS[256], soS[256];
    __shared__ float sQ[8][64], sK[8][64];
    if (tid < 64) {
        float a = 0.f, b = 0.f;
#pragma unroll
        for (int c = 0; c < MCH; c++) {
            a += g_kpart[(c * BH + bh) * Dd + tid];
            b += g_qpart[(c * BH + bh) * Dd + tid];
        }
        ksS[tid] = a + EPSf;
        qsS[tid] = b + EPSf;
    }
    __syncthreads();
    const __half* qb = g_qh + (size_t)bh * Ntok * Dd;
    const __half* kb = g_kh + (size_t)bh * Ntok * Dd;

    // phase 1: one thread per s-row, private dot over d (no shuffles)
    {
        const int s = chunk * 256 + tid;
        const uint4* qrow = (const uint4*)(qb + (size_t)s * Dd);
        const uint4* krow = (const uint4*)(kb + (size_t)s * Dd);
        float s1 = 0.f, s2 = 0.f;
#pragma unroll
        for (int j = 0; j < 8; j++) {
            uint4 qraw = qrow[j];
            uint4 kraw = krow[j];
            const __half2* qh2 = (const __half2*)&qraw;
            const __half2* kh2 = (const __half2*)&kraw;
#pragma unroll
            for (int u = 0; u < 4; u++) {
                float2 qf = __half22float2(qh2[u]);
                float2 kf = __half22float2(kh2[u]);
                const int d = j * 8 + 2 * u;
                s1 += (qf.x + EPSf) * ksS[d] + (qf.y + EPSf) * ksS[d + 1];
                s2 += (kf.x + EPSf) * qsS[d] + (kf.y + EPSf) * qsS[d + 1];
            }
        }
        const float si = 1.f / (s1 + EPSf);
        const float so = 1.f / (s2 + EPSf);
        g_si[bh * Ntok + s] = si;
        siS[tid] = si; soS[tid] = so;
    }
    __syncthreads();

    // phase 2: weighted colsums, coalesced (rows L1-hot from phase 1)
    const int p = tid >> 5, dp = tid & 31;
    float aq0 = 0.f, aq1 = 0.f, ak0 = 0.f, ak1 = 0.f;
#pragma unroll 4
    for (int i = 0; i < 32; i++) {
        const int sl = p + 8 * i;
        const int s = chunk * 256 + sl;
        float2 qf = __half22float2(*(const __half2*)(qb + (size_t)s * Dd + 2 * dp));
        float2 kf = __half22float2(*(const __half2*)(kb + (size_t)s * Dd + 2 * dp));
        const float si = siS[sl], so = soS[sl];
        aq0 += si * qf.x; aq1 += si * qf.y;
        ak0 += so * kf.x; ak1 += so * kf.y;
    }
    sQ[p][2 * dp] = aq0; sQ[p][2 * dp + 1] = aq1;
    sK[p][2 * dp] = ak0; sK[p][2 * dp + 1] = ak1;
    __syncthreads();
    if (tid < 64) {
        float sq = 0.f, sk = 0.f;
#pragma unroll
        for (int w2 = 0; w2 < 8; w2++) { sq += sQ[w2][tid]; sk += sK[w2][tid]; }
        g_qpart2[(chunk * BH + bh) * Dd + tid] = sq;   // si-weighted q sums -> qsi
        g_kpart2[(chunk * BH + bh) * Dd + tid] = sk;   // so-weighted k sums -> kso
    }
}

// ---------------- fused: conserved_source (inline) + exp + kv partials + exp-sum ----------------
__global__ void __launch_bounds__(256) k_kv(const float* __restrict__ tptr)
{
    const int bh = blockIdx.y, chunk = blockIdx.x;
    __shared__ float ks[32][64];
    __shared__ float ws[32][64];
    __shared__ float qsiS[64];
    __shared__ float esred[32];
    const int tid = threadIdx.x;
    const int lr = tid >> 3;
    const int lc = (tid & 7) << 3;
    if (tid < 64) {
        float a = 0.f;
#pragma unroll
        for (int c = 0; c < MCH; c++) a += g_qpart2[(c * BH + bh) * Dd + tid];
        qsiS[tid] = a + EPSf;
    }
    __syncthreads();
    const float invT = 1.f / tptr[0];
    const size_t base = (size_t)bh * Ntok * Dd;
    const int d0 = (tid & 15) << 2, e0 = (tid >> 4) << 2;
    float acc[4][4] = {};
    float esum = 0.f;
    for (int s0 = chunk * 256; s0 < chunk * 256 + 256; s0 += 32) {
        const int s = s0 + lr;
        uint4 kraw = *(const uint4*)(g_kh + base + (size_t)s * Dd + lc);
        uint4 vraw = *(const uint4*)(g_vh + base + (size_t)s * Dd + lc);
        const __half2* kh2 = (const __half2*)&kraw;
        const __half2* vh2 = (const __half2*)&vraw;
        float kvals[8], vvals[8];
        float pd = 0.f;
#pragma unroll
        for (int j = 0; j < 4; j++) {
            float2 kf = __half22float2(kh2[j]);
            float2 vf = __half22float2(vh2[j]);
            kvals[2 * j] = kf.x; kvals[2 * j + 1] = kf.y;
            vvals[2 * j] = vf.x; vvals[2 * j + 1] = vf.y;
            pd += (kf.x + EPSf) * qsiS[lc + 2 * j] + (kf.y + EPSf) * qsiS[lc + 2 * j + 1];
        }
        pd += __shfl_xor_sync(0xffffffffu, pd, 1);
        pd += __shfl_xor_sync(0xffffffffu, pd, 2);
        pd += __shfl_xor_sync(0xffffffffu, pd, 4);
        const float cs = fminf(1.f, fmaxf(-1.f, pd + EPSf));
        const float e = expf(cs * invT);
        if ((tid & 7) == 0) esum += e;
#pragma unroll
        for (int j = 0; j < 8; j++) {
            ks[lr][lc + j] = kvals[j];
            ws[lr][lc + j] = vvals[j] * e;
        }
        __syncthreads();
#pragma unroll
        for (int ss = 0; ss < 32; ss++) {
            float4 kf = *(const float4*)&ks[ss][d0];
            float4 wf = *(const float4*)&ws[ss][e0];
            float krr[4] = {kf.x, kf.y, kf.z, kf.w};
            float wr[4] = {wf.x, wf.y, wf.z, wf.w};
#pragma unroll
            for (int i = 0; i < 4; i++)
#pragma unroll
                for (int j = 0; j < 4; j++)
                    acc[i][j] = fmaf(krr[i], wr[j], acc[i][j]);
        }
        __syncthreads();
    }
    if ((tid & 7) == 0) esred[tid >> 3] = esum;
    __syncthreads();
    if (tid == 0) {
        float t = 0.f;
#pragma unroll
        for (int i = 0; i < 32; i++) t += esred[i];
        g_esum[chunk * BH + bh] = t;
    }
    float* dst = g_kvpart + ((size_t)chunk * BH + bh) * Dd * Dd;
#pragma unroll
    for (int i = 0; i < 4; i++)
#pragma unroll
        for (int j = 0; j < 4; j++)
            dst[(d0 + i) * Dd + e0 + j] = acc[i][j];
}

// ---------------- reduce kv partials, apply softmax scale C/Σe ----------------
__global__ void k_kvred()
{
    const int i = blockIdx.x * blockDim.x + threadIdx.x;
    if (i >= BH * Dd * Dd) return;
    const int bh = i >> 12;
    float es = 0.f;
#pragma unroll
    for (int c = 0; c < MCH; c++) es += g_esum[c * BH + bh];
    const float scale = (float)Cc / es;
    float s = 0.f;
#pragma unroll
    for (int c = 0; c < MCH; c++) s += g_kvpart[(size_t)c * BH * Dd * Dd + i];
    g_kv[i] = s * scale;
}

// ---------------- out_update = (q @ kv) * si * sigmoid(q·(kso+eps)+eps) -> fp16 ----------------
__global__ void __launch_bounds__(256) k_outupd()
{
    const int bh = blockIdx.y, nt = blockIdx.x;
    const int b = bh >> 3, h = bh & 7;
    __shared__ float kvs[64][64];
    __shared__ float qsT[64][68];
    __shared__ float ksoS[64];
    const int tid = threadIdx.x;

    if (tid < 64) {
        float a = 0.f;
#pragma unroll
        for (int c = 0; c < MCH; c++) a += g_kpart2[(c * BH + bh) * Dd + tid];
        ksoS[tid] = a + EPSf;
    }

    const float4* kvsrc = (const float4*)(g_kv + (size_t)bh * (Dd * Dd));
    for (int i = tid; i < 1024; i += 256) ((float4*)kvs)[i] = kvsrc[i];

    const int lr = tid >> 3;
    const int lc = (tid & 7) << 3;
    const __half* qb = g_qh + (size_t)bh * Ntok * Dd + (size_t)(nt * 64) * Dd;
#pragma unroll
    for (int rr = lr; rr < 64; rr += 32) {
        uint4 qraw = *(const uint4*)(qb + rr * Dd + lc);
        const __half2* qh2 = (const __half2*)&qraw;
#pragma unroll
        for (int j = 0; j < 4; j++) {
            float2 qf = __half22float2(qh2[j]);
            qsT[lc + 2 * j][rr]     = qf.x;
            qsT[lc + 2 * j + 1][rr] = qf.y;
        }
    }
    __syncthreads();

    float ksoSum = 0.f;
#pragma unroll
    for (int d = 0; d < 64; d++) ksoSum += ksoS[d];

    const int n0 = (tid & 15) << 2, e0 = (tid >> 4) << 2;
    float acc[4][4] = {};
    float sadot[4] = {};
#pragma unroll
    for (int d = 0; d < 64; d++) {
        float4 qa = *(const float4*)&qsT[d][n0];
        float4 kf = *(const float4*)&kvs[d][e0];
        const float ko = ksoS[d];
        float qr[4] = {qa.x, qa.y, qa.z, qa.w};
        float krr[4] = {kf.x, kf.y, kf.z, kf.w};
#pragma unroll
        for (int i = 0; i < 4; i++) {
            sadot[i] = fmaf(qr[i], ko, sadot[i]);
#pragma unroll
            for (int j = 0; j < 4; j++)
                acc[i][j] = fmaf(qr[i], krr[j], acc[i][j]);
        }
    }

#pragma unroll
    for (int i = 0; i < 4; i++) {
        const int n = nt * 64 + n0 + i;
        const float cs_sink = sadot[i] + EPSf * ksoSum + EPSf;
        const float sa = 1.f / (1.f + expf(-cs_sink));
        const float scale = g_si[bh * Ntok + n] * sa;
        const int np = (h << 9) | (n >> 3);
        const int cbase = (n & 7) << 6;
        const size_t lin = (size_t)(b * Ntok + np) * Cc + cbase + e0;
        __half2 h01 = __floats2half2_rn(acc[i][0] * scale, acc[i][1] * scale);
        __half2 h23 = __floats2half2_rn(acc[i][2] * scale, acc[i][3] * scale);
        *(__half2*)(g_Oh + lin)     = h01;
        *(__half2*)(g_Oh + lin + 2) = h23;
    }
}

// ---------------- launch ----------------
extern "C" void kernel_launch(void* const* d_in, const int* in_sizes, int n_in,
                              void* d_out, int out_size)
{
    const float* query = (const float*)d_in[0];
    const float* Wq = (const float*)d_in[1];
    const float* bq = (const float*)d_in[2];
    const float* Wk = (const float*)d_in[3];
    const float* bk = (const float*)d_in[4];
    const float* Wv = (const float*)d_in[5];
    const float* bv = (const float*)d_in[6];
    const float* Wo = (const float*)d_in[7];
    const float* bo = (const float*)d_in[8];
    const float* temp = (const float*)d_in[9];
    float* out = (float*)d_out;

    const int DSMEM = 3 * 32768 + 1024;
    cudaFuncSetAttribute(gemm_tc, cudaFuncAttributeMaxDynamicSharedMemorySize, DSMEM);

    __half *pAh, *pOh, *pB;
    cudaGetSymbolAddress((void**)&pAh, g_Ah);
    cudaGetSymbolAddress((void**)&pOh, g_Oh);
    cudaGetSymbolAddress((void**)&pB,  g_B);

    // operand conversion
    k_split<<<16384, 256>>>(query, pAh);
    k_convW<<<dim3(16, 16, 4), dim3(32, 8)>>>(Wq, Wk, Wv, Wo, pB);

    // q/k/v projections in one launch (z selects mode/weights)
    gemm_tc<<<dim3(4, 256, 3), 256, DSMEM>>>(pAh, pB, bq, bk, bv, nullptr, nullptr, 0);

    k_colsum<<<dim3(MCH, BH), 256>>>();
    k_fuse1<<<dim3(MCH, BH), 256>>>();
    k_kv<<<dim3(MCH, BH), 256>>>(temp);
    k_kvred<<<(BH * Dd * Dd + 255) / 256, 256>>>();
    k_outupd<<<dim3(64, BH), 256>>>();

    // output projection (+bias+residual)
    gemm_tc<<<dim3(4, 256, 1), 256, DSMEM>>>(pOh, pB + 3 * (512 * 512), bo, bo, bo,
                                             query, out, 3);
}

// round 11
// speedup vs baseline: 1.1839x; 1.0053x over previous
#include <cuda_runtime.h>
#include <cuda_fp16.h>
#include <math.h>
#include <stdint.h>

#define Ntok 4096
#define Bb   8
#define Cc   512
#define Hh   8
#define Dd   64
#define BH   64          // B*H
#define EPSf 1e-6f
#define NCHUNK 8         // 512 K / 64 per chunk
#define MCH   16         // mid-section chunks
#define FIXSC 16777216.0f        // 2^24
#define FIXINV (1.0f / 16777216.0f)

// ---------------- scratch (static device arrays; no allocation) ----------------
__device__ __half g_qh[BH * Ntok * Dd];    // (B,H,N,D) sigmoid(q proj) fp16
__device__ __half g_kh[BH * Ntok * Dd];
__device__ __half g_vh[BH * Ntok * Dd];
__device__ float g_si[BH * Ntok];
__device__ unsigned long long g_icol[2][BH * Dd];                   // fixed-point col sums (0:q 1:k)
__device__ float g_kpart2[MCH * BH * Dd], g_qpart2[MCH * BH * Dd];  // weighted col sums
__device__ float g_esum[MCH * BH];                                   // exp-sum partials
__device__ float g_kv[BH * Dd * Dd];
__device__ float g_kvpart[MCH * BH * Dd * Dd];

// fp16 GEMM operands
__device__ __half g_Ah[32768 * 512];       // fp16(query)
__device__ __half g_Oh[32768 * 512];       // fp16(out_update), scrambled (B,N,C)
__device__ __half g_B[4 * 512 * 512];      // [proj][n][k]

// ---------------- PTX helpers (base-arch only) ----------------
__device__ __forceinline__ uint32_t smem_u32(const void* p) {
    uint32_t a;
    asm("{ .reg .u64 t; cvta.to.shared.u64 t, %1; cvt.u32.u64 %0, t; }" : "=r"(a) : "l"(p));
    return a;
}
__device__ __forceinline__ void cp16(uint32_t dst, const void* src) {
    asm volatile("cp.async.cg.shared.global [%0], [%1], 16;" :: "r"(dst), "l"(src) : "memory");
}
__device__ __forceinline__ void cp_commit() {
    asm volatile("cp.async.commit_group;" ::: "memory");
}
__device__ __forceinline__ void cp_wait2() {
    asm volatile("cp.async.wait_group 2;" ::: "memory");
}
__device__ __forceinline__ void ldm4(uint32_t* r, uint32_t addr) {
    asm volatile("ldmatrix.sync.aligned.m8n8.x4.shared.b16 {%0,%1,%2,%3}, [%4];"
                 : "=r"(r[0]), "=r"(r[1]), "=r"(r[2]), "=r"(r[3]) : "r"(addr));
}
__device__ __forceinline__ void mma16816(float* c, const uint32_t* a, const uint32_t* b) {
    asm volatile(
        "mma.sync.aligned.m16n8k16.row.col.f32.f16.f16.f32 "
        "{%0,%1,%2,%3}, {%4,%5,%6,%7}, {%8,%9}, {%0,%1,%2,%3};"
        : "+f"(c[0]), "+f"(c[1]), "+f"(c[2]), "+f"(c[3])
        : "r"(a[0]), "r"(a[1]), "r"(a[2]), "r"(a[3]), "r"(b[0]), "r"(b[1]));
}

// ---------------- merged conversion kernel ----------------
// blocks [0, 16384): fp32->fp16 split of query
// blocks [16384, 17408): weight transpose+convert (4 projections)
__global__ void k_conv(const float* __restrict__ src, __half* __restrict__ dst,
                       const float* __restrict__ Wq, const float* __restrict__ Wk,
                       const float* __restrict__ Wv, const float* __restrict__ Wo,
                       __half* __restrict__ Bop)
{
    if (blockIdx.x < 16384) {
        int i = blockIdx.x * 256 + threadIdx.x;
        float4 v = ((const float4*)src)[i];
        __half2* hp = (__half2*)dst;
        hp[2 * i]     = __floats2half2_rn(v.x, v.y);
        hp[2 * i + 1] = __floats2half2_rn(v.z, v.w);
    } else {
        const int bid = blockIdx.x - 16384;     // 0..1023
        const int z = bid >> 8;                  // projection
        const int rem = bid & 255;
        const int by = rem >> 4, bx = rem & 15;
        const int tx = threadIdx.x & 31, ty = threadIdx.x >> 5;  // (32,8)
        const float* W = (z == 0) ? Wq : (z == 1) ? Wk : (z == 2) ? Wv : Wo;
        __half* Bp = Bop + (size_t)z * (512 * 512);
        __shared__ float t[32][33];
        const int k0 = by * 32, n0 = bx * 32;
        for (int j = ty; j < 32; j += 8) t[j][tx] = W[(size_t)(k0 + j) * 512 + n0 + tx];
        __syncthreads();
        for (int j = ty; j < 32; j += 8)
            Bp[(size_t)(n0 + j) * 512 + (k0 + tx)] = __float2half_rn(t[tx][j]);
    }
}

// ---------------- mma.sync GEMM (f32 acc): D[32768,512] = A[.,512] @ B^T ----------------
// mode 0: q (sigmoid -> g_qh + colsum), 1: k -> g_kh + colsum, 2: v -> g_vh,
// mode 3: out (+bias+resid -> d_out)
__global__ void __launch_bounds__(256) gemm_tc(
    const __half* __restrict__ A, const __half* __restrict__ Bbase,
    const float* __restrict__ b0, const float* __restrict__ b1, const float* __restrict__ b2,
    const float* __restrict__ resid, float* __restrict__ out, int modeBase)
{
    extern __shared__ char dyn[];
    const uint32_t sbase = (smem_u32(dyn) + 1023u) & ~1023u;
    char* dynA = dyn + (sbase - smem_u32(dyn));
    const int tid = threadIdx.x;
    const int wid = tid >> 5, lane = tid & 31;
    const int bn = blockIdx.x * 128, bm = blockIdx.y * 128;
    const int mode = modeBase + blockIdx.z;
    const __half* Bop = Bbase + (size_t)blockIdx.z * (512 * 512);
    const float* bias = (mode == 1) ? b1 : (mode == 2) ? b2 : b0;
    const int warpM = wid & 3, warpN = wid >> 2;   // 4 x 2 warps -> 32x64 warp tile

    float acc[2][8][4];
#pragma unroll
    for (int mf = 0; mf < 2; mf++)
#pragma unroll
        for (int nf = 0; nf < 8; nf++)
#pragma unroll
            for (int i = 0; i < 4; i++) acc[mf][nf][i] = 0.f;

    int aRow[2], bRow[4];
#pragma unroll
    for (int mf = 0; mf < 2; mf++)
        aRow[mf] = warpM * 32 + mf * 16 + (lane & 7) + ((lane >> 3) & 1) * 8;
    const int aHi = lane >> 4;
#pragma unroll
    for (int nf2 = 0; nf2 < 4; nf2++)
        bRow[nf2] = warpN * 64 + nf2 * 16 + (lane & 7) + (lane >> 4) * 8;
    const int bHi = (lane >> 3) & 1;

    auto issue = [&](int c) {
        const int akoff = c << 6;
        const uint32_t buf = sbase + (uint32_t)(c % 3) * 32768u;
#pragma unroll
        for (int t = 0; t < 4; t++) {
            int s = tid + (t << 8);
            int row = s >> 3, sc = s & 7;
            uint32_t off = row * 128 + ((sc ^ (row & 7)) << 4);
            cp16(buf + off, A + ((size_t)(bm + row) * 512 + akoff + sc * 8));
        }
#pragma unroll
        for (int t = 0; t < 4; t++) {
            int s = tid + (t << 8);
            int row = s >> 3, sc = s & 7;
            uint32_t off = row * 128 + ((sc ^ (row & 7)) << 4);
            cp16(buf + 16384u + off, Bop + ((size_t)(bn + row) * 512 + akoff + sc * 8));
        }
    };

    issue(0); cp_commit();
    issue(1); cp_commit();

    for (int c = 0; c < NCHUNK; c++) {
        if (c + 2 < NCHUNK) issue(c + 2);
        cp_commit();
        cp_wait2();
        __syncthreads();

        const uint32_t abuf = sbase + (uint32_t)(c % 3) * 32768u;
        const uint32_t bbuf = abuf + 16384u;
#pragma unroll
        for (int ks = 0; ks < 4; ks++) {
            uint32_t a[2][4], b[4][4];
#pragma unroll
            for (int mf = 0; mf < 2; mf++) {
                const int row = aRow[mf];
                const int cc = 2 * ks + aHi;
                ldm4(a[mf], abuf + row * 128 + ((cc ^ (row & 7)) << 4));
            }
#pragma unroll
            for (int nf2 = 0; nf2 < 4; nf2++) {
                const int row = bRow[nf2];
                const int cc = 2 * ks + bHi;
                ldm4(b[nf2], bbuf + row * 128 + ((cc ^ (row & 7)) << 4));
            }
#pragma unroll
            for (int mf = 0; mf < 2; mf++)
#pragma unroll
                for (int nf = 0; nf < 8; nf++)
                    mma16816(acc[mf][nf], a[mf], &b[nf >> 1][(nf & 1) * 2]);
        }
        __syncthreads();
    }

    // ---------------- epilogue ----------------
    if (mode <= 2) {
        __half* smh = (__half*)dynA;
        const int rloc = warpM * 32 + (lane >> 2);
        const int cloc = warpN * 64 + ((lane & 3) << 1);
#pragma unroll
        for (int mf = 0; mf < 2; mf++)
#pragma unroll
            for (int half = 0; half < 2; half++) {
#pragma unroll
                for (int nf = 0; nf < 8; nf++) {
                    const int c0 = bn + cloc + nf * 8;
                    float vx = acc[mf][nf][half * 2 + 0] + bias[c0];
                    float vy = acc[mf][nf][half * 2 + 1] + bias[c0 + 1];
                    if (mode <= 1) {
                        vx = 1.f / (1.f + expf(-vx));
                        vy = 1.f / (1.f + expf(-vy));
                    }
                    *(__half2*)&smh[(rloc + mf * 16 + half * 8) * 136 + cloc + nf * 8]
                        = __floats2half2_rn(vx, vy);
                }
            }
        __syncthreads();
        __half* dstg = (mode == 0) ? g_qh : (mode == 1) ? g_kh : g_vh;
        const int h0 = bn >> 6;
        const int hl = tid >> 7, nl = (tid & 127) >> 3, dp = tid & 7;
#pragma unroll
        for (int bb2 = 0; bb2 < 8; bb2++) {
            uint4 val = *(const uint4*)(smh + (size_t)(nl * 8 + bb2) * 136 + hl * 64 + dp * 8);
            *(uint4*)(dstg + ((size_t)((bb2 << 3) | (h0 + hl)) * Ntok + (bm >> 3) + nl) * Dd + dp * 8) = val;
        }
        // fused column sums (q/k): deterministic fixed-point atomics over the staged tile
        if (mode <= 1) {
            const int hl2 = tid >> 7;            // head within tile (0..1)
            const int b2 = (tid >> 4) & 7;       // batch
            const int d0 = (tid & 15) << 2;      // 4 d's
            float s0 = 0.f, s1 = 0.f, s2 = 0.f, s3 = 0.f;
#pragma unroll
            for (int n = 0; n < 16; n++) {
                const __half* rowp = smh + (size_t)(n * 8 + b2) * 136 + hl2 * 64 + d0;
                float2 p0 = __half22float2(*(const __half2*)rowp);
                float2 p1 = __half22float2(*(const __half2*)(rowp + 2));
                s0 += p0.x; s1 += p0.y; s2 += p1.x; s3 += p1.y;
            }
            const int bh = (b2 << 3) | ((bn >> 6) + hl2);
            unsigned long long* dst = &g_icol[mode][bh * Dd + d0];
            atomicAdd(dst + 0, (unsigned long long)(long long)llrintf(s0 * FIXSC));
            atomicAdd(dst + 1, (unsigned long long)(long long)llrintf(s1 * FIXSC));
            atomicAdd(dst + 2, (unsigned long long)(long long)llrintf(s2 * FIXSC));
            atomicAdd(dst + 3, (unsigned long long)(long long)llrintf(s3 * FIXSC));
        }
    } else {
        const int r0base = bm + warpM * 32 + (lane >> 2);
        const int cb = bn + warpN * 64 + ((lane & 3) << 1);
#pragma unroll
        for (int mf = 0; mf < 2; mf++)
#pragma unroll
            for (int half = 0; half < 2; half++) {
                const int r = r0base + mf * 16 + half * 8;
#pragma unroll
                for (int nf = 0; nf < 8; nf++) {
                    const int c0 = cb + nf * 8;
                    const int bb = r >> 12, n = r & 4095;
                    const size_t o = (size_t)((n << 3) | bb) * Cc + c0;
                    float2 rs = *(const float2*)(resid + o);
                    float2 v;
                    v.x = acc[mf][nf][half * 2 + 0] + bias[c0] + rs.x;
                    v.y = acc[mf][nf][half * 2 + 1] + bias[c0 + 1] + rs.y;
                    *(float2*)(out + o) = v;
                }
            }
    }
}

// ---------------- fused: rownorm (si/so) + weighted colsum partials ----------------
// SHUFFLE-FREE: phase 1 = thread-per-row private dots; phase 2 = coalesced weighted colsums.
__global__ void __launch_bounds__(256) k_fuse1()
{
    const int bh = blockIdx.y, chunk = blockIdx.x;
    const int tid = threadIdx.x;
    __shared__ float ksS[64], qsS[64];
    __shared__ float siS[256], soS[256];
    __shared__ float sQ[8][64], sK[8][64];
    if (tid < 64) {
        ksS[tid] = (float)(long long)g_icol[1][bh * Dd + tid] * FIXINV + EPSf;
        qsS[tid] = (float)(long long)g_icol[0][bh * Dd + tid] * FIXINV + EPSf;
    }
    __syncthreads();
    const __half* qb = g_qh + (size_t)bh * Ntok * Dd;
    const __half* kb = g_kh + (size_t)bh * Ntok * Dd;

    // phase 1: one thread per s-row, private dot over d (no shuffles)
    {
        const int s = chunk * 256 + tid;
        const uint4* qrow = (const uint4*)(qb + (size_t)s * Dd);
        const uint4* krow = (const uint4*)(kb + (size_t)s * Dd);
        float s1 = 0.f, s2 = 0.f;
#pragma unroll
        for (int j = 0; j < 8; j++) {
            uint4 qraw = qrow[j];
            uint4 kraw = krow[j];
            const __half2* qh2 = (const __half2*)&qraw;
            const __half2* kh2 = (const __half2*)&kraw;
#pragma unroll
            for (int u = 0; u < 4; u++) {
                float2 qf = __half22float2(qh2[u]);
                float2 kf = __half22float2(kh2[u]);
                const int d = j * 8 + 2 * u;
                s1 += (qf.x + EPSf) * ksS[d] + (qf.y + EPSf) * ksS[d + 1];
                s2 += (kf.x + EPSf) * qsS[d] + (kf.y + EPSf) * qsS[d + 1];
            }
        }
        const float si = 1.f / (s1 + EPSf);
        const float so = 1.f / (s2 + EPSf);
        g_si[bh * Ntok + s] = si;
        siS[tid] = si; soS[tid] = so;
    }
    __syncthreads();

    // phase 2: weighted colsums, coalesced (rows L1-hot from phase 1)
    const int p = tid >> 5, dp = tid & 31;
    float aq0 = 0.f, aq1 = 0.f, ak0 = 0.f, ak1 = 0.f;
#pragma unroll 4
    for (int i = 0; i < 32; i++) {
        const int sl = p + 8 * i;
        const int s = chunk * 256 + sl;
        float2 qf = __half22float2(*(const __half2*)(qb + (size_t)s * Dd + 2 * dp));
        float2 kf = __half22float2(*(const __half2*)(kb + (size_t)s * Dd + 2 * dp));
        const float si = siS[sl], so = soS[sl];
        aq0 += si * qf.x; aq1 += si * qf.y;
        ak0 += so * kf.x; ak1 += so * kf.y;
    }
    sQ[p][2 * dp] = aq0; sQ[p][2 * dp + 1] = aq1;
    sK[p][2 * dp] = ak0; sK[p][2 * dp + 1] = ak1;
    __syncthreads();
    if (tid < 64) {
        float sq = 0.f, sk = 0.f;
#pragma unroll
        for (int w2 = 0; w2 < 8; w2++) { sq += sQ[w2][tid]; sk += sK[w2][tid]; }
        g_qpart2[(chunk * BH + bh) * Dd + tid] = sq;   // si-weighted q sums -> qsi
        g_kpart2[(chunk * BH + bh) * Dd + tid] = sk;   // so-weighted k sums -> kso
    }
}

// ---------------- fused: conserved_source (inline) + exp + kv partials + exp-sum ----------------
__global__ void __launch_bounds__(256) k_kv(const float* __restrict__ tptr)
{
    const int bh = blockIdx.y, chunk = blockIdx.x;
    __shared__ float ks[32][64];
    __shared__ float ws[32][64];
    __shared__ float qsiS[64];
    __shared__ float esred[32];
    const int tid = threadIdx.x;
    const int lr = tid >> 3;
    const int lc = (tid & 7) << 3;
    if (tid < 64) {
        float a = 0.f;
#pragma unroll
        for (int c = 0; c < MCH; c++) a += g_qpart2[(c * BH + bh) * Dd + tid];
        qsiS[tid] = a + EPSf;
    }
    __syncthreads();
    const float invT = 1.f / tptr[0];
    const size_t base = (size_t)bh * Ntok * Dd;
    const int d0 = (tid & 15) << 2, e0 = (tid >> 4) << 2;
    float acc[4][4] = {};
    float esum = 0.f;
    for (int s0 = chunk * 256; s0 < chunk * 256 + 256; s0 += 32) {
        const int s = s0 + lr;
        uint4 kraw = *(const uint4*)(g_kh + base + (size_t)s * Dd + lc);
        uint4 vraw = *(const uint4*)(g_vh + base + (size_t)s * Dd + lc);
        const __half2* kh2 = (const __half2*)&kraw;
        const __half2* vh2 = (const __half2*)&vraw;
        float kvals[8], vvals[8];
        float pd = 0.f;
#pragma unroll
        for (int j = 0; j < 4; j++) {
            float2 kf = __half22float2(kh2[j]);
            float2 vf = __half22float2(vh2[j]);
            kvals[2 * j] = kf.x; kvals[2 * j + 1] = kf.y;
            vvals[2 * j] = vf.x; vvals[2 * j + 1] = vf.y;
            pd += (kf.x + EPSf) * qsiS[lc + 2 * j] + (kf.y + EPSf) * qsiS[lc + 2 * j + 1];
        }
        pd += __shfl_xor_sync(0xffffffffu, pd, 1);
        pd += __shfl_xor_sync(0xffffffffu, pd, 2);
        pd += __shfl_xor_sync(0xffffffffu, pd, 4);
        const float cs = fminf(1.f, fmaxf(-1.f, pd + EPSf));
        const float e = expf(cs * invT);
        if ((tid & 7) == 0) esum += e;
#pragma unroll
        for (int j = 0; j < 8; j++) {
            ks[lr][lc + j] = kvals[j];
            ws[lr][lc + j] = vvals[j] * e;
        }
        __syncthreads();
#pragma unroll
        for (int ss = 0; ss < 32; ss++) {
            float4 kf = *(const float4*)&ks[ss][d0];
            float4 wf = *(const float4*)&ws[ss][e0];
            float krr[4] = {kf.x, kf.y, kf.z, kf.w};
            float wr[4] = {wf.x, wf.y, wf.z, wf.w};
#pragma unroll
            for (int i = 0; i < 4; i++)
#pragma unroll
                for (int j = 0; j < 4; j++)
                    acc[i][j] = fmaf(krr[i], wr[j], acc[i][j]);
        }
        __syncthreads();
    }
    if ((tid & 7) == 0) esred[tid >> 3] = esum;
    __syncthreads();
    if (tid == 0) {
        float t = 0.f;
#pragma unroll
        for (int i = 0; i < 32; i++) t += esred[i];
        g_esum[chunk * BH + bh] = t;
    }
    float* dst = g_kvpart + ((size_t)chunk * BH + bh) * Dd * Dd;
#pragma unroll
    for (int i = 0; i < 4; i++)
#pragma unroll
        for (int j = 0; j < 4; j++)
            dst[(d0 + i) * Dd + e0 + j] = acc[i][j];
}

// ---------------- reduce kv partials, apply softmax scale C/Σe ----------------
__global__ void k_kvred()
{
    const int i = blockIdx.x * blockDim.x + threadIdx.x;
    if (i >= BH * Dd * Dd) return;
    const int bh = i >> 12;
    float es = 0.f;
#pragma unroll
    for (int c = 0; c < MCH; c++) es += g_esum[c * BH + bh];
    const float scale = (float)Cc / es;
    float s = 0.f;
#pragma unroll
    for (int c = 0; c < MCH; c++) s += g_kvpart[(size_t)c * BH * Dd * Dd + i];
    g_kv[i] = s * scale;
}

// ---------------- out_update = (q @ kv) * si * sigmoid(q·(kso+eps)+eps) -> fp16 ----------------
__global__ void __launch_bounds__(256) k_outupd()
{
    const int bh = blockIdx.y, nt = blockIdx.x;
    const int b = bh >> 3, h = bh & 7;
    __shared__ float kvs[64][64];
    __shared__ float qsT[64][68];
    __shared__ float ksoS[64];
    const int tid = threadIdx.x;

    if (tid < 64) {
        float a = 0.f;
#pragma unroll
        for (int c = 0; c < MCH; c++) a += g_kpart2[(c * BH + bh) * Dd + tid];
        ksoS[tid] = a + EPSf;
    }

    const float4* kvsrc = (const float4*)(g_kv + (size_t)bh * (Dd * Dd));
    for (int i = tid; i < 1024; i += 256) ((float4*)kvs)[i] = kvsrc[i];

    const int lr = tid >> 3;
    const int lc = (tid & 7) << 3;
    const __half* qb = g_qh + (size_t)bh * Ntok * Dd + (size_t)(nt * 64) * Dd;
#pragma unroll
    for (int rr = lr; rr < 64; rr += 32) {
        uint4 qraw = *(const uint4*)(qb + rr * Dd + lc);
        const __half2* qh2 = (const __half2*)&qraw;
#pragma unroll
        for (int j = 0; j < 4; j++) {
            float2 qf = __half22float2(qh2[j]);
            qsT[lc + 2 * j][rr]     = qf.x;
            qsT[lc + 2 * j + 1][rr] = qf.y;
        }
    }
    __syncthreads();

    float ksoSum = 0.f;
#pragma unroll
    for (int d = 0; d < 64; d++) ksoSum += ksoS[d];

    const int n0 = (tid & 15) << 2, e0 = (tid >> 4) << 2;
    float acc[4][4] = {};
    float sadot[4] = {};
#pragma unroll
    for (int d = 0; d < 64; d++) {
        float4 qa = *(const float4*)&qsT[d][n0];
        float4 kf = *(const float4*)&kvs[d][e0];
        const float ko = ksoS[d];
        float qr[4] = {qa.x, qa.y, qa.z, qa.w};
        float krr[4] = {kf.x, kf.y, kf.z, kf.w};
#pragma unroll
        for (int i = 0; i < 4; i++) {
            sadot[i] = fmaf(qr[i], ko, sadot[i]);
#pragma unroll
            for (int j = 0; j < 4; j++)
                acc[i][j] = fmaf(qr[i], krr[j], acc[i][j]);
        }
    }

#pragma unroll
    for (int i = 0; i < 4; i++) {
        const int n = nt * 64 + n0 + i;
        const float cs_sink = sadot[i] + EPSf * ksoSum + EPSf;
        const float sa = 1.f / (1.f + expf(-cs_sink));
        const float scale = g_si[bh * Ntok + n] * sa;
        const int np = (h << 9) | (n >> 3);
        const int cbase = (n & 7) << 6;
        const size_t lin = (size_t)(b * Ntok + np) * Cc + cbase + e0;
        __half2 h01 = __floats2half2_rn(acc[i][0] * scale, acc[i][1] * scale);
        __half2 h23 = __floats2half2_rn(acc[i][2] * scale, acc[i][3] * scale);
        *(__half2*)(g_Oh + lin)     = h01;
        *(__half2*)(g_Oh + lin + 2) = h23;
    }
}

// ---------------- launch ----------------
extern "C" void kernel_launch(void* const* d_in, const int* in_sizes, int n_in,
                              void* d_out, int out_size)
{
    const float* query = (const float*)d_in[0];
    const float* Wq = (const float*)d_in[1];
    const float* bq = (const float*)d_in[2];
    const float* Wk = (const float*)d_in[3];
    const float* bk = (const float*)d_in[4];
    const float* Wv = (const float*)d_in[5];
    const float* bv = (const float*)d_in[6];
    const float* Wo = (const float*)d_in[7];
    const float* bo = (const float*)d_in[8];
    const float* temp = (const float*)d_in[9];
    float* out = (float*)d_out;

    const int DSMEM = 3 * 32768 + 1024;
    cudaFuncSetAttribute(gemm_tc, cudaFuncAttributeMaxDynamicSharedMemorySize, DSMEM);

    __half *pAh, *pOh, *pB;
    void* pIcol;
    cudaGetSymbolAddress((void**)&pAh, g_Ah);
    cudaGetSymbolAddress((void**)&pOh, g_Oh);
    cudaGetSymbolAddress((void**)&pB,  g_B);
    cudaGetSymbolAddress(&pIcol, g_icol);

    // zero fixed-point colsum accumulators (graph-capturable async memset)
    cudaMemsetAsync(pIcol, 0, 2 * BH * Dd * sizeof(unsigned long long));

    // merged operand conversion (query split + 4 weight converts)
    k_conv<<<17408, 256>>>(query, pAh, Wq, Wk, Wv, Wo, pB);

    // q/k/v projections in one launch; colsum fused in epilogue
    gemm_tc<<<dim3(4, 256, 3), 256, DSMEM>>>(pAh, pB, bq, bk, bv, nullptr, nullptr, 0);

    k_fuse1<<<dim3(MCH, BH), 256>>>();
    k_kv<<<dim3(MCH, BH), 256>>>(temp);
    k_kvred<<<(BH * Dd * Dd + 255) / 256, 256>>>();
    k_outupd<<<dim3(64, BH), 256>>>();

    // output projection (+bias+residual)
    gemm_tc<<<dim3(4, 256, 1), 256, DSMEM>>>(pOh, pB + 3 * (512 * 512), bo, bo, bo,
                                             query, out, 3);
}

// round 12
// speedup vs baseline: 1.1992x; 1.0130x over previous
#include <cuda_runtime.h>
#include <cuda_fp16.h>
#include <math.h>
#include <stdint.h>

#define Ntok 4096
#define Bb   8
#define Cc   512
#define Hh   8
#define Dd   64
#define BH   64          // B*H
#define EPSf 1e-6f
#define NCHUNK 8         // 512 K / 64 per chunk
#define MCH   16         // mid-section chunks
#define FIXSC 16777216.0f        // 2^24
#define FIXINV (1.0f / 16777216.0f)

// ---------------- scratch (static device arrays; no allocation) ----------------
__device__ __half g_qh[BH * Ntok * Dd];    // (B,H,N,D) sigmoid(q proj) fp16
__device__ __half g_kh[BH * Ntok * Dd];
__device__ __half g_vh[BH * Ntok * Dd];
__device__ float g_si[BH * Ntok];
__device__ unsigned long long g_icol[2][BH * Dd];                   // fixed-point col sums (0:q 1:k)
__device__ float g_kpart2[MCH * BH * Dd], g_qpart2[MCH * BH * Dd];  // weighted col sums
__device__ float g_esum[MCH * BH];                                   // exp-sum partials
__device__ float g_kv[BH * Dd * Dd];
__device__ float g_kvpart[MCH * BH * Dd * Dd];

// fp16 GEMM operands
__device__ __half g_Ah[32768 * 512];       // fp16(query)
__device__ __half g_Oh[32768 * 512];       // fp16(out_update), scrambled (B,N,C)
__device__ __half g_B[4 * 512 * 512];      // [proj][n][k]

// ---------------- PTX helpers (base-arch only) ----------------
__device__ __forceinline__ uint32_t smem_u32(const void* p) {
    uint32_t a;
    asm("{ .reg .u64 t; cvta.to.shared.u64 t, %1; cvt.u32.u64 %0, t; }" : "=r"(a) : "l"(p));
    return a;
}
__device__ __forceinline__ void cp16(uint32_t dst, const void* src) {
    asm volatile("cp.async.cg.shared.global [%0], [%1], 16;" :: "r"(dst), "l"(src) : "memory");
}
__device__ __forceinline__ void cp_commit() {
    asm volatile("cp.async.commit_group;" ::: "memory");
}
__device__ __forceinline__ void cp_wait2() {
    asm volatile("cp.async.wait_group 2;" ::: "memory");
}
__device__ __forceinline__ void ldm4(uint32_t* r, uint32_t addr) {
    asm volatile("ldmatrix.sync.aligned.m8n8.x4.shared.b16 {%0,%1,%2,%3}, [%4];"
                 : "=r"(r[0]), "=r"(r[1]), "=r"(r[2]), "=r"(r[3]) : "r"(addr));
}
__device__ __forceinline__ void mma16816(float* c, const uint32_t* a, const uint32_t* b) {
    asm volatile(
        "mma.sync.aligned.m16n8k16.row.col.f32.f16.f16.f32 "
        "{%0,%1,%2,%3}, {%4,%5,%6,%7}, {%8,%9}, {%0,%1,%2,%3};"
        : "+f"(c[0]), "+f"(c[1]), "+f"(c[2]), "+f"(c[3])
        : "r"(a[0]), "r"(a[1]), "r"(a[2]), "r"(a[3]), "r"(b[0]), "r"(b[1]));
}

// ---------------- merged conversion kernel ----------------
// blocks [0, 16384): fp32->fp16 split of query
// blocks [16384, 17408): weight transpose+convert (4 projections)
__global__ void k_conv(const float* __restrict__ src, __half* __restrict__ dst,
                       const float* __restrict__ Wq, const float* __restrict__ Wk,
                       const float* __restrict__ Wv, const float* __restrict__ Wo,
                       __half* __restrict__ Bop)
{
    if (blockIdx.x < 16384) {
        int i = blockIdx.x * 256 + threadIdx.x;
        float4 v = ((const float4*)src)[i];
        __half2* hp = (__half2*)dst;
        hp[2 * i]     = __floats2half2_rn(v.x, v.y);
        hp[2 * i + 1] = __floats2half2_rn(v.z, v.w);
    } else {
        const int bid = blockIdx.x - 16384;     // 0..1023
        const int z = bid >> 8;                  // projection
        const int rem = bid & 255;
        const int by = rem >> 4, bx = rem & 15;
        const int tx = threadIdx.x & 31, ty = threadIdx.x >> 5;  // (32,8)
        const float* W = (z == 0) ? Wq : (z == 1) ? Wk : (z == 2) ? Wv : Wo;
        __half* Bp = Bop + (size_t)z * (512 * 512);
        __shared__ float t[32][33];
        const int k0 = by * 32, n0 = bx * 32;
        for (int j = ty; j < 32; j += 8) t[j][tx] = W[(size_t)(k0 + j) * 512 + n0 + tx];
        __syncthreads();
        for (int j = ty; j < 32; j += 8)
            Bp[(size_t)(n0 + j) * 512 + (k0 + tx)] = __float2half_rn(t[tx][j]);
    }
}

// ---------------- mma.sync GEMM (f32 acc): D[32768,512] = A[.,512] @ B^T ----------------
// mode 0: q (sigmoid -> g_qh + colsum), 1: k -> g_kh + colsum, 2: v -> g_vh,
// mode 3: out (+bias+resid -> d_out)
__global__ void __launch_bounds__(256) gemm_tc(
    const __half* __restrict__ A, const __half* __restrict__ Bbase,
    const float* __restrict__ b0, const float* __restrict__ b1, const float* __restrict__ b2,
    const float* __restrict__ resid, float* __restrict__ out, int modeBase)
{
    extern __shared__ char dyn[];
    const uint32_t sbase = (smem_u32(dyn) + 1023u) & ~1023u;
    char* dynA = dyn + (sbase - smem_u32(dyn));
    const int tid = threadIdx.x;
    const int wid = tid >> 5, lane = tid & 31;
    const int bn = blockIdx.x * 128, bm = blockIdx.y * 128;
    const int mode = modeBase + blockIdx.z;
    const __half* Bop = Bbase + (size_t)blockIdx.z * (512 * 512);
    const float* bias = (mode == 1) ? b1 : (mode == 2) ? b2 : b0;
    const int warpM = wid & 3, warpN = wid >> 2;   // 4 x 2 warps -> 32x64 warp tile

    float acc[2][8][4];
#pragma unroll
    for (int mf = 0; mf < 2; mf++)
#pragma unroll
        for (int nf = 0; nf < 8; nf++)
#pragma unroll
            for (int i = 0; i < 4; i++) acc[mf][nf][i] = 0.f;

    int aRow[2], bRow[4];
#pragma unroll
    for (int mf = 0; mf < 2; mf++)
        aRow[mf] = warpM * 32 + mf * 16 + (lane & 7) + ((lane >> 3) & 1) * 8;
    const int aHi = lane >> 4;
#pragma unroll
    for (int nf2 = 0; nf2 < 4; nf2++)
        bRow[nf2] = warpN * 64 + nf2 * 16 + (lane & 7) + (lane >> 4) * 8;
    const int bHi = (lane >> 3) & 1;

    auto issue = [&](int c) {
        const int akoff = c << 6;
        const uint32_t buf = sbase + (uint32_t)(c % 3) * 32768u;
#pragma unroll
        for (int t = 0; t < 4; t++) {
            int s = tid + (t << 8);
            int row = s >> 3, sc = s & 7;
            uint32_t off = row * 128 + ((sc ^ (row & 7)) << 4);
            cp16(buf + off, A + ((size_t)(bm + row) * 512 + akoff + sc * 8));
        }
#pragma unroll
        for (int t = 0; t < 4; t++) {
            int s = tid + (t << 8);
            int row = s >> 3, sc = s & 7;
            uint32_t off = row * 128 + ((sc ^ (row & 7)) << 4);
            cp16(buf + 16384u + off, Bop + ((size_t)(bn + row) * 512 + akoff + sc * 8));
        }
    };

    issue(0); cp_commit();
    issue(1); cp_commit();

    for (int c = 0; c < NCHUNK; c++) {
        if (c + 2 < NCHUNK) issue(c + 2);
        cp_commit();
        cp_wait2();
        __syncthreads();

        const uint32_t abuf = sbase + (uint32_t)(c % 3) * 32768u;
        const uint32_t bbuf = abuf + 16384u;
#pragma unroll
        for (int ks = 0; ks < 4; ks++) {
            uint32_t a[2][4], b[4][4];
#pragma unroll
            for (int mf = 0; mf < 2; mf++) {
                const int row = aRow[mf];
                const int cc = 2 * ks + aHi;
                ldm4(a[mf], abuf + row * 128 + ((cc ^ (row & 7)) << 4));
            }
#pragma unroll
            for (int nf2 = 0; nf2 < 4; nf2++) {
                const int row = bRow[nf2];
                const int cc = 2 * ks + bHi;
                ldm4(b[nf2], bbuf + row * 128 + ((cc ^ (row & 7)) << 4));
            }
#pragma unroll
            for (int mf = 0; mf < 2; mf++)
#pragma unroll
                for (int nf = 0; nf < 8; nf++)
                    mma16816(acc[mf][nf], a[mf], &b[nf >> 1][(nf & 1) * 2]);
        }
        __syncthreads();
    }

    // ---------------- epilogue ----------------
    if (mode <= 2) {
        __half* smh = (__half*)dynA;
        const int rloc = warpM * 32 + (lane >> 2);
        const int cloc = warpN * 64 + ((lane & 3) << 1);
#pragma unroll
        for (int mf = 0; mf < 2; mf++)
#pragma unroll
            for (int half = 0; half < 2; half++) {
#pragma unroll
                for (int nf = 0; nf < 8; nf++) {
                    const int c0 = bn + cloc + nf * 8;
                    float vx = acc[mf][nf][half * 2 + 0] + bias[c0];
                    float vy = acc[mf][nf][half * 2 + 1] + bias[c0 + 1];
                    if (mode <= 1) {
                        vx = 1.f / (1.f + expf(-vx));
                        vy = 1.f / (1.f + expf(-vy));
                    }
                    *(__half2*)&smh[(rloc + mf * 16 + half * 8) * 136 + cloc + nf * 8]
                        = __floats2half2_rn(vx, vy);
                }
            }
        __syncthreads();
        __half* dstg = (mode == 0) ? g_qh : (mode == 1) ? g_kh : g_vh;
        const int h0 = bn >> 6;
        const int hl = tid >> 7, nl = (tid & 127) >> 3, dp = tid & 7;
#pragma unroll
        for (int bb2 = 0; bb2 < 8; bb2++) {
            uint4 val = *(const uint4*)(smh + (size_t)(nl * 8 + bb2) * 136 + hl * 64 + dp * 8);
            *(uint4*)(dstg + ((size_t)((bb2 << 3) | (h0 + hl)) * Ntok + (bm >> 3) + nl) * Dd + dp * 8) = val;
        }
        // fused column sums (q/k): deterministic fixed-point atomics over the staged tile
        if (mode <= 1) {
            const int hl2 = tid >> 7;            // head within tile (0..1)
            const int b2 = (tid >> 4) & 7;       // batch
            const int d0 = (tid & 15) << 2;      // 4 d's
            float s0 = 0.f, s1 = 0.f, s2 = 0.f, s3 = 0.f;
#pragma unroll
            for (int n = 0; n < 16; n++) {
                const __half* rowp = smh + (size_t)(n * 8 + b2) * 136 + hl2 * 64 + d0;
                float2 p0 = __half22float2(*(const __half2*)rowp);
                float2 p1 = __half22float2(*(const __half2*)(rowp + 2));
                s0 += p0.x; s1 += p0.y; s2 += p1.x; s3 += p1.y;
            }
            const int bh = (b2 << 3) | ((bn >> 6) + hl2);
            unsigned long long* dst = &g_icol[mode][bh * Dd + d0];
            atomicAdd(dst + 0, (unsigned long long)(long long)llrintf(s0 * FIXSC));
            atomicAdd(dst + 1, (unsigned long long)(long long)llrintf(s1 * FIXSC));
            atomicAdd(dst + 2, (unsigned long long)(long long)llrintf(s2 * FIXSC));
            atomicAdd(dst + 3, (unsigned long long)(long long)llrintf(s3 * FIXSC));
        }
    } else {
        const int r0base = bm + warpM * 32 + (lane >> 2);
        const int cb = bn + warpN * 64 + ((lane & 3) << 1);
#pragma unroll
        for (int mf = 0; mf < 2; mf++)
#pragma unroll
            for (int half = 0; half < 2; half++) {
                const int r = r0base + mf * 16 + half * 8;
#pragma unroll
                for (int nf = 0; nf < 8; nf++) {
                    const int c0 = cb + nf * 8;
                    const int bb = r >> 12, n = r & 4095;
                    const size_t o = (size_t)((n << 3) | bb) * Cc + c0;
                    float2 rs = *(const float2*)(resid + o);
                    float2 v;
                    v.x = acc[mf][nf][half * 2 + 0] + bias[c0] + rs.x;
                    v.y = acc[mf][nf][half * 2 + 1] + bias[c0 + 1] + rs.y;
                    *(float2*)(out + o) = v;
                }
            }
    }
}

// ---------------- fused: rownorm (si/so) + weighted colsum partials ----------------
// SHUFFLE-FREE: phase 1 = thread-per-row private dots; phase 2 = coalesced weighted colsums.
__global__ void __launch_bounds__(256) k_fuse1()
{
    const int bh = blockIdx.y, chunk = blockIdx.x;
    const int tid = threadIdx.x;
    __shared__ float ksS[64], qsS[64];
    __shared__ float siS[256], soS[256];
    __shared__ float sQ[8][64], sK[8][64];
    if (tid < 64) {
        ksS[tid] = (float)(long long)g_icol[1][bh * Dd + tid] * FIXINV + EPSf;
        qsS[tid] = (float)(long long)g_icol[0][bh * Dd + tid] * FIXINV + EPSf;
    }
    __syncthreads();
    const __half* qb = g_qh + (size_t)bh * Ntok * Dd;
    const __half* kb = g_kh + (size_t)bh * Ntok * Dd;

    // phase 1: one thread per s-row, private dot over d (no shuffles)
    {
        const int s = chunk * 256 + tid;
        const uint4* qrow = (const uint4*)(qb + (size_t)s * Dd);
        const uint4* krow = (const uint4*)(kb + (size_t)s * Dd);
        float s1 = 0.f, s2 = 0.f;
#pragma unroll
        for (int j = 0; j < 8; j++) {
            uint4 qraw = qrow[j];
            uint4 kraw = krow[j];
            const __half2* qh2 = (const __half2*)&qraw;
            const __half2* kh2 = (const __half2*)&kraw;
#pragma unroll
            for (int u = 0; u < 4; u++) {
                float2 qf = __half22float2(qh2[u]);
                float2 kf = __half22float2(kh2[u]);
                const int d = j * 8 + 2 * u;
                s1 += (qf.x + EPSf) * ksS[d] + (qf.y + EPSf) * ksS[d + 1];
                s2 += (kf.x + EPSf) * qsS[d] + (kf.y + EPSf) * qsS[d + 1];
            }
        }
        const float si = 1.f / (s1 + EPSf);
        const float so = 1.f / (s2 + EPSf);
        g_si[bh * Ntok + s] = si;
        siS[tid] = si; soS[tid] = so;
    }
    __syncthreads();

    // phase 2: weighted colsums, coalesced (rows L1-hot from phase 1)
    const int p = tid >> 5, dp = tid & 31;
    float aq0 = 0.f, aq1 = 0.f, ak0 = 0.f, ak1 = 0.f;
#pragma unroll 4
    for (int i = 0; i < 32; i++) {
        const int sl = p + 8 * i;
        const int s = chunk * 256 + sl;
        float2 qf = __half22float2(*(const __half2*)(qb + (size_t)s * Dd + 2 * dp));
        float2 kf = __half22float2(*(const __half2*)(kb + (size_t)s * Dd + 2 * dp));
        const float si = siS[sl], so = soS[sl];
        aq0 += si * qf.x; aq1 += si * qf.y;
        ak0 += so * kf.x; ak1 += so * kf.y;
    }
    sQ[p][2 * dp] = aq0; sQ[p][2 * dp + 1] = aq1;
    sK[p][2 * dp] = ak0; sK[p][2 * dp + 1] = ak1;
    __syncthreads();
    if (tid < 64) {
        float sq = 0.f, sk = 0.f;
#pragma unroll
        for (int w2 = 0; w2 < 8; w2++) { sq += sQ[w2][tid]; sk += sK[w2][tid]; }
        g_qpart2[(chunk * BH + bh) * Dd + tid] = sq;   // si-weighted q sums -> qsi
        g_kpart2[(chunk * BH + bh) * Dd + tid] = sk;   // so-weighted k sums -> kso
    }
}

// ---------------- fused: conserved_source (inline) + exp + kv partials + exp-sum ----------------
// fp16 smem tiles: halves the smem bandwidth of the FMA inner loop.
__global__ void __launch_bounds__(256) k_kv(const float* __restrict__ tptr)
{
    const int bh = blockIdx.y, chunk = blockIdx.x;
    __shared__ __half ksh[32][64];
    __shared__ __half wsh[32][64];
    __shared__ float qsiS[64];
    __shared__ float esred[32];
    const int tid = threadIdx.x;
    const int lr = tid >> 3;
    const int lc = (tid & 7) << 3;
    if (tid < 64) {
        float a = 0.f;
#pragma unroll
        for (int c = 0; c < MCH; c++) a += g_qpart2[(c * BH + bh) * Dd + tid];
        qsiS[tid] = a + EPSf;
    }
    __syncthreads();
    const float invT = 1.f / tptr[0];
    const size_t base = (size_t)bh * Ntok * Dd;
    const int d0 = (tid & 15) << 2, e0 = (tid >> 4) << 2;
    float acc[4][4] = {};
    float esum = 0.f;
    for (int s0 = chunk * 256; s0 < chunk * 256 + 256; s0 += 32) {
        const int s = s0 + lr;
        uint4 kraw = *(const uint4*)(g_kh + base + (size_t)s * Dd + lc);
        uint4 vraw = *(const uint4*)(g_vh + base + (size_t)s * Dd + lc);
        const __half2* kh2 = (const __half2*)&kraw;
        const __half2* vh2 = (const __half2*)&vraw;
        float pd = 0.f;
#pragma unroll
        for (int j = 0; j < 4; j++) {
            float2 kf = __half22float2(kh2[j]);
            pd += (kf.x + EPSf) * qsiS[lc + 2 * j] + (kf.y + EPSf) * qsiS[lc + 2 * j + 1];
        }
        pd += __shfl_xor_sync(0xffffffffu, pd, 1);
        pd += __shfl_xor_sync(0xffffffffu, pd, 2);
        pd += __shfl_xor_sync(0xffffffffu, pd, 4);
        const float cs = fminf(1.f, fmaxf(-1.f, pd + EPSf));
        const float e = expf(cs * invT);
        if ((tid & 7) == 0) esum += e;
        // store raw fp16 k tile; weighted-v tile in fp16 (hmul by e)
        *(uint4*)&ksh[lr][lc] = kraw;
        const __half2 e2 = __float2half2_rn(e);
        uint4 wout;
        ((__half2*)&wout)[0] = __hmul2(vh2[0], e2);
        ((__half2*)&wout)[1] = __hmul2(vh2[1], e2);
        ((__half2*)&wout)[2] = __hmul2(vh2[2], e2);
        ((__half2*)&wout)[3] = __hmul2(vh2[3], e2);
        *(uint4*)&wsh[lr][lc] = wout;
        __syncthreads();
#pragma unroll
        for (int ss = 0; ss < 32; ss++) {
            uint2 kk = *(const uint2*)&ksh[ss][d0];
            uint2 ww = *(const uint2*)&wsh[ss][e0];
            float2 k01 = __half22float2(*(const __half2*)&kk.x);
            float2 k23 = __half22float2(*(const __half2*)&kk.y);
            float2 w01 = __half22float2(*(const __half2*)&ww.x);
            float2 w23 = __half22float2(*(const __half2*)&ww.y);
            float krr[4] = {k01.x, k01.y, k23.x, k23.y};
            float wr[4]  = {w01.x, w01.y, w23.x, w23.y};
#pragma unroll
            for (int i = 0; i < 4; i++)
#pragma unroll
                for (int j = 0; j < 4; j++)
                    acc[i][j] = fmaf(krr[i], wr[j], acc[i][j]);
        }
        __syncthreads();
    }
    if ((tid & 7) == 0) esred[tid >> 3] = esum;
    __syncthreads();
    if (tid == 0) {
        float t = 0.f;
#pragma unroll
        for (int i = 0; i < 32; i++) t += esred[i];
        g_esum[chunk * BH + bh] = t;
    }
    float* dst = g_kvpart + ((size_t)chunk * BH + bh) * Dd * Dd;
#pragma unroll
    for (int i = 0; i < 4; i++)
#pragma unroll
        for (int j = 0; j < 4; j++)
            dst[(d0 + i) * Dd + e0 + j] = acc[i][j];
}

// ---------------- reduce kv partials, apply softmax scale C/Σe ----------------
__global__ void k_kvred()
{
    const int i = blockIdx.x * blockDim.x + threadIdx.x;
    if (i >= BH * Dd * Dd) return;
    const int bh = i >> 12;
    float es = 0.f;
#pragma unroll
    for (int c = 0; c < MCH; c++) es += g_esum[c * BH + bh];
    const float scale = (float)Cc / es;
    float s = 0.f;
#pragma unroll
    for (int c = 0; c < MCH; c++) s += g_kvpart[(size_t)c * BH * Dd * Dd + i];
    g_kv[i] = s * scale;
}

// ---------------- out_update = (q @ kv) * si * sigmoid(q·(kso+eps)+eps) -> fp16 ----------------
__global__ void __launch_bounds__(256) k_outupd()
{
    const int bh = blockIdx.y, nt = blockIdx.x;
    const int b = bh >> 3, h = bh & 7;
    __shared__ float kvs[64][64];
    __shared__ float qsT[64][68];
    __shared__ float ksoS[64];
    const int tid = threadIdx.x;

    if (tid < 64) {
        float a = 0.f;
#pragma unroll
        for (int c = 0; c < MCH; c++) a += g_kpart2[(c * BH + bh) * Dd + tid];
        ksoS[tid] = a + EPSf;
    }

    const float4* kvsrc = (const float4*)(g_kv + (size_t)bh * (Dd * Dd));
    for (int i = tid; i < 1024; i += 256) ((float4*)kvs)[i] = kvsrc[i];

    const int lr = tid >> 3;
    const int lc = (tid & 7) << 3;
    const __half* qb = g_qh + (size_t)bh * Ntok * Dd + (size_t)(nt * 64) * Dd;
#pragma unroll
    for (int rr = lr; rr < 64; rr += 32) {
        uint4 qraw = *(const uint4*)(qb + rr * Dd + lc);
        const __half2* qh2 = (const __half2*)&qraw;
#pragma unroll
        for (int j = 0; j < 4; j++) {
            float2 qf = __half22float2(qh2[j]);
            qsT[lc + 2 * j][rr]     = qf.x;
            qsT[lc + 2 * j + 1][rr] = qf.y;
        }
    }
    __syncthreads();

    float ksoSum = 0.f;
#pragma unroll
    for (int d = 0; d < 64; d++) ksoSum += ksoS[d];

    const int n0 = (tid & 15) << 2, e0 = (tid >> 4) << 2;
    float acc[4][4] = {};
    float sadot[4] = {};
#pragma unroll
    for (int d = 0; d < 64; d++) {
        float4 qa = *(const float4*)&qsT[d][n0];
        float4 kf = *(const float4*)&kvs[d][e0];
        const float ko = ksoS[d];
        float qr[4] = {qa.x, qa.y, qa.z, qa.w};
        float krr[4] = {kf.x, kf.y, kf.z, kf.w};
#pragma unroll
        for (int i = 0; i < 4; i++) {
            sadot[i] = fmaf(qr[i], ko, sadot[i]);
#pragma unroll
            for (int j = 0; j < 4; j++)
                acc[i][j] = fmaf(qr[i], krr[j], acc[i][j]);
        }
    }

#pragma unroll
    for (int i = 0; i < 4; i++) {
        const int n = nt * 64 + n0 + i;
        const float cs_sink = sadot[i] + EPSf * ksoSum + EPSf;
        const float sa = 1.f / (1.f + expf(-cs_sink));
        const float scale = g_si[bh * Ntok + n] * sa;
        const int np = (h << 9) | (n >> 3);
        const int cbase = (n & 7) << 6;
        const size_t lin = (size_t)(b * Ntok + np) * Cc + cbase + e0;
        __half2 h01 = __floats2half2_rn(acc[i][0] * scale, acc[i][1] * scale);
        __half2 h23 = __floats2half2_rn(acc[i][2] * scale, acc[i][3] * scale);
        *(__half2*)(g_Oh + lin)     = h01;
        *(__half2*)(g_Oh + lin + 2) = h23;
    }
}

// ---------------- launch ----------------
extern "C" void kernel_launch(void* const* d_in, const int* in_sizes, int n_in,
                              void* d_out, int out_size)
{
    const float* query = (const float*)d_in[0];
    const float* Wq = (const float*)d_in[1];
    const float* bq = (const float*)d_in[2];
    const float* Wk = (const float*)d_in[3];
    const float* bk = (const float*)d_in[4];
    const float* Wv = (const float*)d_in[5];
    const float* bv = (const float*)d_in[6];
    const float* Wo = (const float*)d_in[7];
    const float* bo = (const float*)d_in[8];
    const float* temp = (const float*)d_in[9];
    float* out = (float*)d_out;

    const int DSMEM = 3 * 32768 + 1024;
    cudaFuncSetAttribute(gemm_tc, cudaFuncAttributeMaxDynamicSharedMemorySize, DSMEM);

    __half *pAh, *pOh, *pB;
    void* pIcol;
    cudaGetSymbolAddress((void**)&pAh, g_Ah);
    cudaGetSymbolAddress((void**)&pOh, g_Oh);
    cudaGetSymbolAddress((void**)&pB,  g_B);
    cudaGetSymbolAddress(&pIcol, g_icol);

    // zero fixed-point colsum accumulators (graph-capturable async memset)
    cudaMemsetAsync(pIcol, 0, 2 * BH * Dd * sizeof(unsigned long long));

    // merged operand conversion (query split + 4 weight converts)
    k_conv<<<17408, 256>>>(query, pAh, Wq, Wk, Wv, Wo, pB);

    // q/k/v projections in one launch; colsum fused in epilogue
    gemm_tc<<<dim3(4, 256, 3), 256, DSMEM>>>(pAh, pB, bq, bk, bv, nullptr, nullptr, 0);

    k_fuse1<<<dim3(MCH, BH), 256>>>();
    k_kv<<<dim3(MCH, BH), 256>>>(temp);
    k_kvred<<<(BH * Dd * Dd + 255) / 256, 256>>>();
    k_outupd<<<dim3(64, BH), 256>>>();

    // output projection (+bias+residual)
    gemm_tc<<<dim3(4, 256, 1), 256, DSMEM>>>(pOh, pB + 3 * (512 * 512), bo, bo, bo,
                                             query, out, 3);
}

// round 13
// speedup vs baseline: 1.3900x; 1.1591x over previous
#include <cuda_runtime.h>
#include <cuda_fp16.h>
#include <math.h>
#include <stdint.h>

#define Ntok 4096
#define Bb   8
#define Cc   512
#define Hh   8
#define Dd   64
#define BH   64          // B*H
#define EPSf 1e-6f
#define NCHUNK 8         // 512 K / 64 per chunk
#define MCH   16         // mid-section chunks
#define FIXSC 16777216.0f        // 2^24
#define FIXINV (1.0f / 16777216.0f)

// ---------------- scratch (static device arrays; no allocation) ----------------
__device__ __half g_qh[BH * Ntok * Dd];    // (B,H,N,D) sigmoid(q proj) fp16
__device__ __half g_kh[BH * Ntok * Dd];
__device__ __half g_vh[BH * Ntok * Dd];
__device__ float g_si[BH * Ntok];
__device__ unsigned long long g_icol[2][BH * Dd];                   // fixed-point col sums (0:q 1:k)
__device__ float g_kpart2[MCH * BH * Dd], g_qpart2[MCH * BH * Dd];  // weighted col sums
__device__ float g_esum[MCH * BH];                                   // exp-sum partials
__device__ float g_kv[BH * Dd * Dd];
__device__ float g_kvpart[MCH * BH * Dd * Dd];

// fp16 GEMM operands
__device__ __half g_Ah[32768 * 512];       // fp16(query)
__device__ __half g_Oh[32768 * 512];       // fp16(out_update), scrambled (B,N,C)
__device__ __half g_B[4 * 512 * 512];      // [proj][n][k]

// ---------------- PTX helpers (base-arch only) ----------------
__device__ __forceinline__ uint32_t smem_u32(const void* p) {
    uint32_t a;
    asm("{ .reg .u64 t; cvta.to.shared.u64 t, %1; cvt.u32.u64 %0, t; }" : "=r"(a) : "l"(p));
    return a;
}
__device__ __forceinline__ void cp16(uint32_t dst, const void* src) {
    asm volatile("cp.async.cg.shared.global [%0], [%1], 16;" :: "r"(dst), "l"(src) : "memory");
}
__device__ __forceinline__ void cp_commit() {
    asm volatile("cp.async.commit_group;" ::: "memory");
}
__device__ __forceinline__ void cp_wait2() {
    asm volatile("cp.async.wait_group 2;" ::: "memory");
}
__device__ __forceinline__ void ldm4(uint32_t* r, uint32_t addr) {
    asm volatile("ldmatrix.sync.aligned.m8n8.x4.shared.b16 {%0,%1,%2,%3}, [%4];"
                 : "=r"(r[0]), "=r"(r[1]), "=r"(r[2]), "=r"(r[3]) : "r"(addr));
}
__device__ __forceinline__ void ldm4t(uint32_t* r, uint32_t addr) {
    asm volatile("ldmatrix.sync.aligned.m8n8.x4.trans.shared.b16 {%0,%1,%2,%3}, [%4];"
                 : "=r"(r[0]), "=r"(r[1]), "=r"(r[2]), "=r"(r[3]) : "r"(addr));
}
__device__ __forceinline__ void mma16816(float* c, const uint32_t* a, const uint32_t* b) {
    asm volatile(
        "mma.sync.aligned.m16n8k16.row.col.f32.f16.f16.f32 "
        "{%0,%1,%2,%3}, {%4,%5,%6,%7}, {%8,%9}, {%0,%1,%2,%3};"
        : "+f"(c[0]), "+f"(c[1]), "+f"(c[2]), "+f"(c[3])
        : "r"(a[0]), "r"(a[1]), "r"(a[2]), "r"(a[3]), "r"(b[0]), "r"(b[1]));
}

// ---------------- merged conversion kernel ----------------
__global__ void k_conv(const float* __restrict__ src, __half* __restrict__ dst,
                       const float* __restrict__ Wq, const float* __restrict__ Wk,
                       const float* __restrict__ Wv, const float* __restrict__ Wo,
                       __half* __restrict__ Bop)
{
    if (blockIdx.x < 16384) {
        int i = blockIdx.x * 256 + threadIdx.x;
        float4 v = ((const float4*)src)[i];
        __half2* hp = (__half2*)dst;
        hp[2 * i]     = __floats2half2_rn(v.x, v.y);
        hp[2 * i + 1] = __floats2half2_rn(v.z, v.w);
    } else {
        const int bid = blockIdx.x - 16384;     // 0..1023
        const int z = bid >> 8;                  // projection
        const int rem = bid & 255;
        const int by = rem >> 4, bx = rem & 15;
        const int tx = threadIdx.x & 31, ty = threadIdx.x >> 5;  // (32,8)
        const float* W = (z == 0) ? Wq : (z == 1) ? Wk : (z == 2) ? Wv : Wo;
        __half* Bp = Bop + (size_t)z * (512 * 512);
        __shared__ float t[32][33];
        const int k0 = by * 32, n0 = bx * 32;
        for (int j = ty; j < 32; j += 8) t[j][tx] = W[(size_t)(k0 + j) * 512 + n0 + tx];
        __syncthreads();
        for (int j = ty; j < 32; j += 8)
            Bp[(size_t)(n0 + j) * 512 + (k0 + tx)] = __float2half_rn(t[tx][j]);
    }
}

// ---------------- mma.sync GEMM (f32 acc): D[32768,512] = A[.,512] @ B^T ----------------
// mode 0: q (sigmoid -> g_qh + colsum), 1: k -> g_kh + colsum, 2: v -> g_vh,
// mode 3: out (+bias+resid -> d_out)
__global__ void __launch_bounds__(256) gemm_tc(
    const __half* __restrict__ A, const __half* __restrict__ Bbase,
    const float* __restrict__ b0, const float* __restrict__ b1, const float* __restrict__ b2,
    const float* __restrict__ resid, float* __restrict__ out, int modeBase)
{
    extern __shared__ char dyn[];
    const uint32_t sbase = (smem_u32(dyn) + 1023u) & ~1023u;
    char* dynA = dyn + (sbase - smem_u32(dyn));
    const int tid = threadIdx.x;
    const int wid = tid >> 5, lane = tid & 31;
    const int bn = blockIdx.x * 128, bm = blockIdx.y * 128;
    const int mode = modeBase + blockIdx.z;
    const __half* Bop = Bbase + (size_t)blockIdx.z * (512 * 512);
    const float* bias = (mode == 1) ? b1 : (mode == 2) ? b2 : b0;
    const int warpM = wid & 3, warpN = wid >> 2;   // 4 x 2 warps -> 32x64 warp tile

    float acc[2][8][4];
#pragma unroll
    for (int mf = 0; mf < 2; mf++)
#pragma unroll
        for (int nf = 0; nf < 8; nf++)
#pragma unroll
            for (int i = 0; i < 4; i++) acc[mf][nf][i] = 0.f;

    int aRow[2], bRow[4];
#pragma unroll
    for (int mf = 0; mf < 2; mf++)
        aRow[mf] = warpM * 32 + mf * 16 + (lane & 7) + ((lane >> 3) & 1) * 8;
    const int aHi = lane >> 4;
#pragma unroll
    for (int nf2 = 0; nf2 < 4; nf2++)
        bRow[nf2] = warpN * 64 + nf2 * 16 + (lane & 7) + (lane >> 4) * 8;
    const int bHi = (lane >> 3) & 1;

    auto issue = [&](int c) {
        const int akoff = c << 6;
        const uint32_t buf = sbase + (uint32_t)(c % 3) * 32768u;
#pragma unroll
        for (int t = 0; t < 4; t++) {
            int s = tid + (t << 8);
            int row = s >> 3, sc = s & 7;
            uint32_t off = row * 128 + ((sc ^ (row & 7)) << 4);
            cp16(buf + off, A + ((size_t)(bm + row) * 512 + akoff + sc * 8));
        }
#pragma unroll
        for (int t = 0; t < 4; t++) {
            int s = tid + (t << 8);
            int row = s >> 3, sc = s & 7;
            uint32_t off = row * 128 + ((sc ^ (row & 7)) << 4);
            cp16(buf + 16384u + off, Bop + ((size_t)(bn + row) * 512 + akoff + sc * 8));
        }
    };

    issue(0); cp_commit();
    issue(1); cp_commit();

    for (int c = 0; c < NCHUNK; c++) {
        if (c + 2 < NCHUNK) issue(c + 2);
        cp_commit();
        cp_wait2();
        __syncthreads();

        const uint32_t abuf = sbase + (uint32_t)(c % 3) * 32768u;
        const uint32_t bbuf = abuf + 16384u;
#pragma unroll
        for (int ks = 0; ks < 4; ks++) {
            uint32_t a[2][4], b[4][4];
#pragma unroll
            for (int mf = 0; mf < 2; mf++) {
                const int row = aRow[mf];
                const int cc = 2 * ks + aHi;
                ldm4(a[mf], abuf + row * 128 + ((cc ^ (row & 7)) << 4));
            }
#pragma unroll
            for (int nf2 = 0; nf2 < 4; nf2++) {
                const int row = bRow[nf2];
                const int cc = 2 * ks + bHi;
                ldm4(b[nf2], bbuf + row * 128 + ((cc ^ (row & 7)) << 4));
            }
#pragma unroll
            for (int mf = 0; mf < 2; mf++)
#pragma unroll
                for (int nf = 0; nf < 8; nf++)
                    mma16816(acc[mf][nf], a[mf], &b[nf >> 1][(nf & 1) * 2]);
        }
        __syncthreads();
    }

    // ---------------- epilogue ----------------
    if (mode <= 2) {
        __half* smh = (__half*)dynA;
        const int rloc = warpM * 32 + (lane >> 2);
        const int cloc = warpN * 64 + ((lane & 3) << 1);
#pragma unroll
        for (int mf = 0; mf < 2; mf++)
#pragma unroll
            for (int half = 0; half < 2; half++) {
#pragma unroll
                for (int nf = 0; nf < 8; nf++) {
                    const int c0 = bn + cloc + nf * 8;
                    float vx = acc[mf][nf][half * 2 + 0] + bias[c0];
                    float vy = acc[mf][nf][half * 2 + 1] + bias[c0 + 1];
                    if (mode <= 1) {
                        vx = 1.f / (1.f + expf(-vx));
                        vy = 1.f / (1.f + expf(-vy));
                    }
                    *(__half2*)&smh[(rloc + mf * 16 + half * 8) * 136 + cloc + nf * 8]
                        = __floats2half2_rn(vx, vy);
                }
            }
        __syncthreads();
        __half* dstg = (mode == 0) ? g_qh : (mode == 1) ? g_kh : g_vh;
        const int h0 = bn >> 6;
        const int hl = tid >> 7, nl = (tid & 127) >> 3, dp = tid & 7;
#pragma unroll
        for (int bb2 = 0; bb2 < 8; bb2++) {
            uint4 val = *(const uint4*)(smh + (size_t)(nl * 8 + bb2) * 136 + hl * 64 + dp * 8);
            *(uint4*)(dstg + ((size_t)((bb2 << 3) | (h0 + hl)) * Ntok + (bm >> 3) + nl) * Dd + dp * 8) = val;
        }
        // fused column sums (q/k): deterministic fixed-point atomics over the staged tile
        if (mode <= 1) {
            const int hl2 = tid >> 7;            // head within tile (0..1)
            const int b2 = (tid >> 4) & 7;       // batch
            const int d0 = (tid & 15) << 2;      // 4 d's
            float s0 = 0.f, s1 = 0.f, s2 = 0.f, s3 = 0.f;
#pragma unroll
            for (int n = 0; n < 16; n++) {
                const __half* rowp = smh + (size_t)(n * 8 + b2) * 136 + hl2 * 64 + d0;
                float2 p0 = __half22float2(*(const __half2*)rowp);
                float2 p1 = __half22float2(*(const __half2*)(rowp + 2));
                s0 += p0.x; s1 += p0.y; s2 += p1.x; s3 += p1.y;
            }
            const int bh = (b2 << 3) | ((bn >> 6) + hl2);
            unsigned long long* dst = &g_icol[mode][bh * Dd + d0];
            atomicAdd(dst + 0, (unsigned long long)(long long)llrintf(s0 * FIXSC));
            atomicAdd(dst + 1, (unsigned long long)(long long)llrintf(s1 * FIXSC));
            atomicAdd(dst + 2, (unsigned long long)(long long)llrintf(s2 * FIXSC));
            atomicAdd(dst + 3, (unsigned long long)(long long)llrintf(s3 * FIXSC));
        }
    } else {
        const int r0base = bm + warpM * 32 + (lane >> 2);
        const int cb = bn + warpN * 64 + ((lane & 3) << 1);
#pragma unroll
        for (int mf = 0; mf < 2; mf++)
#pragma unroll
            for (int half = 0; half < 2; half++) {
                const int r = r0base + mf * 16 + half * 8;
#pragma unroll
                for (int nf = 0; nf < 8; nf++) {
                    const int c0 = cb + nf * 8;
                    const int bb = r >> 12, n = r & 4095;
                    const size_t o = (size_t)((n << 3) | bb) * Cc + c0;
                    float2 rs = *(const float2*)(resid + o);
                    float2 v;
                    v.x = acc[mf][nf][half * 2 + 0] + bias[c0] + rs.x;
                    v.y = acc[mf][nf][half * 2 + 1] + bias[c0 + 1] + rs.y;
                    *(float2*)(out + o) = v;
                }
            }
    }
}

// ---------------- fused: rownorm (si/so) + weighted colsum partials ----------------
__global__ void __launch_bounds__(256) k_fuse1()
{
    const int bh = blockIdx.y, chunk = blockIdx.x;
    const int tid = threadIdx.x;
    __shared__ float ksS[64], qsS[64];
    __shared__ float siS[256], soS[256];
    __shared__ float sQ[8][64], sK[8][64];
    if (tid < 64) {
        ksS[tid] = (float)(long long)g_icol[1][bh * Dd + tid] * FIXINV + EPSf;
        qsS[tid] = (float)(long long)g_icol[0][bh * Dd + tid] * FIXINV + EPSf;
    }
    __syncthreads();
    const __half* qb = g_qh + (size_t)bh * Ntok * Dd;
    const __half* kb = g_kh + (size_t)bh * Ntok * Dd;

    // phase 1: one thread per s-row, private dot over d (no shuffles)
    {
        const int s = chunk * 256 + tid;
        const uint4* qrow = (const uint4*)(qb + (size_t)s * Dd);
        const uint4* krow = (const uint4*)(kb + (size_t)s * Dd);
        float s1 = 0.f, s2 = 0.f;
#pragma unroll
        for (int j = 0; j < 8; j++) {
            uint4 qraw = qrow[j];
            uint4 kraw = krow[j];
            const __half2* qh2 = (const __half2*)&qraw;
            const __half2* kh2 = (const __half2*)&kraw;
#pragma unroll
            for (int u = 0; u < 4; u++) {
                float2 qf = __half22float2(qh2[u]);
                float2 kf = __half22float2(kh2[u]);
                const int d = j * 8 + 2 * u;
                s1 += (qf.x + EPSf) * ksS[d] + (qf.y + EPSf) * ksS[d + 1];
                s2 += (kf.x + EPSf) * qsS[d] + (kf.y + EPSf) * qsS[d + 1];
            }
        }
        const float si = 1.f / (s1 + EPSf);
        const float so = 1.f / (s2 + EPSf);
        g_si[bh * Ntok + s] = si;
        siS[tid] = si; soS[tid] = so;
    }
    __syncthreads();

    // phase 2: weighted colsums, coalesced (rows L1-hot from phase 1)
    const int p = tid >> 5, dp = tid & 31;
    float aq0 = 0.f, aq1 = 0.f, ak0 = 0.f, ak1 = 0.f;
#pragma unroll 4
    for (int i = 0; i < 32; i++) {
        const int sl = p + 8 * i;
        const int s = chunk * 256 + sl;
        float2 qf = __half22float2(*(const __half2*)(qb + (size_t)s * Dd + 2 * dp));
        float2 kf = __half22float2(*(const __half2*)(kb + (size_t)s * Dd + 2 * dp));
        const float si = siS[sl], so = soS[sl];
        aq0 += si * qf.x; aq1 += si * qf.y;
        ak0 += so * kf.x; ak1 += so * kf.y;
    }
    sQ[p][2 * dp] = aq0; sQ[p][2 * dp + 1] = aq1;
    sK[p][2 * dp] = ak0; sK[p][2 * dp + 1] = ak1;
    __syncthreads();
    if (tid < 64) {
        float sq = 0.f, sk = 0.f;
#pragma unroll
        for (int w2 = 0; w2 < 8; w2++) { sq += sQ[w2][tid]; sk += sK[w2][tid]; }
        g_qpart2[(chunk * BH + bh) * Dd + tid] = sq;   // si-weighted q sums -> qsi
        g_kpart2[(chunk * BH + bh) * Dd + tid] = sk;   // so-weighted k sums -> kso
    }
}

// ---------------- fused: conserved_source + exp + kv partials via mma.sync ----------------
// Tiles staged in fp16 [32][72] (144B rows -> conflict-free trans ldmatrix);
// contraction kv[d][e] += k[s,d]*wv[s,e] done on the tensor pipe.
__global__ void __launch_bounds__(256) k_kv(const float* __restrict__ tptr)
{
    const int bh = blockIdx.y, chunk = blockIdx.x;
    __shared__ __half ksh[32][72];
    __shared__ __half wsh[32][72];
    __shared__ float qsiS[64];
    __shared__ float esred[32];
    const int tid = threadIdx.x;
    const int wid = tid >> 5, lane = tid & 31;
    const int lr = tid >> 3;
    const int lc = (tid & 7) << 3;
    if (tid < 64) {
        float a = 0.f;
#pragma unroll
        for (int c = 0; c < MCH; c++) a += g_qpart2[(c * BH + bh) * Dd + tid];
        qsiS[tid] = a + EPSf;
    }
    __syncthreads();
    const float invT = 1.f / tptr[0];
    const size_t base = (size_t)bh * Ntok * Dd;

    // warp tiling of the 64x64 output: 4 (M=d) x 2 (N=e)
    const int dbase = (wid & 3) << 4;   // 0,16,32,48
    const int ebase = (wid >> 2) << 5;  // 0,32
    // trans-ldmatrix addresses (A from ksh: fragment A[d][s]; B from wsh: fragment B[e][s])
    const uint32_t aAddr = smem_u32(&ksh[((lane >> 4) << 3) + (lane & 7)]
                                       [dbase + (((lane >> 3) & 1) << 3)]);
    const uint32_t bAddr = smem_u32(&wsh[(((lane >> 3) & 1) << 3) + (lane & 7)]
                                       [ebase + ((lane >> 4) << 3)]);

    float acc[4][4] = {};
    float esum = 0.f;
    for (int s0 = chunk * 256; s0 < chunk * 256 + 256; s0 += 32) {
        const int s = s0 + lr;
        uint4 kraw = *(const uint4*)(g_kh + base + (size_t)s * Dd + lc);
        uint4 vraw = *(const uint4*)(g_vh + base + (size_t)s * Dd + lc);
        const __half2* kh2 = (const __half2*)&kraw;
        const __half2* vh2 = (const __half2*)&vraw;
        float pd = 0.f;
#pragma unroll
        for (int j = 0; j < 4; j++) {
            float2 kf = __half22float2(kh2[j]);
            pd += (kf.x + EPSf) * qsiS[lc + 2 * j] + (kf.y + EPSf) * qsiS[lc + 2 * j + 1];
        }
        pd += __shfl_xor_sync(0xffffffffu, pd, 1);
        pd += __shfl_xor_sync(0xffffffffu, pd, 2);
        pd += __shfl_xor_sync(0xffffffffu, pd, 4);
        const float cs = fminf(1.f, fmaxf(-1.f, pd + EPSf));
        const float e = expf(cs * invT);
        if ((tid & 7) == 0) esum += e;
        *(uint4*)&ksh[lr][lc] = kraw;
        const __half2 e2 = __float2half2_rn(e);
        uint4 wout;
        ((__half2*)&wout)[0] = __hmul2(vh2[0], e2);
        ((__half2*)&wout)[1] = __hmul2(vh2[1], e2);
        ((__half2*)&wout)[2] = __hmul2(vh2[2], e2);
        ((__half2*)&wout)[3] = __hmul2(vh2[3], e2);
        *(uint4*)&wsh[lr][lc] = wout;
        __syncthreads();
#pragma unroll
        for (int ks2 = 0; ks2 < 2; ks2++) {
            uint32_t a[4], b0[4], b1[4];
            const uint32_t soff = (uint32_t)(ks2 * 16 * 144);  // 16 s-rows * 144B
            ldm4t(a,  aAddr + soff);
            ldm4t(b0, bAddr + soff);
            ldm4t(b1, bAddr + soff + 32);                      // e+16 cols = 32B
            mma16816(acc[0], a, &b0[0]);
            mma16816(acc[1], a, &b0[2]);
            mma16816(acc[2], a, &b1[0]);
            mma16816(acc[3], a, &b1[2]);
        }
        __syncthreads();
    }
    if ((tid & 7) == 0) esred[tid >> 3] = esum;
    __syncthreads();
    if (tid == 0) {
        float t = 0.f;
#pragma unroll
        for (int i = 0; i < 32; i++) t += esred[i];
        g_esum[chunk * BH + bh] = t;
    }
    // fragment epilogue: dst[d*64 + e]
    float* dst = g_kvpart + ((size_t)chunk * BH + bh) * Dd * Dd;
    const int dd = dbase + (lane >> 2);
    const int ee = ebase + ((lane & 3) << 1);
#pragma unroll
    for (int nf = 0; nf < 4; nf++) {
        *(float2*)(dst + (size_t)dd * Dd + ee + nf * 8)       = make_float2(acc[nf][0], acc[nf][1]);
        *(float2*)(dst + (size_t)(dd + 8) * Dd + ee + nf * 8) = make_float2(acc[nf][2], acc[nf][3]);
    }
}

// ---------------- reduce kv partials, apply softmax scale C/Σe ----------------
__global__ void k_kvred()
{
    const int i = blockIdx.x * blockDim.x + threadIdx.x;
    if (i >= BH * Dd * Dd) return;
    const int bh = i >> 12;
    float es = 0.f;
#pragma unroll
    for (int c = 0; c < MCH; c++) es += g_esum[c * BH + bh];
    const float scale = (float)Cc / es;
    float s = 0.f;
#pragma unroll
    for (int c = 0; c < MCH; c++) s += g_kvpart[(size_t)c * BH * Dd * Dd + i];
    g_kv[i] = s * scale;
}

// ---------------- out_update = (q @ kv) * si * sigmoid(q·(kso+eps)+eps) -> fp16 ----------------
__global__ void __launch_bounds__(256) k_outupd()
{
    const int bh = blockIdx.y, nt = blockIdx.x;
    const int b = bh >> 3, h = bh & 7;
    __shared__ float kvs[64][64];
    __shared__ float qsT[64][68];
    __shared__ float ksoS[64];
    const int tid = threadIdx.x;

    if (tid < 64) {
        float a = 0.f;
#pragma unroll
        for (int c = 0; c < MCH; c++) a += g_kpart2[(c * BH + bh) * Dd + tid];
        ksoS[tid] = a + EPSf;
    }

    const float4* kvsrc = (const float4*)(g_kv + (size_t)bh * (Dd * Dd));
    for (int i = tid; i < 1024; i += 256) ((float4*)kvs)[i] = kvsrc[i];

    const int lr = tid >> 3;
    const int lc = (tid & 7) << 3;
    const __half* qb = g_qh + (size_t)bh * Ntok * Dd + (size_t)(nt * 64) * Dd;
#pragma unroll
    for (int rr = lr; rr < 64; rr += 32) {
        uint4 qraw = *(const uint4*)(qb + rr * Dd + lc);
        const __half2* qh2 = (const __half2*)&qraw;
#pragma unroll
        for (int j = 0; j < 4; j++) {
            float2 qf = __half22float2(qh2[j]);
            qsT[lc + 2 * j][rr]     = qf.x;
            qsT[lc + 2 * j + 1][rr] = qf.y;
        }
    }
    __syncthreads();

    float ksoSum = 0.f;
#pragma unroll
    for (int d = 0; d < 64; d++) ksoSum += ksoS[d];

    const int n0 = (tid & 15) << 2, e0 = (tid >> 4) << 2;
    float acc[4][4] = {};
    float sadot[4] = {};
#pragma unroll
    for (int d = 0; d < 64; d++) {
        float4 qa = *(const float4*)&qsT[d][n0];
        float4 kf = *(const float4*)&kvs[d][e0];
        const float ko = ksoS[d];
        float qr[4] = {qa.x, qa.y, qa.z, qa.w};
        float krr[4] = {kf.x, kf.y, kf.z, kf.w};
#pragma unroll
        for (int i = 0; i < 4; i++) {
            sadot[i] = fmaf(qr[i], ko, sadot[i]);
#pragma unroll
            for (int j = 0; j < 4; j++)
                acc[i][j] = fmaf(qr[i], krr[j], acc[i][j]);
        }
    }

#pragma unroll
    for (int i = 0; i < 4; i++) {
        const int n = nt * 64 + n0 + i;
        const float cs_sink = sadot[i] + EPSf * ksoSum + EPSf;
        const float sa = 1.f / (1.f + expf(-cs_sink));
        const float scale = g_si[bh * Ntok + n] * sa;
        const int np = (h << 9) | (n >> 3);
        const int cbase = (n & 7) << 6;
        const size_t lin = (size_t)(b * Ntok + np) * Cc + cbase + e0;
        __half2 h01 = __floats2half2_rn(acc[i][0] * scale, acc[i][1] * scale);
        __half2 h23 = __floats2half2_rn(acc[i][2] * scale, acc[i][3] * scale);
        *(__half2*)(g_Oh + lin)     = h01;
        *(__half2*)(g_Oh + lin + 2) = h23;
    }
}

// ---------------- launch ----------------
extern "C" void kernel_launch(void* const* d_in, const int* in_sizes, int n_in,
                              void* d_out, int out_size)
{
    const float* query = (const float*)d_in[0];
    const float* Wq = (const float*)d_in[1];
    const float* bq = (const float*)d_in[2];
    const float* Wk = (const float*)d_in[3];
    const float* bk = (const float*)d_in[4];
    const float* Wv = (const float*)d_in[5];
    const float* bv = (const float*)d_in[6];
    const float* Wo = (const float*)d_in[7];
    const float* bo = (const float*)d_in[8];
    const float* temp = (const float*)d_in[9];
    float* out = (float*)d_out;

    const int DSMEM = 3 * 32768 + 1024;
    cudaFuncSetAttribute(gemm_tc, cudaFuncAttributeMaxDynamicSharedMemorySize, DSMEM);

    __half *pAh, *pOh, *pB;
    void* pIcol;
    cudaGetSymbolAddress((void**)&pAh, g_Ah);
    cudaGetSymbolAddress((void**)&pOh, g_Oh);
    cudaGetSymbolAddress((void**)&pB,  g_B);
    cudaGetSymbolAddress(&pIcol, g_icol);

    // zero fixed-point colsum accumulators (graph-capturable async memset)
    cudaMemsetAsync(pIcol, 0, 2 * BH * Dd * sizeof(unsigned long long));

    // merged operand conversion (query split + 4 weight converts)
    k_conv<<<17408, 256>>>(query, pAh, Wq, Wk, Wv, Wo, pB);

    // q/k/v projections in one launch; colsum fused in epilogue
    gemm_tc<<<dim3(4, 256, 3), 256, DSMEM>>>(pAh, pB, bq, bk, bv, nullptr, nullptr, 0);

    k_fuse1<<<dim3(MCH, BH), 256>>>();
    k_kv<<<dim3(MCH, BH), 256>>>(temp);
    k_kvred<<<(BH * Dd * Dd + 255) / 256, 256>>>();
    k_outupd<<<dim3(64, BH), 256>>>();

    // output projection (+bias+residual)
    gemm_tc<<<dim3(4, 256, 1), 256, DSMEM>>>(pOh, pB + 3 * (512 * 512), bo, bo, bo,
                                             query, out, 3);
}

// round 14
// speedup vs baseline: 1.5964x; 1.1485x over previous
#include <cuda_runtime.h>
#include <cuda_fp16.h>
#include <math.h>
#include <stdint.h>

#define Ntok 4096
#define Bb   8
#define Cc   512
#define Hh   8
#define Dd   64
#define BH   64          // B*H
#define EPSf 1e-6f
#define NCHUNK 8         // 512 K / 64 per chunk
#define MCH   16         // mid-section chunks
#define FIXSC 16777216.0f        // 2^24
#define FIXINV (1.0f / 16777216.0f)

// ---------------- scratch (static device arrays; no allocation) ----------------
__device__ __half g_qh[BH * Ntok * Dd];    // (B,H,N,D) sigmoid(q proj) fp16
__device__ __half g_kh[BH * Ntok * Dd];
__device__ __half g_vh[BH * Ntok * Dd];
__device__ float g_si[BH * Ntok];
__device__ unsigned long long g_icol[2][BH * Dd];                   // fixed-point col sums (0:q 1:k)
__device__ float g_kpart2[MCH * BH * Dd], g_qpart2[MCH * BH * Dd];  // weighted col sums
__device__ float g_esum[MCH * BH];                                   // exp-sum partials
__device__ __half g_kvh[BH * Dd * Dd];                               // fp16 kv (post softmax scale)
__device__ float g_kvpart[MCH * BH * Dd * Dd];

// fp16 GEMM operands
__device__ __half g_Ah[32768 * 512];       // fp16(query)
__device__ __half g_Oh[32768 * 512];       // fp16(out_update), scrambled (B,N,C)
__device__ __half g_B[4 * 512 * 512];      // [proj][n][k]

// ---------------- PTX helpers (base-arch only) ----------------
__device__ __forceinline__ uint32_t smem_u32(const void* p) {
    uint32_t a;
    asm("{ .reg .u64 t; cvta.to.shared.u64 t, %1; cvt.u32.u64 %0, t; }" : "=r"(a) : "l"(p));
    return a;
}
__device__ __forceinline__ void cp16(uint32_t dst, const void* src) {
    asm volatile("cp.async.cg.shared.global [%0], [%1], 16;" :: "r"(dst), "l"(src) : "memory");
}
__device__ __forceinline__ void cp_commit() {
    asm volatile("cp.async.commit_group;" ::: "memory");
}
__device__ __forceinline__ void cp_wait2() {
    asm volatile("cp.async.wait_group 2;" ::: "memory");
}
__device__ __forceinline__ void ldm4(uint32_t* r, uint32_t addr) {
    asm volatile("ldmatrix.sync.aligned.m8n8.x4.shared.b16 {%0,%1,%2,%3}, [%4];"
                 : "=r"(r[0]), "=r"(r[1]), "=r"(r[2]), "=r"(r[3]) : "r"(addr));
}
__device__ __forceinline__ void ldm4t(uint32_t* r, uint32_t addr) {
    asm volatile("ldmatrix.sync.aligned.m8n8.x4.trans.shared.b16 {%0,%1,%2,%3}, [%4];"
                 : "=r"(r[0]), "=r"(r[1]), "=r"(r[2]), "=r"(r[3]) : "r"(addr));
}
__device__ __forceinline__ void mma16816(float* c, const uint32_t* a, const uint32_t* b) {
    asm volatile(
        "mma.sync.aligned.m16n8k16.row.col.f32.f16.f16.f32 "
        "{%0,%1,%2,%3}, {%4,%5,%6,%7}, {%8,%9}, {%0,%1,%2,%3};"
        : "+f"(c[0]), "+f"(c[1]), "+f"(c[2]), "+f"(c[3])
        : "r"(a[0]), "r"(a[1]), "r"(a[2]), "r"(a[3]), "r"(b[0]), "r"(b[1]));
}

// ---------------- merged conversion kernel ----------------
__global__ void k_conv(const float* __restrict__ src, __half* __restrict__ dst,
                       const float* __restrict__ Wq, const float* __restrict__ Wk,
                       const float* __restrict__ Wv, const float* __restrict__ Wo,
                       __half* __restrict__ Bop)
{
    if (blockIdx.x < 16384) {
        int i = blockIdx.x * 256 + threadIdx.x;
        float4 v = ((const float4*)src)[i];
        __half2* hp = (__half2*)dst;
        hp[2 * i]     = __floats2half2_rn(v.x, v.y);
        hp[2 * i + 1] = __floats2half2_rn(v.z, v.w);
    } else {
        const int bid = blockIdx.x - 16384;     // 0..1023
        const int z = bid >> 8;                  // projection
        const int rem = bid & 255;
        const int by = rem >> 4, bx = rem & 15;
        const int tx = threadIdx.x & 31, ty = threadIdx.x >> 5;  // (32,8)
        const float* W = (z == 0) ? Wq : (z == 1) ? Wk : (z == 2) ? Wv : Wo;
        __half* Bp = Bop + (size_t)z * (512 * 512);
        __shared__ float t[32][33];
        const int k0 = by * 32, n0 = bx * 32;
        for (int j = ty; j < 32; j += 8) t[j][tx] = W[(size_t)(k0 + j) * 512 + n0 + tx];
        __syncthreads();
        for (int j = ty; j < 32; j += 8)
            Bp[(size_t)(n0 + j) * 512 + (k0 + tx)] = __float2half_rn(t[tx][j]);
    }
}

// ---------------- mma.sync GEMM (f32 acc): D[32768,512] = A[.,512] @ B^T ----------------
// mode 0: q (sigmoid -> g_qh + colsum), 1: k -> g_kh + colsum, 2: v -> g_vh,
// mode 3: out (+bias+resid -> d_out)
__global__ void __launch_bounds__(256) gemm_tc(
    const __half* __restrict__ A, const __half* __restrict__ Bbase,
    const float* __restrict__ b0, const float* __restrict__ b1, const float* __restrict__ b2,
    const float* __restrict__ resid, float* __restrict__ out, int modeBase)
{
    extern __shared__ char dyn[];
    const uint32_t sbase = (smem_u32(dyn) + 1023u) & ~1023u;
    char* dynA = dyn + (sbase - smem_u32(dyn));
    const int tid = threadIdx.x;
    const int wid = tid >> 5, lane = tid & 31;
    const int bn = blockIdx.x * 128, bm = blockIdx.y * 128;
    const int mode = modeBase + blockIdx.z;
    const __half* Bop = Bbase + (size_t)blockIdx.z * (512 * 512);
    const float* bias = (mode == 1) ? b1 : (mode == 2) ? b2 : b0;
    const int warpM = wid & 3, warpN = wid >> 2;   // 4 x 2 warps -> 32x64 warp tile

    float acc[2][8][4];
#pragma unroll
    for (int mf = 0; mf < 2; mf++)
#pragma unroll
        for (int nf = 0; nf < 8; nf++)
#pragma unroll
            for (int i = 0; i < 4; i++) acc[mf][nf][i] = 0.f;

    int aRow[2], bRow[4];
#pragma unroll
    for (int mf = 0; mf < 2; mf++)
        aRow[mf] = warpM * 32 + mf * 16 + (lane & 7) + ((lane >> 3) & 1) * 8;
    const int aHi = lane >> 4;
#pragma unroll
    for (int nf2 = 0; nf2 < 4; nf2++)
        bRow[nf2] = warpN * 64 + nf2 * 16 + (lane & 7) + (lane >> 4) * 8;
    const int bHi = (lane >> 3) & 1;

    auto issue = [&](int c) {
        const int akoff = c << 6;
        const uint32_t buf = sbase + (uint32_t)(c % 3) * 32768u;
#pragma unroll
        for (int t = 0; t < 4; t++) {
            int s = tid + (t << 8);
            int row = s >> 3, sc = s & 7;
            uint32_t off = row * 128 + ((sc ^ (row & 7)) << 4);
            cp16(buf + off, A + ((size_t)(bm + row) * 512 + akoff + sc * 8));
        }
#pragma unroll
        for (int t = 0; t < 4; t++) {
            int s = tid + (t << 8);
            int row = s >> 3, sc = s & 7;
            uint32_t off = row * 128 + ((sc ^ (row & 7)) << 4);
            cp16(buf + 16384u + off, Bop + ((size_t)(bn + row) * 512 + akoff + sc * 8));
        }
    };

    issue(0); cp_commit();
    issue(1); cp_commit();

    for (int c = 0; c < NCHUNK; c++) {
        if (c + 2 < NCHUNK) issue(c + 2);
        cp_commit();
        cp_wait2();
        __syncthreads();

        const uint32_t abuf = sbase + (uint32_t)(c % 3) * 32768u;
        const uint32_t bbuf = abuf + 16384u;
#pragma unroll
        for (int ks = 0; ks < 4; ks++) {
            uint32_t a[2][4], b[4][4];
#pragma unroll
            for (int mf = 0; mf < 2; mf++) {
                const int row = aRow[mf];
                const int cc = 2 * ks + aHi;
                ldm4(a[mf], abuf + row * 128 + ((cc ^ (row & 7)) << 4));
            }
#pragma unroll
            for (int nf2 = 0; nf2 < 4; nf2++) {
                const int row = bRow[nf2];
                const int cc = 2 * ks + bHi;
                ldm4(b[nf2], bbuf + row * 128 + ((cc ^ (row & 7)) << 4));
            }
#pragma unroll
            for (int mf = 0; mf < 2; mf++)
#pragma unroll
                for (int nf = 0; nf < 8; nf++)
                    mma16816(acc[mf][nf], a[mf], &b[nf >> 1][(nf & 1) * 2]);
        }
        __syncthreads();
    }

    // ---------------- epilogue ----------------
    if (mode <= 2) {
        __half* smh = (__half*)dynA;
        const int rloc = warpM * 32 + (lane >> 2);
        const int cloc = warpN * 64 + ((lane & 3) << 1);
#pragma unroll
        for (int mf = 0; mf < 2; mf++)
#pragma unroll
            for (int half = 0; half < 2; half++) {
#pragma unroll
                for (int nf = 0; nf < 8; nf++) {
                    const int c0 = bn + cloc + nf * 8;
                    float vx = acc[mf][nf][half * 2 + 0] + bias[c0];
                    float vy = acc[mf][nf][half * 2 + 1] + bias[c0 + 1];
                    if (mode <= 1) {
                        vx = 1.f / (1.f + expf(-vx));
                        vy = 1.f / (1.f + expf(-vy));
                    }
                    *(__half2*)&smh[(rloc + mf * 16 + half * 8) * 136 + cloc + nf * 8]
                        = __floats2half2_rn(vx, vy);
                }
            }
        __syncthreads();
        __half* dstg = (mode == 0) ? g_qh : (mode == 1) ? g_kh : g_vh;
        const int h0 = bn >> 6;
        const int hl = tid >> 7, nl = (tid & 127) >> 3, dp = tid & 7;
#pragma unroll
        for (int bb2 = 0; bb2 < 8; bb2++) {
            uint4 val = *(const uint4*)(smh + (size_t)(nl * 8 + bb2) * 136 + hl * 64 + dp * 8);
            *(uint4*)(dstg + ((size_t)((bb2 << 3) | (h0 + hl)) * Ntok + (bm >> 3) + nl) * Dd + dp * 8) = val;
        }
        // fused column sums (q/k): deterministic fixed-point atomics over the staged tile
        if (mode <= 1) {
            const int hl2 = tid >> 7;            // head within tile (0..1)
            const int b2 = (tid >> 4) & 7;       // batch
            const int d0 = (tid & 15) << 2;      // 4 d's
            float s0 = 0.f, s1 = 0.f, s2 = 0.f, s3 = 0.f;
#pragma unroll
            for (int n = 0; n < 16; n++) {
                const __half* rowp = smh + (size_t)(n * 8 + b2) * 136 + hl2 * 64 + d0;
                float2 p0 = __half22float2(*(const __half2*)rowp);
                float2 p1 = __half22float2(*(const __half2*)(rowp + 2));
                s0 += p0.x; s1 += p0.y; s2 += p1.x; s3 += p1.y;
            }
            const int bh = (b2 << 3) | ((bn >> 6) + hl2);
            unsigned long long* dst = &g_icol[mode][bh * Dd + d0];
            atomicAdd(dst + 0, (unsigned long long)(long long)llrintf(s0 * FIXSC));
            atomicAdd(dst + 1, (unsigned long long)(long long)llrintf(s1 * FIXSC));
            atomicAdd(dst + 2, (unsigned long long)(long long)llrintf(s2 * FIXSC));
            atomicAdd(dst + 3, (unsigned long long)(long long)llrintf(s3 * FIXSC));
        }
    } else {
        const int r0base = bm + warpM * 32 + (lane >> 2);
        const int cb = bn + warpN * 64 + ((lane & 3) << 1);
#pragma unroll
        for (int mf = 0; mf < 2; mf++)
#pragma unroll
            for (int half = 0; half < 2; half++) {
                const int r = r0base + mf * 16 + half * 8;
#pragma unroll
                for (int nf = 0; nf < 8; nf++) {
                    const int c0 = cb + nf * 8;
                    const int bb = r >> 12, n = r & 4095;
                    const size_t o = (size_t)((n << 3) | bb) * Cc + c0;
                    float2 rs = *(const float2*)(resid + o);
                    float2 v;
                    v.x = acc[mf][nf][half * 2 + 0] + bias[c0] + rs.x;
                    v.y = acc[mf][nf][half * 2 + 1] + bias[c0 + 1] + rs.y;
                    *(float2*)(out + o) = v;
                }
            }
    }
}

// ---------------- fused: rownorm (si/so) + weighted colsum partials ----------------
__global__ void __launch_bounds__(256) k_fuse1()
{
    const int bh = blockIdx.y, chunk = blockIdx.x;
    const int tid = threadIdx.x;
    __shared__ float ksS[64], qsS[64];
    __shared__ float siS[256], soS[256];
    __shared__ float sQ[8][64], sK[8][64];
    if (tid < 64) {
        ksS[tid] = (float)(long long)g_icol[1][bh * Dd + tid] * FIXINV + EPSf;
        qsS[tid] = (float)(long long)g_icol[0][bh * Dd + tid] * FIXINV + EPSf;
    }
    __syncthreads();
    const __half* qb = g_qh + (size_t)bh * Ntok * Dd;
    const __half* kb = g_kh + (size_t)bh * Ntok * Dd;

    // phase 1: one thread per s-row, private dot over d (no shuffles)
    {
        const int s = chunk * 256 + tid;
        const uint4* qrow = (const uint4*)(qb + (size_t)s * Dd);
        const uint4* krow = (const uint4*)(kb + (size_t)s * Dd);
        float s1 = 0.f, s2 = 0.f;
#pragma unroll
        for (int j = 0; j < 8; j++) {
            uint4 qraw = qrow[j];
            uint4 kraw = krow[j];
            const __half2* qh2 = (const __half2*)&qraw;
            const __half2* kh2 = (const __half2*)&kraw;
#pragma unroll
            for (int u = 0; u < 4; u++) {
                float2 qf = __half22float2(qh2[u]);
                float2 kf = __half22float2(kh2[u]);
                const int d = j * 8 + 2 * u;
                s1 += (qf.x + EPSf) * ksS[d] + (qf.y + EPSf) * ksS[d + 1];
                s2 += (kf.x + EPSf) * qsS[d] + (kf.y + EPSf) * qsS[d + 1];
            }
        }
        const float si = 1.f / (s1 + EPSf);
        const float so = 1.f / (s2 + EPSf);
        g_si[bh * Ntok + s] = si;
        siS[tid] = si; soS[tid] = so;
    }
    __syncthreads();

    // phase 2: weighted colsums, coalesced (rows L1-hot from phase 1)
    const int p = tid >> 5, dp = tid & 31;
    float aq0 = 0.f, aq1 = 0.f, ak0 = 0.f, ak1 = 0.f;
#pragma unroll 4
    for (int i = 0; i < 32; i++) {
        const int sl = p + 8 * i;
        const int s = chunk * 256 + sl;
        float2 qf = __half22float2(*(const __half2*)(qb + (size_t)s * Dd + 2 * dp));
        float2 kf = __half22float2(*(const __half2*)(kb + (size_t)s * Dd + 2 * dp));
        const float si = siS[sl], so = soS[sl];
        aq0 += si * qf.x; aq1 += si * qf.y;
        ak0 += so * kf.x; ak1 += so * kf.y;
    }
    sQ[p][2 * dp] = aq0; sQ[p][2 * dp + 1] = aq1;
    sK[p][2 * dp] = ak0; sK[p][2 * dp + 1] = ak1;
    __syncthreads();
    if (tid < 64) {
        float sq = 0.f, sk = 0.f;
#pragma unroll
        for (int w2 = 0; w2 < 8; w2++) { sq += sQ[w2][tid]; sk += sK[w2][tid]; }
        g_qpart2[(chunk * BH + bh) * Dd + tid] = sq;   // si-weighted q sums -> qsi
        g_kpart2[(chunk * BH + bh) * Dd + tid] = sk;   // so-weighted k sums -> kso
    }
}

// ---------------- fused: conserved_source + exp + kv partials via mma.sync ----------------
__global__ void __launch_bounds__(256) k_kv(const float* __restrict__ tptr)
{
    const int bh = blockIdx.y, chunk = blockIdx.x;
    __shared__ __half ksh[32][72];
    __shared__ __half wsh[32][72];
    __shared__ float qsiS[64];
    __shared__ float esred[32];
    const int tid = threadIdx.x;
    const int wid = tid >> 5, lane = tid & 31;
    const int lr = tid >> 3;
    const int lc = (tid & 7) << 3;
    if (tid < 64) {
        float a = 0.f;
#pragma unroll
        for (int c = 0; c < MCH; c++) a += g_qpart2[(c * BH + bh) * Dd + tid];
        qsiS[tid] = a + EPSf;
    }
    __syncthreads();
    const float invT = 1.f / tptr[0];
    const size_t base = (size_t)bh * Ntok * Dd;

    const int dbase = (wid & 3) << 4;   // 0,16,32,48
    const int ebase = (wid >> 2) << 5;  // 0,32
    const uint32_t aAddr = smem_u32(&ksh[((lane >> 4) << 3) + (lane & 7)]
                                       [dbase + (((lane >> 3) & 1) << 3)]);
    const uint32_t bAddr = smem_u32(&wsh[(((lane >> 3) & 1) << 3) + (lane & 7)]
                                       [ebase + ((lane >> 4) << 3)]);

    float acc[4][4] = {};
    float esum = 0.f;
    for (int s0 = chunk * 256; s0 < chunk * 256 + 256; s0 += 32) {
        const int s = s0 + lr;
        uint4 kraw = *(const uint4*)(g_kh + base + (size_t)s * Dd + lc);
        uint4 vraw = *(const uint4*)(g_vh + base + (size_t)s * Dd + lc);
        const __half2* kh2 = (const __half2*)&kraw;
        const __half2* vh2 = (const __half2*)&vraw;
        float pd = 0.f;
#pragma unroll
        for (int j = 0; j < 4; j++) {
            float2 kf = __half22float2(kh2[j]);
            pd += (kf.x + EPSf) * qsiS[lc + 2 * j] + (kf.y + EPSf) * qsiS[lc + 2 * j + 1];
        }
        pd += __shfl_xor_sync(0xffffffffu, pd, 1);
        pd += __shfl_xor_sync(0xffffffffu, pd, 2);
        pd += __shfl_xor_sync(0xffffffffu, pd, 4);
        const float cs = fminf(1.f, fmaxf(-1.f, pd + EPSf));
        const float e = expf(cs * invT);
        if ((tid & 7) == 0) esum += e;
        *(uint4*)&ksh[lr][lc] = kraw;
        const __half2 e2 = __float2half2_rn(e);
        uint4 wout;
        ((__half2*)&wout)[0] = __hmul2(vh2[0], e2);
        ((__half2*)&wout)[1] = __hmul2(vh2[1], e2);
        ((__half2*)&wout)[2] = __hmul2(vh2[2], e2);
        ((__half2*)&wout)[3] = __hmul2(vh2[3], e2);
        *(uint4*)&wsh[lr][lc] = wout;
        __syncthreads();
#pragma unroll
        for (int ks2 = 0; ks2 < 2; ks2++) {
            uint32_t a[4], b0[4], b1[4];
            const uint32_t soff = (uint32_t)(ks2 * 16 * 144);  // 16 s-rows * 144B
            ldm4t(a,  aAddr + soff);
            ldm4t(b0, bAddr + soff);
            ldm4t(b1, bAddr + soff + 32);                      // e+16 cols = 32B
            mma16816(acc[0], a, &b0[0]);
            mma16816(acc[1], a, &b0[2]);
            mma16816(acc[2], a, &b1[0]);
            mma16816(acc[3], a, &b1[2]);
        }
        __syncthreads();
    }
    if ((tid & 7) == 0) esred[tid >> 3] = esum;
    __syncthreads();
    if (tid == 0) {
        float t = 0.f;
#pragma unroll
        for (int i = 0; i < 32; i++) t += esred[i];
        g_esum[chunk * BH + bh] = t;
    }
    float* dst = g_kvpart + ((size_t)chunk * BH + bh) * Dd * Dd;
    const int dd = dbase + (lane >> 2);
    const int ee = ebase + ((lane & 3) << 1);
#pragma unroll
    for (int nf = 0; nf < 4; nf++) {
        *(float2*)(dst + (size_t)dd * Dd + ee + nf * 8)       = make_float2(acc[nf][0], acc[nf][1]);
        *(float2*)(dst + (size_t)(dd + 8) * Dd + ee + nf * 8) = make_float2(acc[nf][2], acc[nf][3]);
    }
}

// ---------------- reduce kv partials, apply softmax scale C/Σe -> fp16 ----------------
__global__ void k_kvred()
{
    const int i = blockIdx.x * blockDim.x + threadIdx.x;
    if (i >= BH * Dd * Dd) return;
    const int bh = i >> 12;
    float es = 0.f;
#pragma unroll
    for (int c = 0; c < MCH; c++) es += g_esum[c * BH + bh];
    const float scale = (float)Cc / es;
    float s = 0.f;
#pragma unroll
    for (int c = 0; c < MCH; c++) s += g_kvpart[(size_t)c * BH * Dd * Dd + i];
    g_kvh[i] = __float2half_rn(s * scale);
}

// ---------------- out_update = (q @ kv) * si * sigmoid(q·(kso+eps)+eps) via mma.sync ----------------
__global__ void __launch_bounds__(256) k_outupd()
{
    const int bh = blockIdx.y, nt = blockIdx.x;
    const int b = bh >> 3, h = bh & 7;
    __shared__ __half qsh[64][72];
    __shared__ __half kvh[64][72];
    __shared__ float ksoS[64];
    __shared__ float sadotS[64];
    __shared__ float siS[64];
    const int tid = threadIdx.x;
    const int wid = tid >> 5, lane = tid & 31;

    if (tid < 64) {
        float a = 0.f;
#pragma unroll
        for (int c = 0; c < MCH; c++) a += g_kpart2[(c * BH + bh) * Dd + tid];
        ksoS[tid] = a + EPSf;
        siS[tid] = g_si[bh * Ntok + nt * 64 + tid];
    }

    // load q (64 rows of this n-tile) and kv (64x64) into fp16 smem tiles
    const int lr = tid >> 3, lc = (tid & 7) << 3;
    const __half* qb = g_qh + (size_t)bh * Ntok * Dd + (size_t)(nt * 64) * Dd;
    const __half* kvb = g_kvh + (size_t)bh * (Dd * Dd);
    *(uint4*)&qsh[lr][lc]      = *(const uint4*)(qb + (size_t)lr * Dd + lc);
    *(uint4*)&qsh[lr + 32][lc] = *(const uint4*)(qb + (size_t)(lr + 32) * Dd + lc);
    *(uint4*)&kvh[lr][lc]      = *(const uint4*)(kvb + (size_t)lr * Dd + lc);
    *(uint4*)&kvh[lr + 32][lc] = *(const uint4*)(kvb + (size_t)(lr + 32) * Dd + lc);
    __syncthreads();

    // sadot[n] = q[n] . (kso+eps): 4 threads per row, 16 d's each
    {
        const int row = tid >> 2, part = tid & 3;
        float s = 0.f;
#pragma unroll
        for (int j = 0; j < 8; j++) {
            const int d = part * 16 + 2 * j;
            float2 qf = __half22float2(*(const __half2*)&qsh[row][d]);
            s += qf.x * ksoS[d] + qf.y * ksoS[d + 1];
        }
        s += __shfl_xor_sync(0xffffffffu, s, 1);
        s += __shfl_xor_sync(0xffffffffu, s, 2);
        if (part == 0) sadotS[row] = s;
    }
    __syncthreads();

    float ksoSum = 0.f;
#pragma unroll
    for (int d = 0; d < 64; d++) ksoSum += ksoS[d];

    // mma: warps 4(n) x 2(e); warp tile 16n x 32e; K = 64 (4 steps)
    const int nbase = (wid & 3) << 4;
    const int ebase = (wid >> 2) << 5;
    const uint32_t aAddr = smem_u32(&qsh[nbase + (lane & 7) + (((lane >> 3) & 1) << 3)]
                                       [(lane >> 4) << 3]);
    const uint32_t bAddr = smem_u32(&kvh[(((lane >> 3) & 1) << 3) + (lane & 7)]
                                       [ebase + ((lane >> 4) << 3)]);
    float acc[4][4] = {};
#pragma unroll
    for (int ks2 = 0; ks2 < 4; ks2++) {
        uint32_t a[4], b0[4], b1[4];
        const uint32_t dA = (uint32_t)(ks2 * 16 * 2);    // +16 halves = 32B along row
        const uint32_t dB = (uint32_t)(ks2 * 16 * 144);  // +16 d-rows
        ldm4(a, aAddr + dA);
        ldm4t(b0, bAddr + dB);
        ldm4t(b1, bAddr + dB + 32);
        mma16816(acc[0], a, &b0[0]);
        mma16816(acc[1], a, &b0[2]);
        mma16816(acc[2], a, &b1[0]);
        mma16816(acc[3], a, &b1[2]);
    }

    // epilogue: scale by si*sa, store fp16 to scrambled (B,N,C)
    const int r0 = nbase + (lane >> 2);
    const int e0 = ebase + ((lane & 3) << 1);
#pragma unroll
    for (int half = 0; half < 2; half++) {
        const int nloc = r0 + half * 8;
        const int n = nt * 64 + nloc;
        const float cs_sink = sadotS[nloc] + EPSf * ksoSum + EPSf;
        const float sa = 1.f / (1.f + expf(-cs_sink));
        const float scale = siS[nloc] * sa;
        const int np = (h << 9) | (n >> 3);
        const int cbase = (n & 7) << 6;
        const size_t lin = (size_t)(b * Ntok + np) * Cc + cbase;
#pragma unroll
        for (int nf = 0; nf < 4; nf++) {
            float vx = acc[nf][half * 2 + 0] * scale;
            float vy = acc[nf][half * 2 + 1] * scale;
            *(__half2*)(g_Oh + lin + e0 + nf * 8) = __floats2half2_rn(vx, vy);
        }
    }
}

// ---------------- launch ----------------
extern "C" void kernel_launch(void* const* d_in, const int* in_sizes, int n_in,
                              void* d_out, int out_size)
{
    const float* query = (const float*)d_in[0];
    const float* Wq = (const float*)d_in[1];
    const float* bq = (const float*)d_in[2];
    const float* Wk = (const float*)d_in[3];
    const float* bk = (const float*)d_in[4];
    const float* Wv = (const float*)d_in[5];
    const float* bv = (const float*)d_in[6];
    const float* Wo = (const float*)d_in[7];
    const float* bo = (const float*)d_in[8];
    const float* temp = (const float*)d_in[9];
    float* out = (float*)d_out;

    const int DSMEM = 3 * 32768 + 1024;
    cudaFuncSetAttribute(gemm_tc, cudaFuncAttributeMaxDynamicSharedMemorySize, DSMEM);

    __half *pAh, *pOh, *pB;
    void* pIcol;
    cudaGetSymbolAddress((void**)&pAh, g_Ah);
    cudaGetSymbolAddress((void**)&pOh, g_Oh);
    cudaGetSymbolAddress((void**)&pB,  g_B);
    cudaGetSymbolAddress(&pIcol, g_icol);

    // zero fixed-point colsum accumulators (graph-capturable async memset)
    cudaMemsetAsync(pIcol, 0, 2 * BH * Dd * sizeof(unsigned long long));

    // merged operand conversion (query split + 4 weight converts)
    k_conv<<<17408, 256>>>(query, pAh, Wq, Wk, Wv, Wo, pB);

    // q/k/v projections in one launch; colsum fused in epilogue
    gemm_tc<<<dim3(4, 256, 3), 256, DSMEM>>>(pAh, pB, bq, bk, bv, nullptr, nullptr, 0);

    k_fuse1<<<dim3(MCH, BH), 256>>>();
    k_kv<<<dim3(MCH, BH), 256>>>(temp);
    k_kvred<<<(BH * Dd * Dd + 255) / 256, 256>>>();
    k_outupd<<<dim3(64, BH), 256>>>();

    // output projection (+bias+residual)
    gemm_tc<<<dim3(4, 256, 1), 256, DSMEM>>>(pOh, pB + 3 * (512 * 512), bo, bo, bo,
                                             query, out, 3);
}

// round 15
// speedup vs baseline: 1.6038x; 1.0046x over previous
#include <cuda_runtime.h>
#include <cuda_fp16.h>
#include <math.h>
#include <stdint.h>

#define Ntok 4096
#define Bb   8
#define Cc   512
#define Hh   8
#define Dd   64
#define BH   64          // B*H
#define EPSf 1e-6f
#define NCHUNK 8         // 512 K / 64 per chunk
#define MCH   16         // mid-section chunks
#define FIXSC 16777216.0f        // 2^24
#define FIXINV (1.0f / 16777216.0f)

// ---------------- scratch (static device arrays; no allocation) ----------------
__device__ __half g_qh[BH * Ntok * Dd];    // (B,H,N,D) sigmoid(q proj) fp16
__device__ __half g_kh[BH * Ntok * Dd];
__device__ __half g_vh[BH * Ntok * Dd];
__device__ float g_si[BH * Ntok];
__device__ unsigned long long g_icol[2][BH * Dd];                   // fixed-point col sums (0:q 1:k)
__device__ float g_kpart2[MCH * BH * Dd], g_qpart2[MCH * BH * Dd];  // weighted col sums
__device__ float g_esum[MCH * BH];                                   // exp-sum partials
__device__ __half g_kvh[BH * Dd * Dd];                               // fp16 kv (post softmax scale)
__device__ float g_kvpart[MCH * BH * Dd * Dd];

// fp16 GEMM operands
__device__ __half g_Ah[32768 * 512];       // fp16(query)
__device__ __half g_Oh[32768 * 512];       // fp16(out_update), scrambled (B,N,C)
__device__ __half g_B[4 * 512 * 512];      // [proj][n][k]

// ---------------- PTX helpers (base-arch only) ----------------
__device__ __forceinline__ uint32_t smem_u32(const void* p) {
    uint32_t a;
    asm("{ .reg .u64 t; cvta.to.shared.u64 t, %1; cvt.u32.u64 %0, t; }" : "=r"(a) : "l"(p));
    return a;
}
__device__ __forceinline__ void cp16(uint32_t dst, const void* src) {
    asm volatile("cp.async.cg.shared.global [%0], [%1], 16;" :: "r"(dst), "l"(src) : "memory");
}
__device__ __forceinline__ void cp_commit() {
    asm volatile("cp.async.commit_group;" ::: "memory");
}
__device__ __forceinline__ void cp_wait2() {
    asm volatile("cp.async.wait_group 2;" ::: "memory");
}
__device__ __forceinline__ void ldm4(uint32_t* r, uint32_t addr) {
    asm volatile("ldmatrix.sync.aligned.m8n8.x4.shared.b16 {%0,%1,%2,%3}, [%4];"
                 : "=r"(r[0]), "=r"(r[1]), "=r"(r[2]), "=r"(r[3]) : "r"(addr));
}
__device__ __forceinline__ void ldm4t(uint32_t* r, uint32_t addr) {
    asm volatile("ldmatrix.sync.aligned.m8n8.x4.trans.shared.b16 {%0,%1,%2,%3}, [%4];"
                 : "=r"(r[0]), "=r"(r[1]), "=r"(r[2]), "=r"(r[3]) : "r"(addr));
}
__device__ __forceinline__ void mma16816(float* c, const uint32_t* a, const uint32_t* b) {
    asm volatile(
        "mma.sync.aligned.m16n8k16.row.col.f32.f16.f16.f32 "
        "{%0,%1,%2,%3}, {%4,%5,%6,%7}, {%8,%9}, {%0,%1,%2,%3};"
        : "+f"(c[0]), "+f"(c[1]), "+f"(c[2]), "+f"(c[3])
        : "r"(a[0]), "r"(a[1]), "r"(a[2]), "r"(a[3]), "r"(b[0]), "r"(b[1]));
}

// ---------------- merged conversion kernel ----------------
__global__ void k_conv(const float* __restrict__ src, __half* __restrict__ dst,
                       const float* __restrict__ Wq, const float* __restrict__ Wk,
                       const float* __restrict__ Wv, const float* __restrict__ Wo,
                       __half* __restrict__ Bop)
{
    if (blockIdx.x < 16384) {
        int i = blockIdx.x * 256 + threadIdx.x;
        float4 v = ((const float4*)src)[i];
        __half2* hp = (__half2*)dst;
        hp[2 * i]     = __floats2half2_rn(v.x, v.y);
        hp[2 * i + 1] = __floats2half2_rn(v.z, v.w);
    } else {
        const int bid = blockIdx.x - 16384;     // 0..1023
        const int z = bid >> 8;                  // projection
        const int rem = bid & 255;
        const int by = rem >> 4, bx = rem & 15;
        const int tx = threadIdx.x & 31, ty = threadIdx.x >> 5;  // (32,8)
        const float* W = (z == 0) ? Wq : (z == 1) ? Wk : (z == 2) ? Wv : Wo;
        __half* Bp = Bop + (size_t)z * (512 * 512);
        __shared__ float t[32][33];
        const int k0 = by * 32, n0 = bx * 32;
        for (int j = ty; j < 32; j += 8) t[j][tx] = W[(size_t)(k0 + j) * 512 + n0 + tx];
        __syncthreads();
        for (int j = ty; j < 32; j += 8)
            Bp[(size_t)(n0 + j) * 512 + (k0 + tx)] = __float2half_rn(t[tx][j]);
    }
}

// ---------------- mma.sync GEMM (f32 acc): D[32768,512] = A[.,512] @ B^T ----------------
// mode 0: q (sigmoid -> g_qh + colsum), 1: k -> g_kh + colsum, 2: v -> g_vh,
// mode 3: out (+bias+resid -> d_out)
__global__ void __launch_bounds__(256, 2) gemm_tc(
    const __half* __restrict__ A, const __half* __restrict__ Bbase,
    const float* __restrict__ b0, const float* __restrict__ b1, const float* __restrict__ b2,
    const float* __restrict__ resid, float* __restrict__ out, int modeBase)
{
    extern __shared__ char dyn[];
    const uint32_t sbase = (smem_u32(dyn) + 1023u) & ~1023u;
    char* dynA = dyn + (sbase - smem_u32(dyn));
    const int tid = threadIdx.x;
    const int wid = tid >> 5, lane = tid & 31;
    const int bn = blockIdx.x * 128, bm = blockIdx.y * 128;
    const int mode = modeBase + blockIdx.z;
    const __half* Bop = Bbase + (size_t)blockIdx.z * (512 * 512);
    const float* bias = (mode == 1) ? b1 : (mode == 2) ? b2 : b0;
    const int warpM = wid & 3, warpN = wid >> 2;   // 4 x 2 warps -> 32x64 warp tile

    float acc[2][8][4];
#pragma unroll
    for (int mf = 0; mf < 2; mf++)
#pragma unroll
        for (int nf = 0; nf < 8; nf++)
#pragma unroll
            for (int i = 0; i < 4; i++) acc[mf][nf][i] = 0.f;

    int aRow[2], bRow[4];
#pragma unroll
    for (int mf = 0; mf < 2; mf++)
        aRow[mf] = warpM * 32 + mf * 16 + (lane & 7) + ((lane >> 3) & 1) * 8;
    const int aHi = lane >> 4;
#pragma unroll
    for (int nf2 = 0; nf2 < 4; nf2++)
        bRow[nf2] = warpN * 64 + nf2 * 16 + (lane & 7) + (lane >> 4) * 8;
    const int bHi = (lane >> 3) & 1;

    auto issue = [&](int c) {
        const int akoff = c << 6;
        const uint32_t buf = sbase + (uint32_t)(c % 3) * 32768u;
#pragma unroll
        for (int t = 0; t < 4; t++) {
            int s = tid + (t << 8);
            int row = s >> 3, sc = s & 7;
            uint32_t off = row * 128 + ((sc ^ (row & 7)) << 4);
            cp16(buf + off, A + ((size_t)(bm + row) * 512 + akoff + sc * 8));
        }
#pragma unroll
        for (int t = 0; t < 4; t++) {
            int s = tid + (t << 8);
            int row = s >> 3, sc = s & 7;
            uint32_t off = row * 128 + ((sc ^ (row & 7)) << 4);
            cp16(buf + 16384u + off, Bop + ((size_t)(bn + row) * 512 + akoff + sc * 8));
        }
    };

    issue(0); cp_commit();
    issue(1); cp_commit();

    for (int c = 0; c < NCHUNK; c++) {
        if (c + 2 < NCHUNK) issue(c + 2);
        cp_commit();
        cp_wait2();
        __syncthreads();

        const uint32_t abuf = sbase + (uint32_t)(c % 3) * 32768u;
        const uint32_t bbuf = abuf + 16384u;
#pragma unroll
        for (int ks = 0; ks < 4; ks++) {
            uint32_t a[2][4], b[4][4];
#pragma unroll
            for (int mf = 0; mf < 2; mf++) {
                const int row = aRow[mf];
                const int cc = 2 * ks + aHi;
                ldm4(a[mf], abuf + row * 128 + ((cc ^ (row & 7)) << 4));
            }
#pragma unroll
            for (int nf2 = 0; nf2 < 4; nf2++) {
                const int row = bRow[nf2];
                const int cc = 2 * ks + bHi;
                ldm4(b[nf2], bbuf + row * 128 + ((cc ^ (row & 7)) << 4));
            }
#pragma unroll
            for (int mf = 0; mf < 2; mf++)
#pragma unroll
                for (int nf = 0; nf < 8; nf++)
                    mma16816(acc[mf][nf], a[mf], &b[nf >> 1][(nf & 1) * 2]);
        }
        __syncthreads();
    }

    // ---------------- epilogue ----------------
    if (mode <= 2) {
        __half* smh = (__half*)dynA;
        const int rloc = warpM * 32 + (lane >> 2);
        const int cloc = warpN * 64 + ((lane & 3) << 1);
#pragma unroll
        for (int mf = 0; mf < 2; mf++)
#pragma unroll
            for (int half = 0; half < 2; half++) {
#pragma unroll
                for (int nf = 0; nf < 8; nf++) {
                    const int c0 = bn + cloc + nf * 8;
                    float vx = acc[mf][nf][half * 2 + 0] + bias[c0];
                    float vy = acc[mf][nf][half * 2 + 1] + bias[c0 + 1];
                    if (mode <= 1) {
                        vx = 1.f / (1.f + expf(-vx));
                        vy = 1.f / (1.f + expf(-vy));
                    }
                    *(__half2*)&smh[(rloc + mf * 16 + half * 8) * 136 + cloc + nf * 8]
                        = __floats2half2_rn(vx, vy);
                }
            }
        __syncthreads();
        __half* dstg = (mode == 0) ? g_qh : (mode == 1) ? g_kh : g_vh;
        const int h0 = bn >> 6;
        const int hl = tid >> 7, nl = (tid & 127) >> 3, dp = tid & 7;
#pragma unroll
        for (int bb2 = 0; bb2 < 8; bb2++) {
            uint4 val = *(const uint4*)(smh + (size_t)(nl * 8 + bb2) * 136 + hl * 64 + dp * 8);
            *(uint4*)(dstg + ((size_t)((bb2 << 3) | (h0 + hl)) * Ntok + (bm >> 3) + nl) * Dd + dp * 8) = val;
        }
        // fused column sums (q/k): deterministic fixed-point atomics over the staged tile
        if (mode <= 1) {
            const int hl2 = tid >> 7;            // head within tile (0..1)
            const int b2 = (tid >> 4) & 7;       // batch
            const int d0 = (tid & 15) << 2;      // 4 d's
            float s0 = 0.f, s1 = 0.f, s2 = 0.f, s3 = 0.f;
#pragma unroll
            for (int n = 0; n < 16; n++) {
                const __half* rowp = smh + (size_t)(n * 8 + b2) * 136 + hl2 * 64 + d0;
                float2 p0 = __half22float2(*(const __half2*)rowp);
                float2 p1 = __half22float2(*(const __half2*)(rowp + 2));
                s0 += p0.x; s1 += p0.y; s2 += p1.x; s3 += p1.y;
            }
            const int bh = (b2 << 3) | ((bn >> 6) + hl2);
            unsigned long long* dst = &g_icol[mode][bh * Dd + d0];
            atomicAdd(dst + 0, (unsigned long long)(long long)llrintf(s0 * FIXSC));
            atomicAdd(dst + 1, (unsigned long long)(long long)llrintf(s1 * FIXSC));
            atomicAdd(dst + 2, (unsigned long long)(long long)llrintf(s2 * FIXSC));
            atomicAdd(dst + 3, (unsigned long long)(long long)llrintf(s3 * FIXSC));
        }
    } else {
        const int r0base = bm + warpM * 32 + (lane >> 2);
        const int cb = bn + warpN * 64 + ((lane & 3) << 1);
#pragma unroll
        for (int mf = 0; mf < 2; mf++)
#pragma unroll
            for (int half = 0; half < 2; half++) {
                const int r = r0base + mf * 16 + half * 8;
#pragma unroll
                for (int nf = 0; nf < 8; nf++) {
                    const int c0 = cb + nf * 8;
                    const int bb = r >> 12, n = r & 4095;
                    const size_t o = (size_t)((n << 3) | bb) * Cc + c0;
                    float2 rs = *(const float2*)(resid + o);
                    float2 v;
                    v.x = acc[mf][nf][half * 2 + 0] + bias[c0] + rs.x;
                    v.y = acc[mf][nf][half * 2 + 1] + bias[c0 + 1] + rs.y;
                    *(float2*)(out + o) = v;
                }
            }
    }
}

// ---------------- fused: rownorm (si/so) + weighted colsum partials ----------------
__global__ void __launch_bounds__(256) k_fuse1()
{
    const int bh = blockIdx.y, chunk = blockIdx.x;
    const int tid = threadIdx.x;
    __shared__ float ksS[64], qsS[64];
    __shared__ float siS[256], soS[256];
    __shared__ float sQ[8][64], sK[8][64];
    if (tid < 64) {
        ksS[tid] = (float)(long long)g_icol[1][bh * Dd + tid] * FIXINV + EPSf;
        qsS[tid] = (float)(long long)g_icol[0][bh * Dd + tid] * FIXINV + EPSf;
    }
    __syncthreads();
    const __half* qb = g_qh + (size_t)bh * Ntok * Dd;
    const __half* kb = g_kh + (size_t)bh * Ntok * Dd;

    // phase 1: one thread per s-row, private dot over d (no shuffles)
    {
        const int s = chunk * 256 + tid;
        const uint4* qrow = (const uint4*)(qb + (size_t)s * Dd);
        const uint4* krow = (const uint4*)(kb + (size_t)s * Dd);
        float s1 = 0.f, s2 = 0.f;
#pragma unroll
        for (int j = 0; j < 8; j++) {
            uint4 qraw = qrow[j];
            uint4 kraw = krow[j];
            const __half2* qh2 = (const __half2*)&qraw;
            const __half2* kh2 = (const __half2*)&kraw;
#pragma unroll
            for (int u = 0; u < 4; u++) {
                float2 qf = __half22float2(qh2[u]);
                float2 kf = __half22float2(kh2[u]);
                const int d = j * 8 + 2 * u;
                s1 += (qf.x + EPSf) * ksS[d] + (qf.y + EPSf) * ksS[d + 1];
                s2 += (kf.x + EPSf) * qsS[d] + (kf.y + EPSf) * qsS[d + 1];
            }
        }
        const float si = 1.f / (s1 + EPSf);
        const float so = 1.f / (s2 + EPSf);
        g_si[bh * Ntok + s] = si;
        siS[tid] = si; soS[tid] = so;
    }
    __syncthreads();

    // phase 2: weighted colsums, coalesced (rows L1-hot from phase 1)
    const int p = tid >> 5, dp = tid & 31;
    float aq0 = 0.f, aq1 = 0.f, ak0 = 0.f, ak1 = 0.f;
#pragma unroll 4
    for (int i = 0; i < 32; i++) {
        const int sl = p + 8 * i;
        const int s = chunk * 256 + sl;
        float2 qf = __half22float2(*(const __half2*)(qb + (size_t)s * Dd + 2 * dp));
        float2 kf = __half22float2(*(const __half2*)(kb + (size_t)s * Dd + 2 * dp));
        const float si = siS[sl], so = soS[sl];
        aq0 += si * qf.x; aq1 += si * qf.y;
        ak0 += so * kf.x; ak1 += so * kf.y;
    }
    sQ[p][2 * dp] = aq0; sQ[p][2 * dp + 1] = aq1;
    sK[p][2 * dp] = ak0; sK[p][2 * dp + 1] = ak1;
    __syncthreads();
    if (tid < 64) {
        float sq = 0.f, sk = 0.f;
#pragma unroll
        for (int w2 = 0; w2 < 8; w2++) { sq += sQ[w2][tid]; sk += sK[w2][tid]; }
        g_qpart2[(chunk * BH + bh) * Dd + tid] = sq;   // si-weighted q sums -> qsi
        g_kpart2[(chunk * BH + bh) * Dd + tid] = sk;   // so-weighted k sums -> kso
    }
}

// ---------------- fused: conserved_source + exp + kv partials via mma.sync ----------------
// Double-buffered fp16 tiles: overlap gmem load + pd/exp production with the mma phase.
__global__ void __launch_bounds__(256) k_kv(const float* __restrict__ tptr)
{
    const int bh = blockIdx.y, chunk = blockIdx.x;
    __shared__ __half ksh[2][32][72];
    __shared__ __half wsh[2][32][72];
    __shared__ float qsiS[64];
    __shared__ float esred[32];
    const int tid = threadIdx.x;
    const int wid = tid >> 5, lane = tid & 31;
    const int lr = tid >> 3;
    const int lc = (tid & 7) << 3;
    if (tid < 64) {
        float a = 0.f;
#pragma unroll
        for (int c = 0; c < MCH; c++) a += g_qpart2[(c * BH + bh) * Dd + tid];
        qsiS[tid] = a + EPSf;
    }
    __syncthreads();
    const float invT = 1.f / tptr[0];
    const size_t base = (size_t)bh * Ntok * Dd;

    const int dbase = (wid & 3) << 4;   // 0,16,32,48
    const int ebase = (wid >> 2) << 5;  // 0,32
    const uint32_t aAddr = smem_u32(&ksh[0][((lane >> 4) << 3) + (lane & 7)]
                                       [dbase + (((lane >> 3) & 1) << 3)]);
    const uint32_t bAddr = smem_u32(&wsh[0][(((lane >> 3) & 1) << 3) + (lane & 7)]
                                       [ebase + ((lane >> 4) << 3)]);
    const uint32_t KBUF = 32u * 72u * 2u;   // bytes per buffer

    float acc[4][4] = {};
    float esum = 0.f;

    // produce a tile into buffer b from row block t
    auto produce = [&](int t, int buf) {
        const int s = chunk * 256 + t * 32 + lr;
        uint4 kraw = *(const uint4*)(g_kh + base + (size_t)s * Dd + lc);
        uint4 vraw = *(const uint4*)(g_vh + base + (size_t)s * Dd + lc);
        const __half2* kh2 = (const __half2*)&kraw;
        const __half2* vh2 = (const __half2*)&vraw;
        float pd = 0.f;
#pragma unroll
        for (int j = 0; j < 4; j++) {
            float2 kf = __half22float2(kh2[j]);
            pd += (kf.x + EPSf) * qsiS[lc + 2 * j] + (kf.y + EPSf) * qsiS[lc + 2 * j + 1];
        }
        pd += __shfl_xor_sync(0xffffffffu, pd, 1);
        pd += __shfl_xor_sync(0xffffffffu, pd, 2);
        pd += __shfl_xor_sync(0xffffffffu, pd, 4);
        const float cs = fminf(1.f, fmaxf(-1.f, pd + EPSf));
        const float e = expf(cs * invT);
        if ((tid & 7) == 0) esum += e;
        *(uint4*)&ksh[buf][lr][lc] = kraw;
        const __half2 e2 = __float2half2_rn(e);
        uint4 wout;
        ((__half2*)&wout)[0] = __hmul2(vh2[0], e2);
        ((__half2*)&wout)[1] = __hmul2(vh2[1], e2);
        ((__half2*)&wout)[2] = __hmul2(vh2[2], e2);
        ((__half2*)&wout)[3] = __hmul2(vh2[3], e2);
        *(uint4*)&wsh[buf][lr][lc] = wout;
    };

    produce(0, 0);
    __syncthreads();
    for (int t = 0; t < 8; t++) {
        const uint32_t boff = (uint32_t)(t & 1) * KBUF;
        // mma on buffer t&1 while producing t+1 into the other buffer
        if (t + 1 < 8) produce(t + 1, (t + 1) & 1);
#pragma unroll
        for (int ks2 = 0; ks2 < 2; ks2++) {
            uint32_t a[4], b0[4], b1[4];
            const uint32_t soff = boff + (uint32_t)(ks2 * 16 * 144);
            ldm4t(a,  aAddr + soff);
            ldm4t(b0, bAddr + soff);
            ldm4t(b1, bAddr + soff + 32);
            mma16816(acc[0], a, &b0[0]);
            mma16816(acc[1], a, &b0[2]);
            mma16816(acc[2], a, &b1[0]);
            mma16816(acc[3], a, &b1[2]);
        }
        __syncthreads();
    }
    if ((tid & 7) == 0) esred[tid >> 3] = esum;
    __syncthreads();
    if (tid == 0) {
        float t = 0.f;
#pragma unroll
        for (int i = 0; i < 32; i++) t += esred[i];
        g_esum[chunk * BH + bh] = t;
    }
    float* dst = g_kvpart + ((size_t)chunk * BH + bh) * Dd * Dd;
    const int dd = dbase + (lane >> 2);
    const int ee = ebase + ((lane & 3) << 1);
#pragma unroll
    for (int nf = 0; nf < 4; nf++) {
        *(float2*)(dst + (size_t)dd * Dd + ee + nf * 8)       = make_float2(acc[nf][0], acc[nf][1]);
        *(float2*)(dst + (size_t)(dd + 8) * Dd + ee + nf * 8) = make_float2(acc[nf][2], acc[nf][3]);
    }
}

// ---------------- reduce kv partials, apply softmax scale C/Σe -> fp16 ----------------
__global__ void k_kvred()
{
    const int i = blockIdx.x * blockDim.x + threadIdx.x;
    if (i >= BH * Dd * Dd) return;
    const int bh = i >> 12;
    float es = 0.f;
#pragma unroll
    for (int c = 0; c < MCH; c++) es += g_esum[c * BH + bh];
    const float scale = (float)Cc / es;
    float s = 0.f;
#pragma unroll
    for (int c = 0; c < MCH; c++) s += g_kvpart[(size_t)c * BH * Dd * Dd + i];
    g_kvh[i] = __float2half_rn(s * scale);
}

// ---------------- out_update = (q @ kv) * si * sigmoid(q·(kso+eps)+eps) via mma.sync ----------------
__global__ void __launch_bounds__(256) k_outupd()
{
    const int bh = blockIdx.y, nt = blockIdx.x;
    const int b = bh >> 3, h = bh & 7;
    __shared__ __half qsh[64][72];
    __shared__ __half kvh[64][72];
    __shared__ float ksoS[64];
    __shared__ float sadotS[64];
    __shared__ float siS[64];
    const int tid = threadIdx.x;
    const int wid = tid >> 5, lane = tid & 31;

    if (tid < 64) {
        float a = 0.f;
#pragma unroll
        for (int c = 0; c < MCH; c++) a += g_kpart2[(c * BH + bh) * Dd + tid];
        ksoS[tid] = a + EPSf;
        siS[tid] = g_si[bh * Ntok + nt * 64 + tid];
    }

    // load q (64 rows of this n-tile) and kv (64x64) into fp16 smem tiles
    const int lr = tid >> 3, lc = (tid & 7) << 3;
    const __half* qb = g_qh + (size_t)bh * Ntok * Dd + (size_t)(nt * 64) * Dd;
    const __half* kvb = g_kvh + (size_t)bh * (Dd * Dd);
    *(uint4*)&qsh[lr][lc]      = *(const uint4*)(qb + (size_t)lr * Dd + lc);
    *(uint4*)&qsh[lr + 32][lc] = *(const uint4*)(qb + (size_t)(lr + 32) * Dd + lc);
    *(uint4*)&kvh[lr][lc]      = *(const uint4*)(kvb + (size_t)lr * Dd + lc);
    *(uint4*)&kvh[lr + 32][lc] = *(const uint4*)(kvb + (size_t)(lr + 32) * Dd + lc);
    __syncthreads();

    // sadot[n] = q[n] . (kso+eps): 4 threads per row, 16 d's each
    {
        const int row = tid >> 2, part = tid & 3;
        float s = 0.f;
#pragma unroll
        for (int j = 0; j < 8; j++) {
            const int d = part * 16 + 2 * j;
            float2 qf = __half22float2(*(const __half2*)&qsh[row][d]);
            s += qf.x * ksoS[d] + qf.y * ksoS[d + 1];
        }
        s += __shfl_xor_sync(0xffffffffu, s, 1);
        s += __shfl_xor_sync(0xffffffffu, s, 2);
        if (part == 0) sadotS[row] = s;
    }
    __syncthreads();

    float ksoSum = 0.f;
#pragma unroll
    for (int d = 0; d < 64; d++) ksoSum += ksoS[d];

    // mma: warps 4(n) x 2(e); warp tile 16n x 32e; K = 64 (4 steps)
    const int nbase = (wid & 3) << 4;
    const int ebase = (wid >> 2) << 5;
    const uint32_t aAddr = smem_u32(&qsh[nbase + (lane & 7) + (((lane >> 3) & 1) << 3)]
                                       [(lane >> 4) << 3]);
    const uint32_t bAddr = smem_u32(&kvh[(((lane >> 3) & 1) << 3) + (lane & 7)]
                                       [ebase + ((lane >> 4) << 3)]);
    float acc[4][4] = {};
#pragma unroll
    for (int ks2 = 0; ks2 < 4; ks2++) {
        uint32_t a[4], b0[4], b1[4];
        const uint32_t dA = (uint32_t)(ks2 * 16 * 2);    // +16 halves = 32B along row
        const uint32_t dB = (uint32_t)(ks2 * 16 * 144);  // +16 d-rows
        ldm4(a, aAddr + dA);
        ldm4t(b0, bAddr + dB);
        ldm4t(b1, bAddr + dB + 32);
        mma16816(acc[0], a, &b0[0]);
        mma16816(acc[1], a, &b0[2]);
        mma16816(acc[2], a, &b1[0]);
        mma16816(acc[3], a, &b1[2]);
    }

    // epilogue: scale by si*sa, store fp16 to scrambled (B,N,C)
    const int r0 = nbase + (lane >> 2);
    const int e0 = ebase + ((lane & 3) << 1);
#pragma unroll
    for (int half = 0; half < 2; half++) {
        const int nloc = r0 + half * 8;
        const int n = nt * 64 + nloc;
        const float cs_sink = sadotS[nloc] + EPSf * ksoSum + EPSf;
        const float sa = 1.f / (1.f + expf(-cs_sink));
        const float scale = siS[nloc] * sa;
        const int np = (h << 9) | (n >> 3);
        const int cbase = (n & 7) << 6;
        const size_t lin = (size_t)(b * Ntok + np) * Cc + cbase;
#pragma unroll
        for (int nf = 0; nf < 4; nf++) {
            float vx = acc[nf][half * 2 + 0] * scale;
            float vy = acc[nf][half * 2 + 1] * scale;
            *(__half2*)(g_Oh + lin + e0 + nf * 8) = __floats2half2_rn(vx, vy);
        }
    }
}

// ---------------- launch ----------------
extern "C" void kernel_launch(void* const* d_in, const int* in_sizes, int n_in,
                              void* d_out, int out_size)
{
    const float* query = (const float*)d_in[0];
    const float* Wq = (const float*)d_in[1];
    const float* bq = (const float*)d_in[2];
    const float* Wk = (const float*)d_in[3];
    const float* bk = (const float*)d_in[4];
    const float* Wv = (const float*)d_in[5];
    const float* bv = (const float*)d_in[6];
    const float* Wo = (const float*)d_in[7];
    const float* bo = (const float*)d_in[8];
    const float* temp = (const float*)d_in[9];
    float* out = (float*)d_out;

    const int DSMEM = 3 * 32768 + 1024;
    cudaFuncSetAttribute(gemm_tc, cudaFuncAttributeMaxDynamicSharedMemorySize, DSMEM);

    __half *pAh, *pOh, *pB;
    void* pIcol;
    cudaGetSymbolAddress((void**)&pAh, g_Ah);
    cudaGetSymbolAddress((void**)&pOh, g_Oh);
    cudaGetSymbolAddress((void**)&pB,  g_B);
    cudaGetSymbolAddress(&pIcol, g_icol);

    // zero fixed-point colsum accumulators (graph-capturable async memset)
    cudaMemsetAsync(pIcol, 0, 2 * BH * Dd * sizeof(unsigned long long));

    // merged operand conversion (query split + 4 weight converts)
    k_conv<<<17408, 256>>>(query, pAh, Wq, Wk, Wv, Wo, pB);

    // q/k/v projections in one launch; colsum fused in epilogue
    gemm_tc<<<dim3(4, 256, 3), 256, DSMEM>>>(pAh, pB, bq, bk, bv, nullptr, nullptr, 0);

    k_fuse1<<<dim3(MCH, BH), 256>>>();
    k_kv<<<dim3(MCH, BH), 256>>>(temp);
    k_kvred<<<(BH * Dd * Dd + 255) / 256, 256>>>();
    k_outupd<<<dim3(64, BH), 256>>>();

    // output projection (+bias+residual)
    gemm_tc<<<dim3(4, 256, 1), 256, DSMEM>>>(pOh, pB + 3 * (512 * 512), bo, bo, bo,
                                             query, out, 3);
}

// round 16
// speedup vs baseline: 1.6069x; 1.0020x over previous
#include <cuda_runtime.h>
#include <cuda_fp16.h>
#include <math.h>
#include <stdint.h>

#define Ntok 4096
#define Bb   8
#define Cc   512
#define Hh   8
#define Dd   64
#define BH   64          // B*H
#define EPSf 1e-6f
#define NCHUNK 8         // 512 K / 64 per chunk
#define MCH   16         // mid-section chunks
#define FIXSC 16777216.0f        // 2^24
#define FIXINV (1.0f / 16777216.0f)

// ---------------- scratch (static device arrays; no allocation) ----------------
__device__ __half g_qh[BH * Ntok * Dd];    // (B,H,N,D) sigmoid(q proj) fp16
__device__ __half g_kh[BH * Ntok * Dd];
__device__ __half g_vh[BH * Ntok * Dd];
__device__ float g_si[BH * Ntok];
__device__ unsigned long long g_icol[2][BH * Dd];                   // fixed-point col sums (0:q 1:k)
__device__ float g_kpart2[MCH * BH * Dd], g_qpart2[MCH * BH * Dd];  // weighted col sums
__device__ float g_esum[MCH * BH];                                   // exp-sum partials
__device__ __half g_kvh[BH * Dd * Dd];                               // fp16 kv (post softmax scale)
__device__ float g_kvpart[MCH * BH * Dd * Dd];

// fp16 GEMM operands
__device__ __half g_Ah[32768 * 512];       // fp16(query)
__device__ __half g_Oh[32768 * 512];       // fp16(out_update), scrambled (B,N,C)
__device__ __half g_B[4 * 512 * 512];      // [proj][n][k]

// ---------------- PTX helpers (base-arch only) ----------------
__device__ __forceinline__ uint32_t smem_u32(const void* p) {
    uint32_t a;
    asm("{ .reg .u64 t; cvta.to.shared.u64 t, %1; cvt.u32.u64 %0, t; }" : "=r"(a) : "l"(p));
    return a;
}
__device__ __forceinline__ void cp16(uint32_t dst, const void* src) {
    asm volatile("cp.async.cg.shared.global [%0], [%1], 16;" :: "r"(dst), "l"(src) : "memory");
}
__device__ __forceinline__ void cp_commit() {
    asm volatile("cp.async.commit_group;" ::: "memory");
}
__device__ __forceinline__ void cp_wait1() {
    asm volatile("cp.async.wait_group 1;" ::: "memory");
}
__device__ __forceinline__ void cp_wait0() {
    asm volatile("cp.async.wait_group 0;" ::: "memory");
}
__device__ __forceinline__ void ldm4(uint32_t* r, uint32_t addr) {
    asm volatile("ldmatrix.sync.aligned.m8n8.x4.shared.b16 {%0,%1,%2,%3}, [%4];"
                 : "=r"(r[0]), "=r"(r[1]), "=r"(r[2]), "=r"(r[3]) : "r"(addr));
}
__device__ __forceinline__ void ldm4t(uint32_t* r, uint32_t addr) {
    asm volatile("ldmatrix.sync.aligned.m8n8.x4.trans.shared.b16 {%0,%1,%2,%3}, [%4];"
                 : "=r"(r[0]), "=r"(r[1]), "=r"(r[2]), "=r"(r[3]) : "r"(addr));
}
__device__ __forceinline__ void mma16816(float* c, const uint32_t* a, const uint32_t* b) {
    asm volatile(
        "mma.sync.aligned.m16n8k16.row.col.f32.f16.f16.f32 "
        "{%0,%1,%2,%3}, {%4,%5,%6,%7}, {%8,%9}, {%0,%1,%2,%3};"
        : "+f"(c[0]), "+f"(c[1]), "+f"(c[2]), "+f"(c[3])
        : "r"(a[0]), "r"(a[1]), "r"(a[2]), "r"(a[3]), "r"(b[0]), "r"(b[1]));
}

// ---------------- merged conversion kernel ----------------
__global__ void k_conv(const float* __restrict__ src, __half* __restrict__ dst,
                       const float* __restrict__ Wq, const float* __restrict__ Wk,
                       const float* __restrict__ Wv, const float* __restrict__ Wo,
                       __half* __restrict__ Bop)
{
    if (blockIdx.x < 16384) {
        int i = blockIdx.x * 256 + threadIdx.x;
        float4 v = ((const float4*)src)[i];
        __half2* hp = (__half2*)dst;
        hp[2 * i]     = __floats2half2_rn(v.x, v.y);
        hp[2 * i + 1] = __floats2half2_rn(v.z, v.w);
    } else {
        const int bid = blockIdx.x - 16384;     // 0..1023
        const int z = bid >> 8;                  // projection
        const int rem = bid & 255;
        const int by = rem >> 4, bx = rem & 15;
        const int tx = threadIdx.x & 31, ty = threadIdx.x >> 5;  // (32,8)
        const float* W = (z == 0) ? Wq : (z == 1) ? Wk : (z == 2) ? Wv : Wo;
        __half* Bp = Bop + (size_t)z * (512 * 512);
        __shared__ float t[32][33];
        const int k0 = by * 32, n0 = bx * 32;
        for (int j = ty; j < 32; j += 8) t[j][tx] = W[(size_t)(k0 + j) * 512 + n0 + tx];
        __syncthreads();
        for (int j = ty; j < 32; j += 8)
            Bp[(size_t)(n0 + j) * 512 + (k0 + tx)] = __float2half_rn(t[tx][j]);
    }
}

// ---------------- mma.sync GEMM (f32 acc): D[32768,512] = A[.,512] @ B^T ----------------
// 2-stage pipeline, 64KB dynamic smem -> 2 CTAs/SM (16 warps) for latency hiding.
// mode 0: q (sigmoid -> g_qh + colsum), 1: k -> g_kh + colsum, 2: v -> g_vh,
// mode 3: out (+bias+resid -> d_out)
__global__ void __launch_bounds__(256, 2) gemm_tc(
    const __half* __restrict__ A, const __half* __restrict__ Bbase,
    const float* __restrict__ b0, const float* __restrict__ b1, const float* __restrict__ b2,
    const float* __restrict__ resid, float* __restrict__ out, int modeBase)
{
    extern __shared__ char dyn[];
    const uint32_t sbase = (smem_u32(dyn) + 1023u) & ~1023u;
    char* dynA = dyn + (sbase - smem_u32(dyn));
    const int tid = threadIdx.x;
    const int wid = tid >> 5, lane = tid & 31;
    const int bn = blockIdx.x * 128, bm = blockIdx.y * 128;
    const int mode = modeBase + blockIdx.z;
    const __half* Bop = Bbase + (size_t)blockIdx.z * (512 * 512);
    const float* bias = (mode == 1) ? b1 : (mode == 2) ? b2 : b0;
    const int warpM = wid & 3, warpN = wid >> 2;   // 4 x 2 warps -> 32x64 warp tile

    float acc[2][8][4];
#pragma unroll
    for (int mf = 0; mf < 2; mf++)
#pragma unroll
        for (int nf = 0; nf < 8; nf++)
#pragma unroll
            for (int i = 0; i < 4; i++) acc[mf][nf][i] = 0.f;

    int aRow[2], bRow[4];
#pragma unroll
    for (int mf = 0; mf < 2; mf++)
        aRow[mf] = warpM * 32 + mf * 16 + (lane & 7) + ((lane >> 3) & 1) * 8;
    const int aHi = lane >> 4;
#pragma unroll
    for (int nf2 = 0; nf2 < 4; nf2++)
        bRow[nf2] = warpN * 64 + nf2 * 16 + (lane & 7) + (lane >> 4) * 8;
    const int bHi = (lane >> 3) & 1;

    auto issue = [&](int c) {
        const int akoff = c << 6;
        const uint32_t buf = sbase + (uint32_t)(c & 1) * 32768u;
#pragma unroll
        for (int t = 0; t < 4; t++) {
            int s = tid + (t << 8);
            int row = s >> 3, sc = s & 7;
            uint32_t off = row * 128 + ((sc ^ (row & 7)) << 4);
            cp16(buf + off, A + ((size_t)(bm + row) * 512 + akoff + sc * 8));
        }
#pragma unroll
        for (int t = 0; t < 4; t++) {
            int s = tid + (t << 8);
            int row = s >> 3, sc = s & 7;
            uint32_t off = row * 128 + ((sc ^ (row & 7)) << 4);
            cp16(buf + 16384u + off, Bop + ((size_t)(bn + row) * 512 + akoff + sc * 8));
        }
    };

    issue(0); cp_commit();

    for (int c = 0; c < NCHUNK; c++) {
        if (c + 1 < NCHUNK) {
            issue(c + 1); cp_commit();
            cp_wait1();
        } else {
            cp_wait0();
        }
        __syncthreads();

        const uint32_t abuf = sbase + (uint32_t)(c & 1) * 32768u;
        const uint32_t bbuf = abuf + 16384u;
#pragma unroll
        for (int ks = 0; ks < 4; ks++) {
            uint32_t a[2][4], b[4][4];
#pragma unroll
            for (int mf = 0; mf < 2; mf++) {
                const int row = aRow[mf];
                const int cc = 2 * ks + aHi;
                ldm4(a[mf], abuf + row * 128 + ((cc ^ (row & 7)) << 4));
            }
#pragma unroll
            for (int nf2 = 0; nf2 < 4; nf2++) {
                const int row = bRow[nf2];
                const int cc = 2 * ks + bHi;
                ldm4(b[nf2], bbuf + row * 128 + ((cc ^ (row & 7)) << 4));
            }
#pragma unroll
            for (int mf = 0; mf < 2; mf++)
#pragma unroll
                for (int nf = 0; nf < 8; nf++)
                    mma16816(acc[mf][nf], a[mf], &b[nf >> 1][(nf & 1) * 2]);
        }
        __syncthreads();
    }

    // ---------------- epilogue ----------------
    if (mode <= 2) {
        __half* smh = (__half*)dynA;
        const int rloc = warpM * 32 + (lane >> 2);
        const int cloc = warpN * 64 + ((lane & 3) << 1);
#pragma unroll
        for (int mf = 0; mf < 2; mf++)
#pragma unroll
            for (int half = 0; half < 2; half++) {
#pragma unroll
                for (int nf = 0; nf < 8; nf++) {
                    const int c0 = bn + cloc + nf * 8;
                    float vx = acc[mf][nf][half * 2 + 0] + bias[c0];
                    float vy = acc[mf][nf][half * 2 + 1] + bias[c0 + 1];
                    if (mode <= 1) {
                        vx = 1.f / (1.f + expf(-vx));
                        vy = 1.f / (1.f + expf(-vy));
                    }
                    *(__half2*)&smh[(rloc + mf * 16 + half * 8) * 136 + cloc + nf * 8]
                        = __floats2half2_rn(vx, vy);
                }
            }
        __syncthreads();
        __half* dstg = (mode == 0) ? g_qh : (mode == 1) ? g_kh : g_vh;
        const int h0 = bn >> 6;
        const int hl = tid >> 7, nl = (tid & 127) >> 3, dp = tid & 7;
#pragma unroll
        for (int bb2 = 0; bb2 < 8; bb2++) {
            uint4 val = *(const uint4*)(smh + (size_t)(nl * 8 + bb2) * 136 + hl * 64 + dp * 8);
            *(uint4*)(dstg + ((size_t)((bb2 << 3) | (h0 + hl)) * Ntok + (bm >> 3) + nl) * Dd + dp * 8) = val;
        }
        // fused column sums (q/k): deterministic fixed-point atomics over the staged tile
        if (mode <= 1) {
            const int hl2 = tid >> 7;            // head within tile (0..1)
            const int b2 = (tid >> 4) & 7;       // batch
            const int d0 = (tid & 15) << 2;      // 4 d's
            float s0 = 0.f, s1 = 0.f, s2 = 0.f, s3 = 0.f;
#pragma unroll
            for (int n = 0; n < 16; n++) {
                const __half* rowp = smh + (size_t)(n * 8 + b2) * 136 + hl2 * 64 + d0;
                float2 p0 = __half22float2(*(const __half2*)rowp);
                float2 p1 = __half22float2(*(const __half2*)(rowp + 2));
                s0 += p0.x; s1 += p0.y; s2 += p1.x; s3 += p1.y;
            }
            const int bh = (b2 << 3) | ((bn >> 6) + hl2);
            unsigned long long* dst = &g_icol[mode][bh * Dd + d0];
            atomicAdd(dst + 0, (unsigned long long)(long long)llrintf(s0 * FIXSC));
            atomicAdd(dst + 1, (unsigned long long)(long long)llrintf(s1 * FIXSC));
            atomicAdd(dst + 2, (unsigned long long)(long long)llrintf(s2 * FIXSC));
            atomicAdd(dst + 3, (unsigned long long)(long long)llrintf(s3 * FIXSC));
        }
    } else {
        const int r0base = bm + warpM * 32 + (lane >> 2);
        const int cb = bn + warpN * 64 + ((lane & 3) << 1);
#pragma unroll
        for (int mf = 0; mf < 2; mf++)
#pragma unroll
            for (int half = 0; half < 2; half++) {
                const int r = r0base + mf * 16 + half * 8;
#pragma unroll
                for (int nf = 0; nf < 8; nf++) {
                    const int c0 = cb + nf * 8;
                    const int bb = r >> 12, n = r & 4095;
                    const size_t o = (size_t)((n << 3) | bb) * Cc + c0;
                    float2 rs = *(const float2*)(resid + o);
                    float2 v;
                    v.x = acc[mf][nf][half * 2 + 0] + bias[c0] + rs.x;
                    v.y = acc[mf][nf][half * 2 + 1] + bias[c0 + 1] + rs.y;
                    *(float2*)(out + o) = v;
                }
            }
    }
}

// ---------------- fused: rownorm (si/so) + weighted colsum partials ----------------
__global__ void __launch_bounds__(256) k_fuse1()
{
    const int bh = blockIdx.y, chunk = blockIdx.x;
    const int tid = threadIdx.x;
    __shared__ float ksS[64], qsS[64];
    __shared__ float siS[256], soS[256];
    __shared__ float sQ[8][64], sK[8][64];
    if (tid < 64) {
        ksS[tid] = (float)(long long)g_icol[1][bh * Dd + tid] * FIXINV + EPSf;
        qsS[tid] = (float)(long long)g_icol[0][bh * Dd + tid] * FIXINV + EPSf;
    }
    __syncthreads();
    const __half* qb = g_qh + (size_t)bh * Ntok * Dd;
    const __half* kb = g_kh + (size_t)bh * Ntok * Dd;

    // phase 1: one thread per s-row, private dot over d (no shuffles)
    {
        const int s = chunk * 256 + tid;
        const uint4* qrow = (const uint4*)(qb + (size_t)s * Dd);
        const uint4* krow = (const uint4*)(kb + (size_t)s * Dd);
        float s1 = 0.f, s2 = 0.f;
#pragma unroll
        for (int j = 0; j < 8; j++) {
            uint4 qraw = qrow[j];
            uint4 kraw = krow[j];
            const __half2* qh2 = (const __half2*)&qraw;
            const __half2* kh2 = (const __half2*)&kraw;
#pragma unroll
            for (int u = 0; u < 4; u++) {
                float2 qf = __half22float2(qh2[u]);
                float2 kf = __half22float2(kh2[u]);
                const int d = j * 8 + 2 * u;
                s1 += (qf.x + EPSf) * ksS[d] + (qf.y + EPSf) * ksS[d + 1];
                s2 += (kf.x + EPSf) * qsS[d] + (kf.y + EPSf) * qsS[d + 1];
            }
        }
        const float si = 1.f / (s1 + EPSf);
        const float so = 1.f / (s2 + EPSf);
        g_si[bh * Ntok + s] = si;
        siS[tid] = si; soS[tid] = so;
    }
    __syncthreads();

    // phase 2: weighted colsums, coalesced (rows L1-hot from phase 1)
    const int p = tid >> 5, dp = tid & 31;
    float aq0 = 0.f, aq1 = 0.f, ak0 = 0.f, ak1 = 0.f;
#pragma unroll 4
    for (int i = 0; i < 32; i++) {
        const int sl = p + 8 * i;
        const int s = chunk * 256 + sl;
        float2 qf = __half22float2(*(const __half2*)(qb + (size_t)s * Dd + 2 * dp));
        float2 kf = __half22float2(*(const __half2*)(kb + (size_t)s * Dd + 2 * dp));
        const float si = siS[sl], so = soS[sl];
        aq0 += si * qf.x; aq1 += si * qf.y;
        ak0 += so * kf.x; ak1 += so * kf.y;
    }
    sQ[p][2 * dp] = aq0; sQ[p][2 * dp + 1] = aq1;
    sK[p][2 * dp] = ak0; sK[p][2 * dp + 1] = ak1;
    __syncthreads();
    if (tid < 64) {
        float sq = 0.f, sk = 0.f;
#pragma unroll
        for (int w2 = 0; w2 < 8; w2++) { sq += sQ[w2][tid]; sk += sK[w2][tid]; }
        g_qpart2[(chunk * BH + bh) * Dd + tid] = sq;   // si-weighted q sums -> qsi
        g_kpart2[(chunk * BH + bh) * Dd + tid] = sk;   // so-weighted k sums -> kso
    }
}

// ---------------- fused: conserved_source + exp + kv partials via mma.sync ----------------
// Double-buffered fp16 tiles: overlap gmem load + pd/exp production with the mma phase.
__global__ void __launch_bounds__(256) k_kv(const float* __restrict__ tptr)
{
    const int bh = blockIdx.y, chunk = blockIdx.x;
    __shared__ __half ksh[2][32][72];
    __shared__ __half wsh[2][32][72];
    __shared__ float qsiS[64];
    __shared__ float esred[32];
    const int tid = threadIdx.x;
    const int wid = tid >> 5, lane = tid & 31;
    const int lr = tid >> 3;
    const int lc = (tid & 7) << 3;
    if (tid < 64) {
        float a = 0.f;
#pragma unroll
        for (int c = 0; c < MCH; c++) a += g_qpart2[(c * BH + bh) * Dd + tid];
        qsiS[tid] = a + EPSf;
    }
    __syncthreads();
    const float invT = 1.f / tptr[0];
    const size_t base = (size_t)bh * Ntok * Dd;

    const int dbase = (wid & 3) << 4;   // 0,16,32,48
    const int ebase = (wid >> 2) << 5;  // 0,32
    const uint32_t aAddr = smem_u32(&ksh[0][((lane >> 4) << 3) + (lane & 7)]
                                       [dbase + (((lane >> 3) & 1) << 3)]);
    const uint32_t bAddr = smem_u32(&wsh[0][(((lane >> 3) & 1) << 3) + (lane & 7)]
                                       [ebase + ((lane >> 4) << 3)]);
    const uint32_t KBUF = 32u * 72u * 2u;   // bytes per buffer

    float acc[4][4] = {};
    float esum = 0.f;

    auto produce = [&](int t, int buf) {
        const int s = chunk * 256 + t * 32 + lr;
        uint4 kraw = *(const uint4*)(g_kh + base + (size_t)s * Dd + lc);
        uint4 vraw = *(const uint4*)(g_vh + base + (size_t)s * Dd + lc);
        const __half2* kh2 = (const __half2*)&kraw;
        const __half2* vh2 = (const __half2*)&vraw;
        float pd = 0.f;
#pragma unroll
        for (int j = 0; j < 4; j++) {
            float2 kf = __half22float2(kh2[j]);
            pd += (kf.x + EPSf) * qsiS[lc + 2 * j] + (kf.y + EPSf) * qsiS[lc + 2 * j + 1];
        }
        pd += __shfl_xor_sync(0xffffffffu, pd, 1);
        pd += __shfl_xor_sync(0xffffffffu, pd, 2);
        pd += __shfl_xor_sync(0xffffffffu, pd, 4);
        const float cs = fminf(1.f, fmaxf(-1.f, pd + EPSf));
        const float e = expf(cs * invT);
        if ((tid & 7) == 0) esum += e;
        *(uint4*)&ksh[buf][lr][lc] = kraw;
        const __half2 e2 = __float2half2_rn(e);
        uint4 wout;
        ((__half2*)&wout)[0] = __hmul2(vh2[0], e2);
        ((__half2*)&wout)[1] = __hmul2(vh2[1], e2);
        ((__half2*)&wout)[2] = __hmul2(vh2[2], e2);
        ((__half2*)&wout)[3] = __hmul2(vh2[3], e2);
        *(uint4*)&wsh[buf][lr][lc] = wout;
    };

    produce(0, 0);
    __syncthreads();
    for (int t = 0; t < 8; t++) {
        const uint32_t boff = (uint32_t)(t & 1) * KBUF;
        if (t + 1 < 8) produce(t + 1, (t + 1) & 1);
#pragma unroll
        for (int ks2 = 0; ks2 < 2; ks2++) {
            uint32_t a[4], b0[4], b1[4];
            const uint32_t soff = boff + (uint32_t)(ks2 * 16 * 144);
            ldm4t(a,  aAddr + soff);
            ldm4t(b0, bAddr + soff);
            ldm4t(b1, bAddr + soff + 32);
            mma16816(acc[0], a, &b0[0]);
            mma16816(acc[1], a, &b0[2]);
            mma16816(acc[2], a, &b1[0]);
            mma16816(acc[3], a, &b1[2]);
        }
        __syncthreads();
    }
    if ((tid & 7) == 0) esred[tid >> 3] = esum;
    __syncthreads();
    if (tid == 0) {
        float t = 0.f;
#pragma unroll
        for (int i = 0; i < 32; i++) t += esred[i];
        g_esum[chunk * BH + bh] = t;
    }
    float* dst = g_kvpart + ((size_t)chunk * BH + bh) * Dd * Dd;
    const int dd = dbase + (lane >> 2);
    const int ee = ebase + ((lane & 3) << 1);
#pragma unroll
    for (int nf = 0; nf < 4; nf++) {
        *(float2*)(dst + (size_t)dd * Dd + ee + nf * 8)       = make_float2(acc[nf][0], acc[nf][1]);
        *(float2*)(dst + (size_t)(dd + 8) * Dd + ee + nf * 8) = make_float2(acc[nf][2], acc[nf][3]);
    }
}

// ---------------- reduce kv partials, apply softmax scale C/Σe -> fp16 ----------------
__global__ void k_kvred()
{
    const int i = blockIdx.x * blockDim.x + threadIdx.x;
    if (i >= BH * Dd * Dd) return;
    const int bh = i >> 12;
    float es = 0.f;
#pragma unroll
    for (int c = 0; c < MCH; c++) es += g_esum[c * BH + bh];
    const float scale = (float)Cc / es;
    float s = 0.f;
#pragma unroll
    for (int c = 0; c < MCH; c++) s += g_kvpart[(size_t)c * BH * Dd * Dd + i];
    g_kvh[i] = __float2half_rn(s * scale);
}

// ---------------- out_update = (q @ kv) * si * sigmoid(q·(kso+eps)+eps) via mma.sync ----------------
__global__ void __launch_bounds__(256) k_outupd()
{
    const int bh = blockIdx.y, nt = blockIdx.x;
    const int b = bh >> 3, h = bh & 7;
    __shared__ __half qsh[64][72];
    __shared__ __half kvh[64][72];
    __shared__ float ksoS[64];
    __shared__ float sadotS[64];
    __shared__ float siS[64];
    const int tid = threadIdx.x;
    const int wid = tid >> 5, lane = tid & 31;

    if (tid < 64) {
        float a = 0.f;
#pragma unroll
        for (int c = 0; c < MCH; c++) a += g_kpart2[(c * BH + bh) * Dd + tid];
        ksoS[tid] = a + EPSf;
        siS[tid] = g_si[bh * Ntok + nt * 64 + tid];
    }

    // load q (64 rows of this n-tile) and kv (64x64) into fp16 smem tiles
    const int lr = tid >> 3, lc = (tid & 7) << 3;
    const __half* qb = g_qh + (size_t)bh * Ntok * Dd + (size_t)(nt * 64) * Dd;
    const __half* kvb = g_kvh + (size_t)bh * (Dd * Dd);
    *(uint4*)&qsh[lr][lc]      = *(const uint4*)(qb + (size_t)lr * Dd + lc);
    *(uint4*)&qsh[lr + 32][lc] = *(const uint4*)(qb + (size_t)(lr + 32) * Dd + lc);
    *(uint4*)&kvh[lr][lc]      = *(const uint4*)(kvb + (size_t)lr * Dd + lc);
    *(uint4*)&kvh[lr + 32][lc] = *(const uint4*)(kvb + (size_t)(lr + 32) * Dd + lc);
    __syncthreads();

    // sadot[n] = q[n] . (kso+eps): 4 threads per row, 16 d's each
    {
        const int row = tid >> 2, part = tid & 3;
        float s = 0.f;
#pragma unroll
        for (int j = 0; j < 8; j++) {
            const int d = part * 16 + 2 * j;
            float2 qf = __half22float2(*(const __half2*)&qsh[row][d]);
            s += qf.x * ksoS[d] + qf.y * ksoS[d + 1];
        }
        s += __shfl_xor_sync(0xffffffffu, s, 1);
        s += __shfl_xor_sync(0xffffffffu, s, 2);
        if (part == 0) sadotS[row] = s;
    }
    __syncthreads();

    float ksoSum = 0.f;
#pragma unroll
    for (int d = 0; d < 64; d++) ksoSum += ksoS[d];

    // mma: warps 4(n) x 2(e); warp tile 16n x 32e; K = 64 (4 steps)
    const int nbase = (wid & 3) << 4;
    const int ebase = (wid >> 2) << 5;
    const uint32_t aAddr = smem_u32(&qsh[nbase + (lane & 7) + (((lane >> 3) & 1) << 3)]
                                       [(lane >> 4) << 3]);
    const uint32_t bAddr = smem_u32(&kvh[(((lane >> 3) & 1) << 3) + (lane & 7)]
                                       [ebase + ((lane >> 4) << 3)]);
    float acc[4][4] = {};
#pragma unroll
    for (int ks2 = 0; ks2 < 4; ks2++) {
        uint32_t a[4], b0[4], b1[4];
        const uint32_t dA = (uint32_t)(ks2 * 16 * 2);    // +16 halves = 32B along row
        const uint32_t dB = (uint32_t)(ks2 * 16 * 144);  // +16 d-rows
        ldm4(a, aAddr + dA);
        ldm4t(b0, bAddr + dB);
        ldm4t(b1, bAddr + dB + 32);
        mma16816(acc[0], a, &b0[0]);
        mma16816(acc[1], a, &b0[2]);
        mma16816(acc[2], a, &b1[0]);
        mma16816(acc[3], a, &b1[2]);
    }

    // epilogue: scale by si*sa, store fp16 to scrambled (B,N,C)
    const int r0 = nbase + (lane >> 2);
    const int e0 = ebase + ((lane & 3) << 1);
#pragma unroll
    for (int half = 0; half < 2; half++) {
        const int nloc = r0 + half * 8;
        const int n = nt * 64 + nloc;
        const float cs_sink = sadotS[nloc] + EPSf * ksoSum + EPSf;
        const float sa = 1.f / (1.f + expf(-cs_sink));
        const float scale = siS[nloc] * sa;
        const int np = (h << 9) | (n >> 3);
        const int cbase = (n & 7) << 6;
        const size_t lin = (size_t)(b * Ntok + np) * Cc + cbase;
#pragma unroll
        for (int nf = 0; nf < 4; nf++) {
            float vx = acc[nf][half * 2 + 0] * scale;
            float vy = acc[nf][half * 2 + 1] * scale;
            *(__half2*)(g_Oh + lin + e0 + nf * 8) = __floats2half2_rn(vx, vy);
        }
    }
}

// ---------------- launch ----------------
extern "C" void kernel_launch(void* const* d_in, const int* in_sizes, int n_in,
                              void* d_out, int out_size)
{
    const float* query = (const float*)d_in[0];
    const float* Wq = (const float*)d_in[1];
    const float* bq = (const float*)d_in[2];
    const float* Wk = (const float*)d_in[3];
    const float* bk = (const float*)d_in[4];
    const float* Wv = (const float*)d_in[5];
    const float* bv = (const float*)d_in[6];
    const float* Wo = (const float*)d_in[7];
    const float* bo = (const float*)d_in[8];
    const float* temp = (const float*)d_in[9];
    float* out = (float*)d_out;

    const int DSMEM = 2 * 32768 + 1024;     // 2-stage pipeline: 2 CTAs/SM
    cudaFuncSetAttribute(gemm_tc, cudaFuncAttributeMaxDynamicSharedMemorySize, DSMEM);

    __half *pAh, *pOh, *pB;
    void* pIcol;
    cudaGetSymbolAddress((void**)&pAh, g_Ah);
    cudaGetSymbolAddress((void**)&pOh, g_Oh);
    cudaGetSymbolAddress((void**)&pB,  g_B);
    cudaGetSymbolAddress(&pIcol, g_icol);

    // zero fixed-point colsum accumulators (graph-capturable async memset)
    cudaMemsetAsync(pIcol, 0, 2 * BH * Dd * sizeof(unsigned long long));

    // merged operand conversion (query split + 4 weight converts)
    k_conv<<<17408, 256>>>(query, pAh, Wq, Wk, Wv, Wo, pB);

    // q/k/v projections in one launch; colsum fused in epilogue
    gemm_tc<<<dim3(4, 256, 3), 256, DSMEM>>>(pAh, pB, bq, bk, bv, nullptr, nullptr, 0);

    k_fuse1<<<dim3(MCH, BH), 256>>>();
    k_kv<<<dim3(MCH, BH), 256>>>(temp);
    k_kvred<<<(BH * Dd * Dd + 255) / 256, 256>>>();
    k_outupd<<<dim3(64, BH), 256>>>();

    // output projection (+bias+residual)
    gemm_tc<<<dim3(4, 256, 1), 256, DSMEM>>>(pOh, pB + 3 * (512 * 512), bo, bo, bo,
                                             query, out, 3);
}